// round 9
// baseline (speedup 1.0000x reference)
#include <cuda_runtime.h>
#include <stdint.h>
#include <math.h>

#define SEQ_   32768
#define NV_    256
#define NH_    512
#define NR_    256
#define CDK_   5
#define NSWEEP 10

// JAX >= 0.5 default: jax_threefry_partitionable = True
#define JAX_PARTITIONABLE 1

// ---------------------------------------------------------------------------
// Scratch (device globals; allocation-free per harness rules)
// ---------------------------------------------------------------------------
__device__ float g_X   [(size_t)SEQ_ * NR_];
__device__ float g_Ua  [(size_t)SEQ_ * NR_];
__device__ float g_Ub  [(size_t)SEQ_ * NR_];
__device__ float g_bvt [(size_t)SEQ_ * NV_];
__device__ float g_bh1t[(size_t)SEQ_ * NH_];
__device__ float g_bh2t[(size_t)SEQ_ * NH_];
__device__ float g_h   [(size_t)SEQ_ * NH_];
__device__ float g_h1  [(size_t)SEQ_ * NH_];
__device__ float g_h2  [(size_t)SEQ_ * NH_];
__device__ float g_h1s [(size_t)SEQ_ * NH_];
__device__ float g_vs  [(size_t)SEQ_ * NV_];
// 0: sum sp(v_seq)   1: sum sp(v_sample)  2: sum sp(h1)  3: sum sp(h1_sample)
// 4: monitor sum     5: sum v_seq.bvt     6: sum vs.bvt  7: sum (h1-h1s).bh1t
__device__ double g_acc[8];

// ---------------------------------------------------------------------------
// Threefry-2x32 (20 rounds) — exactly JAX's cipher
// ---------------------------------------------------------------------------
__host__ __device__ __forceinline__
void tf2x32(uint32_t k0, uint32_t k1, uint32_t x0, uint32_t x1,
            uint32_t* o0, uint32_t* o1)
{
    uint32_t ks2 = k0 ^ k1 ^ 0x1BD11BDAu;
    x0 += k0; x1 += k1;
#define TF_RND(R) { x0 += x1; x1 = (x1 << (R)) | (x1 >> (32 - (R))); x1 ^= x0; }
    TF_RND(13) TF_RND(15) TF_RND(26) TF_RND(6)
    x0 += k1;  x1 += ks2 + 1u;
    TF_RND(17) TF_RND(29) TF_RND(16) TF_RND(24)
    x0 += ks2; x1 += k0 + 2u;
    TF_RND(13) TF_RND(15) TF_RND(26) TF_RND(6)
    x0 += k0;  x1 += k1 + 3u;
    TF_RND(17) TF_RND(29) TF_RND(16) TF_RND(24)
    x0 += k1;  x1 += ks2 + 4u;
    TF_RND(13) TF_RND(15) TF_RND(26) TF_RND(6)
    x0 += ks2; x1 += k0 + 5u;
#undef TF_RND
    *o0 = x0; *o1 = x1;
}

__device__ __forceinline__
float jx_uniform(uint32_t k0, uint32_t k1, uint32_t idx, uint32_t half)
{
    uint32_t bits;
#if JAX_PARTITIONABLE
    uint32_t o0, o1;
    tf2x32(k0, k1, 0u, idx, &o0, &o1);
    bits = o0 ^ o1;
#else
    uint32_t o0, o1;
    if (idx < half) { tf2x32(k0, k1, idx, idx + half, &o0, &o1); bits = o0; }
    else            { tf2x32(k0, k1, idx - half, idx, &o0, &o1); bits = o1; }
#endif
    return __uint_as_float((bits >> 9) | 0x3f800000u) - 1.0f;
}

// ---------------------------------------------------------------------------
// init
// ---------------------------------------------------------------------------
__global__ void k_init()
{
    size_t i   = (size_t)blockIdx.x * blockDim.x + threadIdx.x;
    size_t tot = (size_t)SEQ_ * NR_;
    size_t str = (size_t)gridDim.x * blockDim.x;
    for (size_t j = i; j < tot; j += str) g_Ua[j] = 0.0f;
    if (i < 8) g_acc[i] = 0.0;
}

// ---------------------------------------------------------------------------
// Fused tiled GEMM:  C[S,N] = A[S,K] @ B  (+ bias_vec[n] + bias_arr[t,n])
//   128x128x16 block tile, 8x8 micro-tile, 256 threads.
//   TRANSB: B source is [N,K]; else [K,N].
//   shiftA: row t of A reads source row t-1 (row 0 -> zeros)
//   mode  : 0=linear  1=tanh  2=bernoulli(sigmoid) sample (out2 gets p)
//   red   : 0=none  1=sum softplus(z)  2=sum monitor(vmon, p)   -> red[slot]
// ---------------------------------------------------------------------------
#define BM 128
#define BN 128
#define BK 16

template<bool TRANSB>
__global__ void __launch_bounds__(256, 2)
gemm_ep(const float* __restrict__ A, int shiftA,
        const float* __restrict__ Bm, int K, int N,
        const float* __restrict__ bias_vec,
        const float* __restrict__ bias_arr,
        float* __restrict__ outC, float* __restrict__ out2,
        int mode, int red_mode, int slot,
        const float* __restrict__ vmon,
        uint32_t rk0, uint32_t rk1, uint32_t half,
        double* __restrict__ red)
{
    __shared__ float As[BK][BM];
    __shared__ float Bs[BK][BN + 4];

    const int tid = threadIdx.x;
    const int tx  = tid & 15;        // 0..15 -> col group
    const int ty  = tid >> 4;        // 0..15 -> row group
    const int rowBase = blockIdx.y * BM;
    const int colBase = blockIdx.x * BN;

    float c[8][8];
#pragma unroll
    for (int i = 0; i < 8; i++)
#pragma unroll
        for (int j = 0; j < 8; j++) c[i][j] = 0.0f;

    for (int kc = 0; kc < K; kc += BK) {
        // ---- A tile: 128 rows x 16 k, stored k-major in smem ----
        {
            int r  = tid >> 1;           // 0..127
            int kq = (tid & 1) << 3;     // 0 or 8
            int srow = rowBase + r - shiftA;
            float4 v0 = make_float4(0.f,0.f,0.f,0.f);
            float4 v1 = v0;
            if (srow >= 0) {
                const float* p = A + (size_t)srow * K + kc + kq;
                v0 = *reinterpret_cast<const float4*>(p);
                v1 = *reinterpret_cast<const float4*>(p + 4);
            }
            As[kq + 0][r] = v0.x; As[kq + 1][r] = v0.y;
            As[kq + 2][r] = v0.z; As[kq + 3][r] = v0.w;
            As[kq + 4][r] = v1.x; As[kq + 5][r] = v1.y;
            As[kq + 6][r] = v1.z; As[kq + 7][r] = v1.w;
        }
        // ---- B tile: 16 k x 128 n ----
        if (TRANSB) {
            int n  = tid >> 1;
            int kq = (tid & 1) << 3;
            const float* p = Bm + (size_t)(colBase + n) * K + kc + kq;
            float4 v0 = *reinterpret_cast<const float4*>(p);
            float4 v1 = *reinterpret_cast<const float4*>(p + 4);
            Bs[kq + 0][n] = v0.x; Bs[kq + 1][n] = v0.y;
            Bs[kq + 2][n] = v0.z; Bs[kq + 3][n] = v0.w;
            Bs[kq + 4][n] = v1.x; Bs[kq + 5][n] = v1.y;
            Bs[kq + 6][n] = v1.z; Bs[kq + 7][n] = v1.w;
        } else {
            int kk = tid >> 4;            // 0..15
            int nq = (tid & 15) << 3;     // 0..120
            const float* p = Bm + (size_t)(kc + kk) * N + colBase + nq;
            *reinterpret_cast<float4*>(&Bs[kk][nq])     = *reinterpret_cast<const float4*>(p);
            *reinterpret_cast<float4*>(&Bs[kk][nq + 4]) = *reinterpret_cast<const float4*>(p + 4);
        }
        __syncthreads();

#pragma unroll
        for (int k = 0; k < BK; k++) {
            float4 a0 = *reinterpret_cast<const float4*>(&As[k][ty * 8]);
            float4 a1 = *reinterpret_cast<const float4*>(&As[k][ty * 8 + 4]);
            float4 b0 = *reinterpret_cast<const float4*>(&Bs[k][tx * 8]);
            float4 b1 = *reinterpret_cast<const float4*>(&Bs[k][tx * 8 + 4]);
            float av[8] = {a0.x, a0.y, a0.z, a0.w, a1.x, a1.y, a1.z, a1.w};
            float bv[8] = {b0.x, b0.y, b0.z, b0.w, b1.x, b1.y, b1.z, b1.w};
#pragma unroll
            for (int i = 0; i < 8; i++)
#pragma unroll
                for (int j = 0; j < 8; j++)
                    c[i][j] += av[i] * bv[j];
        }
        __syncthreads();
    }

    // ---- epilogue ----
    double local = 0.0;
#pragma unroll
    for (int i = 0; i < 8; i++) {
        int r = rowBase + ty * 8 + i;
#pragma unroll
        for (int j = 0; j < 8; j++) {
            int nn = colBase + tx * 8 + j;
            size_t off = (size_t)r * N + nn;
            float z = c[i][j];
            if (bias_vec) z += bias_vec[nn];
            if (bias_arr) z += bias_arr[off];

            if (red_mode == 1) {  // softplus = max(z,0)+log1p(exp(-|z|))
                local += (double)(fmaxf(z, 0.f) + log1pf(expf(-fabsf(z))));
            }

            if (mode == 0) {
                if (outC) outC[off] = z;
            } else if (mode == 1) {
                outC[off] = tanhf(z);
            } else {  // bernoulli sample
                float p = 1.f / (1.f + expf(-z));
                float u = jx_uniform(rk0, rk1, (uint32_t)off, half);
                outC[off] = (u < p) ? 1.f : 0.f;
                if (out2) out2[off] = p;
                if (red_mode == 2) {
                    float v = vmon[off];
                    local += (double)(v * logf(p + 1e-10f)
                                      + (1.f - v) * logf(1.f - p + 1e-10f));
                }
            }
        }
    }

    if (red_mode) {
        __shared__ double rs[256];
        rs[tid] = local;
        __syncthreads();
        for (int s = 128; s > 0; s >>= 1) {
            if (tid < s) rs[tid] += rs[tid + s];
            __syncthreads();
        }
        if (tid == 0) atomicAdd(&red[slot], rs[0]);
    }
}

// ---------------------------------------------------------------------------
// dot-product reductions for the free-energy bias terms
// ---------------------------------------------------------------------------
__global__ void __launch_bounds__(256)
k_dots(const float* __restrict__ v,   const float* __restrict__ bvt,
       const float* __restrict__ vs,  const float* __restrict__ h1,
       const float* __restrict__ h1s, const float* __restrict__ bh1t,
       double* __restrict__ red)
{
    size_t i0  = (size_t)blockIdx.x * blockDim.x + threadIdx.x;
    size_t str = (size_t)gridDim.x * blockDim.x;
    size_t nv  = (size_t)SEQ_ * NV_;
    size_t nh  = (size_t)SEQ_ * NH_;
    double d5 = 0, d6 = 0, d7 = 0;
    for (size_t i = i0; i < nv; i += str) {
        float b = bvt[i];
        d5 += (double)(v[i]  * b);
        d6 += (double)(vs[i] * b);
    }
    for (size_t i = i0; i < nh; i += str)
        d7 += (double)((h1[i] - h1s[i]) * bh1t[i]);

    __shared__ double s5[256], s6[256], s7[256];
    int t = threadIdx.x;
    s5[t] = d5; s6[t] = d6; s7[t] = d7;
    __syncthreads();
    for (int s = 128; s > 0; s >>= 1) {
        if (t < s) { s5[t] += s5[t+s]; s6[t] += s6[t+s]; s7[t] += s7[t+s]; }
        __syncthreads();
    }
    if (t == 0) {
        atomicAdd(&red[5], s5[0]);
        atomicAdd(&red[6], s6[0]);
        atomicAdd(&red[7], s7[0]);
    }
}

__global__ void k_final(const double* __restrict__ red, float* __restrict__ out)
{
    double cost1 = (-red[5] - red[0] + red[6] + red[1]) / (double)SEQ_;
    double cost2 = (-red[7] - red[2] + red[3]) / (double)SEQ_;
    out[0] = (float)(cost1 + cost2);
    out[1] = (float)(red[4] / (double)SEQ_);
}

// ---------------------------------------------------------------------------
// host
// ---------------------------------------------------------------------------
static inline void launch_gemm(const float* A, int shiftA, const float* B, int transb,
                               int K, int N,
                               const float* bvec, const float* barr,
                               float* outC, float* out2, int mode,
                               int red_mode, int slot, const float* vmon,
                               uint32_t kk0, uint32_t kk1, double* acc)
{
    dim3 grid(N / BN, SEQ_ / BM), blk(256);
    uint32_t half = (uint32_t)(((size_t)SEQ_ * (size_t)N) / 2);
    if (transb)
        gemm_ep<true ><<<grid, blk>>>(A, shiftA, B, K, N, bvec, barr, outC, out2,
                                      mode, red_mode, slot, vmon, kk0, kk1, half, acc);
    else
        gemm_ep<false><<<grid, blk>>>(A, shiftA, B, K, N, bvec, barr, outC, out2,
                                      mode, red_mode, slot, vmon, kk0, kk1, half, acc);
}

extern "C" void kernel_launch(void* const* d_in, const int* in_sizes, int n_in,
                              void* d_out, int out_size)
{
    const float* v_seq = (const float*)d_in[0];
    const float* W1    = (const float*)d_in[1];
    const float* bv    = (const float*)d_in[2];
    const float* bh1   = (const float*)d_in[3];
    const float* W2    = (const float*)d_in[4];
    const float* bh2   = (const float*)d_in[5];
    const float* Wyv   = (const float*)d_in[6];
    const float* Wyh1  = (const float*)d_in[7];
    const float* Wyh2  = (const float*)d_in[8];
    const float* Wvu   = (const float*)d_in[9];
    const float* Wuu   = (const float*)d_in[10];
    const float* bu    = (const float*)d_in[11];
    float* out = (float*)d_out;

    float *X, *Ua, *Ub, *bvt, *bh1t, *bh2t, *h, *h1, *h2, *h1s, *vs;
    double* acc;
    cudaGetSymbolAddress((void**)&X,    g_X);
    cudaGetSymbolAddress((void**)&Ua,   g_Ua);
    cudaGetSymbolAddress((void**)&Ub,   g_Ub);
    cudaGetSymbolAddress((void**)&bvt,  g_bvt);
    cudaGetSymbolAddress((void**)&bh1t, g_bh1t);
    cudaGetSymbolAddress((void**)&bh2t, g_bh2t);
    cudaGetSymbolAddress((void**)&h,    g_h);
    cudaGetSymbolAddress((void**)&h1,   g_h1);
    cudaGetSymbolAddress((void**)&h2,   g_h2);
    cudaGetSymbolAddress((void**)&h1s,  g_h1s);
    cudaGetSymbolAddress((void**)&vs,   g_vs);
    cudaGetSymbolAddress((void**)&acc,  g_acc);

    // ---- JAX key schedule: key(42) -> 10x split(key,3) ----
    uint32_t kk0 = 0u, kk1 = 42u;
    uint32_t K1[10][2], K2[10][2];
    for (int i = 0; i < 10; i++) {
#if JAX_PARTITIONABLE
        uint32_t n0, n1, a0, a1, b0, b1;
        tf2x32(kk0, kk1, 0u, 0u, &n0, &n1);
        tf2x32(kk0, kk1, 0u, 1u, &a0, &a1);
        tf2x32(kk0, kk1, 0u, 2u, &b0, &b1);
        K1[i][0] = a0; K1[i][1] = a1;
        K2[i][0] = b0; K2[i][1] = b1;
        kk0 = n0; kk1 = n1;
#else
        uint32_t o00, o01, o10, o11, o20, o21;
        tf2x32(kk0, kk1, 0u, 3u, &o00, &o01);
        tf2x32(kk0, kk1, 1u, 4u, &o10, &o11);
        tf2x32(kk0, kk1, 2u, 5u, &o20, &o21);
        K1[i][0] = o20; K1[i][1] = o01;
        K2[i][0] = o11; K2[i][1] = o21;
        kk0 = o00; kk1 = o10;
#endif
    }

    k_init<<<1024, 256>>>();

    // X = v_seq @ Wvu + bu
    launch_gemm(v_seq, 0, Wvu, 0, NV_, NR_, bu, nullptr, X, nullptr, 0, 0, 0, nullptr, 0, 0, acc);

    // Jacobi sweeps: U <- tanh(X + shift(U) @ Wuu)
    for (int s = 0; s < NSWEEP; s++) {
        float* in    = (s % 2 == 0) ? Ua : Ub;
        float* out_u = (s % 2 == 0) ? Ub : Ua;
        launch_gemm(in, 1, Wuu, 0, NR_, NR_, nullptr, X, out_u, nullptr, 1, 0, 0, nullptr, 0, 0, acc);
    }
    // final U in Ua (NSWEEP even)

    // time-varying biases from shifted RNN output
    launch_gemm(Ua, 1, Wyv,  1, NR_, NV_, bv,  nullptr, bvt,  nullptr, 0, 0, 0, nullptr, 0, 0, acc);
    launch_gemm(Ua, 1, Wyh1, 1, NR_, NH_, bh1, nullptr, bh1t, nullptr, 0, 0, 0, nullptr, 0, 0, acc);
    launch_gemm(Ua, 1, Wyh2, 1, NR_, NH_, bh2, nullptr, bh2t, nullptr, 0, 0, 0, nullptr, 0, 0, acc);

    // ---- RBM1 CD-5 (splits 0..4). Iter 0 also yields h1 and FE1(v_seq) sp-sum.
    launch_gemm(v_seq, 0, W1, 0, NV_, NH_, nullptr, bh1t, h, h1, 2, 1, 0, nullptr,
                K1[0][0], K1[0][1], acc);
    launch_gemm(h, 0, W1, 1, NH_, NV_, nullptr, bvt, vs, nullptr, 2, 0, 0, nullptr,
                K2[0][0], K2[0][1], acc);
    for (int i = 1; i < CDK_ - 1; i++) {
        launch_gemm(vs, 0, W1, 0, NV_, NH_, nullptr, bh1t, h, nullptr, 2, 0, 0, nullptr,
                    K1[i][0], K1[i][1], acc);
        launch_gemm(h, 0, W1, 1, NH_, NV_, nullptr, bvt, vs, nullptr, 2, 0, 0, nullptr,
                    K2[i][0], K2[i][1], acc);
    }
    // last iter: the v-GEMM also accumulates the monitor with mean_v
    launch_gemm(vs, 0, W1, 0, NV_, NH_, nullptr, bh1t, h, nullptr, 2, 0, 0, nullptr,
                K1[CDK_-1][0], K1[CDK_-1][1], acc);
    launch_gemm(h, 0, W1, 1, NH_, NV_, nullptr, bvt, vs, nullptr, 2, 2, 4, v_seq,
                K2[CDK_-1][0], K2[CDK_-1][1], acc);

    // FE1(v_sample): softplus(vs@W1 + bh1t)
    launch_gemm(vs, 0, W1, 0, NV_, NH_, nullptr, bh1t, nullptr, nullptr, 0, 1, 1, nullptr,
                0, 0, acc);

    // ---- RBM2 CD-5 (splits 5..9). Iter 0 GEMM shares z with FE2(h1) sp-sum.
    launch_gemm(h1, 0, W2, 0, NH_, NH_, nullptr, bh2t, h2, nullptr, 2, 1, 2, nullptr,
                K1[5][0], K1[5][1], acc);
    launch_gemm(h2, 0, W2, 1, NH_, NH_, nullptr, bh1t, h1s, nullptr, 2, 0, 0, nullptr,
                K2[5][0], K2[5][1], acc);
    for (int i = 6; i < 10; i++) {
        launch_gemm(h1s, 0, W2, 0, NH_, NH_, nullptr, bh2t, h2, nullptr, 2, 0, 0, nullptr,
                    K1[i][0], K1[i][1], acc);
        launch_gemm(h2, 0, W2, 1, NH_, NH_, nullptr, bh1t, h1s, nullptr, 2, 0, 0, nullptr,
                    K2[i][0], K2[i][1], acc);
    }

    // FE2(h1_sample): softplus(h1s@W2 + bh2t)
    launch_gemm(h1s, 0, W2, 0, NH_, NH_, nullptr, bh2t, nullptr, nullptr, 0, 1, 3, nullptr,
                0, 0, acc);

    // bias dot terms + finalize
    k_dots<<<2048, 256>>>(v_seq, bvt, vs, h1, h1s, bh1t, acc);
    k_final<<<1, 1>>>(acc, out);
}

// round 10
// speedup vs baseline: 1.4716x; 1.4716x over previous
#include <cuda_runtime.h>
#include <stdint.h>
#include <math.h>

#define SEQ_   32768
#define NV_    256
#define NH_    512
#define NR_    256
#define CDK_   5
#define NSWEEP 10

// JAX >= 0.5 default: jax_threefry_partitionable = True
#define JAX_PARTITIONABLE 1

// ---------------------------------------------------------------------------
// Scratch (device globals; allocation-free per harness rules)
// ---------------------------------------------------------------------------
__device__ float g_X   [(size_t)SEQ_ * NR_];
__device__ float g_Ua  [(size_t)SEQ_ * NR_];
__device__ float g_Ub  [(size_t)SEQ_ * NR_];
__device__ float g_bvt [(size_t)SEQ_ * NV_];
__device__ float g_bh1t[(size_t)SEQ_ * NH_];
__device__ float g_bh2t[(size_t)SEQ_ * NH_];
__device__ float g_h   [(size_t)SEQ_ * NH_];
__device__ float g_h1  [(size_t)SEQ_ * NH_];
__device__ float g_h2  [(size_t)SEQ_ * NH_];
__device__ float g_h1s [(size_t)SEQ_ * NH_];
__device__ float g_vs  [(size_t)SEQ_ * NV_];
// 0: sum sp(v_seq)   1: sum sp(v_sample)  2: sum sp(h1)  3: sum sp(h1_sample)
// 4: monitor sum     5: sum v_seq.bvt     6: sum vs.bvt  7: sum (h1-h1s).bh1t
__device__ double g_acc[8];

// ---------------------------------------------------------------------------
// Threefry-2x32 (20 rounds) — exactly JAX's cipher
// ---------------------------------------------------------------------------
__host__ __device__ __forceinline__
void tf2x32(uint32_t k0, uint32_t k1, uint32_t x0, uint32_t x1,
            uint32_t* o0, uint32_t* o1)
{
    uint32_t ks2 = k0 ^ k1 ^ 0x1BD11BDAu;
    x0 += k0; x1 += k1;
#define TF_RND(R) { x0 += x1; x1 = (x1 << (R)) | (x1 >> (32 - (R))); x1 ^= x0; }
    TF_RND(13) TF_RND(15) TF_RND(26) TF_RND(6)
    x0 += k1;  x1 += ks2 + 1u;
    TF_RND(17) TF_RND(29) TF_RND(16) TF_RND(24)
    x0 += ks2; x1 += k0 + 2u;
    TF_RND(13) TF_RND(15) TF_RND(26) TF_RND(6)
    x0 += k0;  x1 += k1 + 3u;
    TF_RND(17) TF_RND(29) TF_RND(16) TF_RND(24)
    x0 += k1;  x1 += ks2 + 4u;
    TF_RND(13) TF_RND(15) TF_RND(26) TF_RND(6)
    x0 += ks2; x1 += k0 + 5u;
#undef TF_RND
    *o0 = x0; *o1 = x1;
}

__device__ __forceinline__
float jx_uniform(uint32_t k0, uint32_t k1, uint32_t idx, uint32_t half)
{
    uint32_t bits;
#if JAX_PARTITIONABLE
    uint32_t o0, o1;
    tf2x32(k0, k1, 0u, idx, &o0, &o1);
    bits = o0 ^ o1;
#else
    uint32_t o0, o1;
    if (idx < half) { tf2x32(k0, k1, idx, idx + half, &o0, &o1); bits = o0; }
    else            { tf2x32(k0, k1, idx - half, idx, &o0, &o1); bits = o1; }
#endif
    return __uint_as_float((bits >> 9) | 0x3f800000u) - 1.0f;
}

__device__ __forceinline__ float to_tf32(float x)
{
    uint32_t u;
    asm("cvt.rna.tf32.f32 %0, %1;" : "=r"(u) : "f"(x));
    return __uint_as_float(u);
}

// ---------------------------------------------------------------------------
// init
// ---------------------------------------------------------------------------
__global__ void k_init()
{
    size_t i   = (size_t)blockIdx.x * blockDim.x + threadIdx.x;
    size_t tot = (size_t)SEQ_ * NR_;
    size_t str = (size_t)gridDim.x * blockDim.x;
    for (size_t j = i; j < tot; j += str) g_Ua[j] = 0.0f;
    if (i < 8) g_acc[i] = 0.0;
}

// ---------------------------------------------------------------------------
// Fused tf32 tensor-core GEMM:  C[S,N] = A[S,K] @ B (+biases, fused epilogue)
//   Block 128x128x32, 8 warps, warp tile 64x32 (mma.m16n8k8.tf32).
//   TRANSB: B source is [N,K]; else [K,N].
//   shiftA: row t of A reads source row t-1 (row 0 -> zeros)
//   mode  : 0=linear  1=tanh  2=bernoulli(sigmoid) sample (out2 gets p)
//   red   : 0=none  1=sum softplus(z)  2=sum monitor(vmon, p)  -> red[slot]
// ---------------------------------------------------------------------------
#define BM 128
#define BN 128
#define BK 32
#define SPAD 8

template<bool TRANSB>
__global__ void __launch_bounds__(256, 2)
gemm_ep(const float* __restrict__ A, int shiftA,
        const float* __restrict__ Bm, int K, int N,
        const float* __restrict__ bias_vec,
        const float* __restrict__ bias_arr,
        float* __restrict__ outC, float* __restrict__ out2,
        int mode, int red_mode, int slot,
        const float* __restrict__ vmon,
        uint32_t rk0, uint32_t rk1, uint32_t half,
        double* __restrict__ red)
{
    __shared__ float As[BK][BM + SPAD];   // k-major
    __shared__ float Bs[BK][BN + SPAD];   // k-major

    const int tid  = threadIdx.x;
    const int lane = tid & 31;
    const int wid  = tid >> 5;            // 0..7
    const int warpM = wid >> 2;           // 0..1  (x64 rows)
    const int warpN = wid & 3;            // 0..3  (x32 cols)
    const int qr = lane >> 2;             // 0..7
    const int qc = lane & 3;              // 0..3
    const int rowBase = blockIdx.y * BM;
    const int colBase = blockIdx.x * BN;
    const int mBase = warpM * 64;
    const int nBase = warpN * 32;

    float c[4][4][4];
#pragma unroll
    for (int mt = 0; mt < 4; mt++)
#pragma unroll
        for (int nt = 0; nt < 4; nt++)
#pragma unroll
            for (int e = 0; e < 4; e++) c[mt][nt][e] = 0.0f;

    for (int kc = 0; kc < K; kc += BK) {
        // ---- A tile: 128 rows x 32 k -> As[k][m] (tf32) ----
        {
            int r  = tid & 127;
            int kq = (tid >> 7) << 4;   // 0 or 16
            int srow = rowBase + r - shiftA;
            float v[16];
            if (srow >= 0) {
                const float* p = A + (size_t)srow * K + kc + kq;
#pragma unroll
                for (int q = 0; q < 4; q++) {
                    float4 t = *reinterpret_cast<const float4*>(p + q * 4);
                    v[q*4+0] = t.x; v[q*4+1] = t.y; v[q*4+2] = t.z; v[q*4+3] = t.w;
                }
            } else {
#pragma unroll
                for (int j = 0; j < 16; j++) v[j] = 0.0f;
            }
#pragma unroll
            for (int j = 0; j < 16; j++) As[kq + j][r] = to_tf32(v[j]);
        }
        // ---- B tile -> Bs[k][n] (tf32) ----
        if (TRANSB) {
            int n  = tid & 127;
            int kq = (tid >> 7) << 4;
            const float* p = Bm + (size_t)(colBase + n) * K + kc + kq;
            float v[16];
#pragma unroll
            for (int q = 0; q < 4; q++) {
                float4 t = *reinterpret_cast<const float4*>(p + q * 4);
                v[q*4+0] = t.x; v[q*4+1] = t.y; v[q*4+2] = t.z; v[q*4+3] = t.w;
            }
#pragma unroll
            for (int j = 0; j < 16; j++) Bs[kq + j][n] = to_tf32(v[j]);
        } else {
            int k  = tid >> 3;            // 0..31
            int nq = (tid & 7) << 4;      // 0..112
            const float* p = Bm + (size_t)(kc + k) * N + colBase + nq;
#pragma unroll
            for (int q = 0; q < 4; q++) {
                float4 t = *reinterpret_cast<const float4*>(p + q * 4);
                float4 w;
                w.x = to_tf32(t.x); w.y = to_tf32(t.y);
                w.z = to_tf32(t.z); w.w = to_tf32(t.w);
                *reinterpret_cast<float4*>(&Bs[k][nq + q * 4]) = w;
            }
        }
        __syncthreads();

#pragma unroll
        for (int kk = 0; kk < 4; kk++) {
            uint32_t af[4][4];
#pragma unroll
            for (int mt = 0; mt < 4; mt++) {
                int m0 = mBase + mt * 16;
                af[mt][0] = __float_as_uint(As[kk*8 + qc    ][m0 + qr    ]);
                af[mt][1] = __float_as_uint(As[kk*8 + qc    ][m0 + qr + 8]);
                af[mt][2] = __float_as_uint(As[kk*8 + qc + 4][m0 + qr    ]);
                af[mt][3] = __float_as_uint(As[kk*8 + qc + 4][m0 + qr + 8]);
            }
            uint32_t bf[4][2];
#pragma unroll
            for (int nt = 0; nt < 4; nt++) {
                int n0 = nBase + nt * 8;
                bf[nt][0] = __float_as_uint(Bs[kk*8 + qc    ][n0 + qr]);
                bf[nt][1] = __float_as_uint(Bs[kk*8 + qc + 4][n0 + qr]);
            }
#pragma unroll
            for (int mt = 0; mt < 4; mt++)
#pragma unroll
                for (int nt = 0; nt < 4; nt++) {
                    asm volatile(
                        "mma.sync.aligned.m16n8k8.row.col.f32.tf32.tf32.f32 "
                        "{%0,%1,%2,%3}, {%4,%5,%6,%7}, {%8,%9}, {%0,%1,%2,%3};"
                        : "+f"(c[mt][nt][0]), "+f"(c[mt][nt][1]),
                          "+f"(c[mt][nt][2]), "+f"(c[mt][nt][3])
                        : "r"(af[mt][0]), "r"(af[mt][1]),
                          "r"(af[mt][2]), "r"(af[mt][3]),
                          "r"(bf[nt][0]), "r"(bf[nt][1]));
                }
        }
        __syncthreads();
    }

    // ---- epilogue (fragment layout: e0:(qr,2qc) e1:(qr,2qc+1) e2:+8row e3) ----
    double local = 0.0;
#pragma unroll
    for (int mt = 0; mt < 4; mt++) {
#pragma unroll
        for (int nt = 0; nt < 4; nt++) {
#pragma unroll
            for (int e = 0; e < 4; e++) {
                int r  = rowBase + mBase + mt * 16 + qr + ((e >> 1) << 3);
                int nn = colBase + nBase + nt * 8 + (qc << 1) + (e & 1);
                size_t off = (size_t)r * N + nn;
                float z = c[mt][nt][e];
                if (bias_vec) z += bias_vec[nn];
                if (bias_arr) z += bias_arr[off];

                if (red_mode == 1) {  // softplus
                    local += (double)(fmaxf(z, 0.f) + log1pf(expf(-fabsf(z))));
                }

                if (mode == 0) {
                    if (outC) outC[off] = z;
                } else if (mode == 1) {
                    outC[off] = tanhf(z);
                } else {  // bernoulli sample
                    float p = 1.f / (1.f + expf(-z));
                    float u = jx_uniform(rk0, rk1, (uint32_t)off, half);
                    outC[off] = (u < p) ? 1.f : 0.f;
                    if (out2) out2[off] = p;
                    if (red_mode == 2) {
                        float v = vmon[off];
                        local += (double)(v * logf(p + 1e-10f)
                                          + (1.f - v) * logf(1.f - p + 1e-10f));
                    }
                }
            }
        }
    }

    if (red_mode) {
        __shared__ double rs[256];
        rs[tid] = local;
        __syncthreads();
        for (int s = 128; s > 0; s >>= 1) {
            if (tid < s) rs[tid] += rs[tid + s];
            __syncthreads();
        }
        if (tid == 0) atomicAdd(&red[slot], rs[0]);
    }
}

// ---------------------------------------------------------------------------
// dot-product reductions for the free-energy bias terms
// ---------------------------------------------------------------------------
__global__ void __launch_bounds__(256)
k_dots(const float* __restrict__ v,   const float* __restrict__ bvt,
       const float* __restrict__ vs,  const float* __restrict__ h1,
       const float* __restrict__ h1s, const float* __restrict__ bh1t,
       double* __restrict__ red)
{
    size_t i0  = (size_t)blockIdx.x * blockDim.x + threadIdx.x;
    size_t str = (size_t)gridDim.x * blockDim.x;
    size_t nv  = (size_t)SEQ_ * NV_;
    size_t nh  = (size_t)SEQ_ * NH_;
    double d5 = 0, d6 = 0, d7 = 0;
    for (size_t i = i0; i < nv; i += str) {
        float b = bvt[i];
        d5 += (double)(v[i]  * b);
        d6 += (double)(vs[i] * b);
    }
    for (size_t i = i0; i < nh; i += str)
        d7 += (double)((h1[i] - h1s[i]) * bh1t[i]);

    __shared__ double s5[256], s6[256], s7[256];
    int t = threadIdx.x;
    s5[t] = d5; s6[t] = d6; s7[t] = d7;
    __syncthreads();
    for (int s = 128; s > 0; s >>= 1) {
        if (t < s) { s5[t] += s5[t+s]; s6[t] += s6[t+s]; s7[t] += s7[t+s]; }
        __syncthreads();
    }
    if (t == 0) {
        atomicAdd(&red[5], s5[0]);
        atomicAdd(&red[6], s6[0]);
        atomicAdd(&red[7], s7[0]);
    }
}

__global__ void k_final(const double* __restrict__ red, float* __restrict__ out)
{
    double cost1 = (-red[5] - red[0] + red[6] + red[1]) / (double)SEQ_;
    double cost2 = (-red[7] - red[2] + red[3]) / (double)SEQ_;
    out[0] = (float)(cost1 + cost2);
    out[1] = (float)(red[4] / (double)SEQ_);
}

// ---------------------------------------------------------------------------
// host
// ---------------------------------------------------------------------------
static inline void launch_gemm(const float* A, int shiftA, const float* B, int transb,
                               int K, int N,
                               const float* bvec, const float* barr,
                               float* outC, float* out2, int mode,
                               int red_mode, int slot, const float* vmon,
                               uint32_t kk0, uint32_t kk1, double* acc)
{
    dim3 grid(N / BN, SEQ_ / BM), blk(256);
    uint32_t half = (uint32_t)(((size_t)SEQ_ * (size_t)N) / 2);
    if (transb)
        gemm_ep<true ><<<grid, blk>>>(A, shiftA, B, K, N, bvec, barr, outC, out2,
                                      mode, red_mode, slot, vmon, kk0, kk1, half, acc);
    else
        gemm_ep<false><<<grid, blk>>>(A, shiftA, B, K, N, bvec, barr, outC, out2,
                                      mode, red_mode, slot, vmon, kk0, kk1, half, acc);
}

extern "C" void kernel_launch(void* const* d_in, const int* in_sizes, int n_in,
                              void* d_out, int out_size)
{
    const float* v_seq = (const float*)d_in[0];
    const float* W1    = (const float*)d_in[1];
    const float* bv    = (const float*)d_in[2];
    const float* bh1   = (const float*)d_in[3];
    const float* W2    = (const float*)d_in[4];
    const float* bh2   = (const float*)d_in[5];
    const float* Wyv   = (const float*)d_in[6];
    const float* Wyh1  = (const float*)d_in[7];
    const float* Wyh2  = (const float*)d_in[8];
    const float* Wvu   = (const float*)d_in[9];
    const float* Wuu   = (const float*)d_in[10];
    const float* bu    = (const float*)d_in[11];
    float* out = (float*)d_out;

    float *X, *Ua, *Ub, *bvt, *bh1t, *bh2t, *h, *h1, *h2, *h1s, *vs;
    double* acc;
    cudaGetSymbolAddress((void**)&X,    g_X);
    cudaGetSymbolAddress((void**)&Ua,   g_Ua);
    cudaGetSymbolAddress((void**)&Ub,   g_Ub);
    cudaGetSymbolAddress((void**)&bvt,  g_bvt);
    cudaGetSymbolAddress((void**)&bh1t, g_bh1t);
    cudaGetSymbolAddress((void**)&bh2t, g_bh2t);
    cudaGetSymbolAddress((void**)&h,    g_h);
    cudaGetSymbolAddress((void**)&h1,   g_h1);
    cudaGetSymbolAddress((void**)&h2,   g_h2);
    cudaGetSymbolAddress((void**)&h1s,  g_h1s);
    cudaGetSymbolAddress((void**)&vs,   g_vs);
    cudaGetSymbolAddress((void**)&acc,  g_acc);

    // ---- JAX key schedule: key(42) -> 10x split(key,3) ----
    uint32_t kk0 = 0u, kk1 = 42u;
    uint32_t K1[10][2], K2[10][2];
    for (int i = 0; i < 10; i++) {
#if JAX_PARTITIONABLE
        uint32_t n0, n1, a0, a1, b0, b1;
        tf2x32(kk0, kk1, 0u, 0u, &n0, &n1);
        tf2x32(kk0, kk1, 0u, 1u, &a0, &a1);
        tf2x32(kk0, kk1, 0u, 2u, &b0, &b1);
        K1[i][0] = a0; K1[i][1] = a1;
        K2[i][0] = b0; K2[i][1] = b1;
        kk0 = n0; kk1 = n1;
#else
        uint32_t o00, o01, o10, o11, o20, o21;
        tf2x32(kk0, kk1, 0u, 3u, &o00, &o01);
        tf2x32(kk0, kk1, 1u, 4u, &o10, &o11);
        tf2x32(kk0, kk1, 2u, 5u, &o20, &o21);
        K1[i][0] = o20; K1[i][1] = o01;
        K2[i][0] = o11; K2[i][1] = o21;
        kk0 = o00; kk1 = o10;
#endif
    }

    k_init<<<1024, 256>>>();

    // X = v_seq @ Wvu + bu
    launch_gemm(v_seq, 0, Wvu, 0, NV_, NR_, bu, nullptr, X, nullptr, 0, 0, 0, nullptr, 0, 0, acc);

    // Jacobi sweeps: U <- tanh(X + shift(U) @ Wuu)
    for (int s = 0; s < NSWEEP; s++) {
        float* in    = (s % 2 == 0) ? Ua : Ub;
        float* out_u = (s % 2 == 0) ? Ub : Ua;
        launch_gemm(in, 1, Wuu, 0, NR_, NR_, nullptr, X, out_u, nullptr, 1, 0, 0, nullptr, 0, 0, acc);
    }
    // final U in Ua (NSWEEP even)

    // time-varying biases from shifted RNN output
    launch_gemm(Ua, 1, Wyv,  1, NR_, NV_, bv,  nullptr, bvt,  nullptr, 0, 0, 0, nullptr, 0, 0, acc);
    launch_gemm(Ua, 1, Wyh1, 1, NR_, NH_, bh1, nullptr, bh1t, nullptr, 0, 0, 0, nullptr, 0, 0, acc);
    launch_gemm(Ua, 1, Wyh2, 1, NR_, NH_, bh2, nullptr, bh2t, nullptr, 0, 0, 0, nullptr, 0, 0, acc);

    // ---- RBM1 CD-5 (splits 0..4). Iter 0 also yields h1 and FE1(v_seq) sp-sum.
    launch_gemm(v_seq, 0, W1, 0, NV_, NH_, nullptr, bh1t, h, h1, 2, 1, 0, nullptr,
                K1[0][0], K1[0][1], acc);
    launch_gemm(h, 0, W1, 1, NH_, NV_, nullptr, bvt, vs, nullptr, 2, 0, 0, nullptr,
                K2[0][0], K2[0][1], acc);
    for (int i = 1; i < CDK_ - 1; i++) {
        launch_gemm(vs, 0, W1, 0, NV_, NH_, nullptr, bh1t, h, nullptr, 2, 0, 0, nullptr,
                    K1[i][0], K1[i][1], acc);
        launch_gemm(h, 0, W1, 1, NH_, NV_, nullptr, bvt, vs, nullptr, 2, 0, 0, nullptr,
                    K2[i][0], K2[i][1], acc);
    }
    // last iter: the v-GEMM also accumulates the monitor with mean_v
    launch_gemm(vs, 0, W1, 0, NV_, NH_, nullptr, bh1t, h, nullptr, 2, 0, 0, nullptr,
                K1[CDK_-1][0], K1[CDK_-1][1], acc);
    launch_gemm(h, 0, W1, 1, NH_, NV_, nullptr, bvt, vs, nullptr, 2, 2, 4, v_seq,
                K2[CDK_-1][0], K2[CDK_-1][1], acc);

    // FE1(v_sample): softplus(vs@W1 + bh1t)
    launch_gemm(vs, 0, W1, 0, NV_, NH_, nullptr, bh1t, nullptr, nullptr, 0, 1, 1, nullptr,
                0, 0, acc);

    // ---- RBM2 CD-5 (splits 5..9). Iter 0 GEMM shares z with FE2(h1) sp-sum.
    launch_gemm(h1, 0, W2, 0, NH_, NH_, nullptr, bh2t, h2, nullptr, 2, 1, 2, nullptr,
                K1[5][0], K1[5][1], acc);
    launch_gemm(h2, 0, W2, 1, NH_, NH_, nullptr, bh1t, h1s, nullptr, 2, 0, 0, nullptr,
                K2[5][0], K2[5][1], acc);
    for (int i = 6; i < 10; i++) {
        launch_gemm(h1s, 0, W2, 0, NH_, NH_, nullptr, bh2t, h2, nullptr, 2, 0, 0, nullptr,
                    K1[i][0], K1[i][1], acc);
        launch_gemm(h2, 0, W2, 1, NH_, NH_, nullptr, bh1t, h1s, nullptr, 2, 0, 0, nullptr,
                    K2[i][0], K2[i][1], acc);
    }

    // FE2(h1_sample): softplus(h1s@W2 + bh2t)
    launch_gemm(h1s, 0, W2, 0, NH_, NH_, nullptr, bh2t, nullptr, nullptr, 0, 1, 3, nullptr,
                0, 0, acc);

    // bias dot terms + finalize
    k_dots<<<2048, 256>>>(v_seq, bvt, vs, h1, h1s, bh1t, acc);
    k_final<<<1, 1>>>(acc, out);
}

// round 11
// speedup vs baseline: 1.9852x; 1.3491x over previous
#include <cuda_runtime.h>
#include <stdint.h>
#include <math.h>

#define SEQ_   32768
#define NV_    256
#define NH_    512
#define NR_    256
#define CDK_   5
#define NSWEEP 10

// JAX >= 0.5 default: jax_threefry_partitionable = True
#define JAX_PARTITIONABLE 1

// ---------------------------------------------------------------------------
// Scratch (device globals; allocation-free per harness rules)
// ---------------------------------------------------------------------------
__device__ float g_X   [(size_t)SEQ_ * NR_];
__device__ float g_Ua  [(size_t)SEQ_ * NR_];
__device__ float g_Ub  [(size_t)SEQ_ * NR_];
__device__ float g_bvt [(size_t)SEQ_ * NV_];
__device__ float g_bh1t[(size_t)SEQ_ * NH_];
__device__ float g_bh2t[(size_t)SEQ_ * NH_];
__device__ float g_h   [(size_t)SEQ_ * NH_];
__device__ float g_h1  [(size_t)SEQ_ * NH_];
__device__ float g_h2  [(size_t)SEQ_ * NH_];
__device__ float g_h1s [(size_t)SEQ_ * NH_];
__device__ float g_vs  [(size_t)SEQ_ * NV_];
// 0: sum sp(v_seq)   1: sum sp(v_sample)  2: sum sp(h1)  3: sum sp(h1_sample)
// 4: monitor sum     5: sum v_seq.bvt     6: sum vs.bvt  7: sum (h1-h1s).bh1t
__device__ double g_acc[8];

// ---------------------------------------------------------------------------
// Threefry-2x32 (20 rounds) — exactly JAX's cipher
// ---------------------------------------------------------------------------
__host__ __device__ __forceinline__
void tf2x32(uint32_t k0, uint32_t k1, uint32_t x0, uint32_t x1,
            uint32_t* o0, uint32_t* o1)
{
    uint32_t ks2 = k0 ^ k1 ^ 0x1BD11BDAu;
    x0 += k0; x1 += k1;
#define TF_RND(R) { x0 += x1; x1 = (x1 << (R)) | (x1 >> (32 - (R))); x1 ^= x0; }
    TF_RND(13) TF_RND(15) TF_RND(26) TF_RND(6)
    x0 += k1;  x1 += ks2 + 1u;
    TF_RND(17) TF_RND(29) TF_RND(16) TF_RND(24)
    x0 += ks2; x1 += k0 + 2u;
    TF_RND(13) TF_RND(15) TF_RND(26) TF_RND(6)
    x0 += k0;  x1 += k1 + 3u;
    TF_RND(17) TF_RND(29) TF_RND(16) TF_RND(24)
    x0 += k1;  x1 += ks2 + 4u;
    TF_RND(13) TF_RND(15) TF_RND(26) TF_RND(6)
    x0 += ks2; x1 += k0 + 5u;
#undef TF_RND
    *o0 = x0; *o1 = x1;
}

__device__ __forceinline__
float jx_uniform(uint32_t k0, uint32_t k1, uint32_t idx, uint32_t half)
{
    uint32_t bits;
#if JAX_PARTITIONABLE
    uint32_t o0, o1;
    tf2x32(k0, k1, 0u, idx, &o0, &o1);
    bits = o0 ^ o1;
#else
    uint32_t o0, o1;
    if (idx < half) { tf2x32(k0, k1, idx, idx + half, &o0, &o1); bits = o0; }
    else            { tf2x32(k0, k1, idx - half, idx, &o0, &o1); bits = o1; }
#endif
    return __uint_as_float((bits >> 9) | 0x3f800000u) - 1.0f;
}

__device__ __forceinline__ uint32_t smem_u32(const void* p)
{
    uint32_t a;
    asm("{ .reg .u64 t; cvta.to.shared.u64 t, %1; cvt.u32.u64 %0, t; }"
        : "=r"(a) : "l"(p));
    return a;
}

__device__ __forceinline__ void cp16(uint32_t dst, const void* src, bool pred)
{
    int sz = pred ? 16 : 0;
    asm volatile("cp.async.cg.shared.global [%0], [%1], 16, %2;"
                 :: "r"(dst), "l"(src), "r"(sz));
}
__device__ __forceinline__ void cp4(uint32_t dst, const void* src)
{
    asm volatile("cp.async.ca.shared.global [%0], [%1], 4;"
                 :: "r"(dst), "l"(src));
}
__device__ __forceinline__ void ldsm_x4(uint32_t& r0, uint32_t& r1,
                                        uint32_t& r2, uint32_t& r3, uint32_t addr)
{
    asm volatile("ldmatrix.sync.aligned.m8n8.x4.shared.b16 {%0,%1,%2,%3}, [%4];"
                 : "=r"(r0), "=r"(r1), "=r"(r2), "=r"(r3) : "r"(addr));
}

// ---------------------------------------------------------------------------
// init
// ---------------------------------------------------------------------------
__global__ void k_init()
{
    size_t i   = (size_t)blockIdx.x * blockDim.x + threadIdx.x;
    size_t tot = (size_t)SEQ_ * NR_;
    size_t str = (size_t)gridDim.x * blockDim.x;
    for (size_t j = i; j < tot; j += str) g_Ua[j] = 0.0f;
    if (i < 8) g_acc[i] = 0.0;
}

// ---------------------------------------------------------------------------
// Fused tf32 tensor-core GEMM, ldmatrix + cp.async 2-stage pipeline.
//   C[S,N] = A[S,K] @ B (+biases, fused epilogue)
//   Block 128x128x32, 8 warps, warp tile 64x32 (mma.m16n8k8.tf32).
//   Smem: A row-major [m][k], B n-major [n][k], 16B-chunk swizzle c^(row&7).
//   TRANSB: B source is [N,K]; else [K,N] (transposed via 4B cp.async).
//   shiftA: row t of A reads source row t-1 (row 0 -> zeros, cp.async zfill)
//   mode  : 0=linear  1=tanh  2=bernoulli(sigmoid) sample (out2 gets p)
//   red   : 0=none  1=sum softplus(z)  2=sum monitor(vmon, p)  -> red[slot]
// ---------------------------------------------------------------------------
#define BM 128
#define BN 128
#define BK 32
#define GEMM_SMEM (2 * (BM * BK + BN * BK) * 4)   // 65536 bytes

template<bool TRANSB>
__global__ void __launch_bounds__(256, 2)
gemm_ep(const float* __restrict__ A, int shiftA,
        const float* __restrict__ Bm, int K, int N,
        const float* __restrict__ bias_vec,
        const float* __restrict__ bias_arr,
        float* __restrict__ outC, float* __restrict__ out2,
        int mode, int red_mode, int slot,
        const float* __restrict__ vmon,
        uint32_t rk0, uint32_t rk1, uint32_t half,
        double* __restrict__ red)
{
    extern __shared__ float dsm[];
    const uint32_t sA = smem_u32(dsm);                       // [2][BM][BK]
    const uint32_t sB = sA + 2u * BM * BK * 4u;              // [2][BN][BK]

    const int tid  = threadIdx.x;
    const int lane = tid & 31;
    const int wid  = tid >> 5;
    const int warpM = wid >> 2;           // 0..1
    const int warpN = wid & 3;            // 0..3
    const int qr = lane >> 2;
    const int qc = lane & 3;
    const int rowBase = blockIdx.y * BM;
    const int colBase = blockIdx.x * BN;
    const int mBase = warpM * 64;
    const int nBase = warpN * 32;

    float c[4][4][4];
#pragma unroll
    for (int mt = 0; mt < 4; mt++)
#pragma unroll
        for (int nt = 0; nt < 4; nt++)
#pragma unroll
            for (int e = 0; e < 4; e++) c[mt][nt][e] = 0.0f;

    // ---- tile loader (cp.async) ----
    auto load_tile = [&](int st, int kc) {
        // A: 128 rows x 8 chunks of 16B
#pragma unroll
        for (int p = 0; p < 4; p++) {
            int idx = p * 256 + tid;
            int r   = idx >> 3;
            int ch  = idx & 7;
            int srow = rowBase + r - shiftA;
            const float* src = A + (size_t)(srow < 0 ? 0 : srow) * K + kc + ch * 4;
            uint32_t dst = sA + (((uint32_t)st * BM + r) * BK
                                 + ((uint32_t)(ch ^ (r & 7)) << 2)) * 4u;
            cp16(dst, src, srow >= 0);
        }
        if (TRANSB) {
            // B source [N,K]: n-major rows, same pattern as A
#pragma unroll
            for (int p = 0; p < 4; p++) {
                int idx = p * 256 + tid;
                int n   = idx >> 3;
                int ch  = idx & 7;
                const float* src = Bm + (size_t)(colBase + n) * K + kc + ch * 4;
                uint32_t dst = sB + (((uint32_t)st * BN + n) * BK
                                     + ((uint32_t)(ch ^ (n & 7)) << 2)) * 4u;
                cp16(dst, src, true);
            }
        } else {
            // B source [K,N]: transpose into n-major smem via 4B cp.async
#pragma unroll
            for (int p = 0; p < 16; p++) {
                int idx = p * 256 + tid;
                int n   = idx & 127;
                int k   = idx >> 7;
                const float* src = Bm + (size_t)(kc + k) * N + colBase + n;
                uint32_t dst = sB + (((uint32_t)st * BN + n) * BK
                                     + ((uint32_t)(((k >> 2) ^ (n & 7)) << 2) + (k & 3)) * 1u) * 4u;
                cp4(dst, src);
            }
        }
    };

    const int T = K / BK;
    load_tile(0, 0);
    asm volatile("cp.async.commit_group;" ::: "memory");

    for (int t = 0; t < T; t++) {
        if (t + 1 < T) {
            load_tile((t + 1) & 1, (t + 1) * BK);
            asm volatile("cp.async.commit_group;" ::: "memory");
            asm volatile("cp.async.wait_group 1;" ::: "memory");
        } else {
            asm volatile("cp.async.wait_group 0;" ::: "memory");
        }
        __syncthreads();

        const int st = t & 1;
        const uint32_t aStage = sA + (uint32_t)st * BM * BK * 4u;
        const uint32_t bStage = sB + (uint32_t)st * BN * BK * 4u;

#pragma unroll
        for (int kk = 0; kk < 4; kk++) {
            // A fragments: one ldmatrix.x4 per 16-row tile
            uint32_t af[4][4];
#pragma unroll
            for (int mt = 0; mt < 4; mt++) {
                int row = mBase + mt * 16 + (lane & 15);
                int ch  = (2 * kk + (lane >> 4)) ^ (row & 7);
                uint32_t addr = aStage + ((uint32_t)row * BK + ((uint32_t)ch << 2)) * 4u;
                ldsm_x4(af[mt][0], af[mt][1], af[mt][2], af[mt][3], addr);
            }
            // B fragments: one ldmatrix.x4 covers two n-tiles (2 regs each)
            uint32_t bf[2][4];
#pragma unroll
            for (int pr = 0; pr < 2; pr++) {
                int n  = nBase + pr * 16 + (lane & 7) + ((lane >> 4) << 3);
                int ch = (2 * kk + ((lane >> 3) & 1)) ^ (n & 7);
                uint32_t addr = bStage + ((uint32_t)n * BK + ((uint32_t)ch << 2)) * 4u;
                ldsm_x4(bf[pr][0], bf[pr][1], bf[pr][2], bf[pr][3], addr);
            }
#pragma unroll
            for (int mt = 0; mt < 4; mt++)
#pragma unroll
                for (int nt = 0; nt < 4; nt++) {
                    uint32_t b0 = bf[nt >> 1][(nt & 1) * 2];
                    uint32_t b1 = bf[nt >> 1][(nt & 1) * 2 + 1];
                    asm volatile(
                        "mma.sync.aligned.m16n8k8.row.col.f32.tf32.tf32.f32 "
                        "{%0,%1,%2,%3}, {%4,%5,%6,%7}, {%8,%9}, {%0,%1,%2,%3};"
                        : "+f"(c[mt][nt][0]), "+f"(c[mt][nt][1]),
                          "+f"(c[mt][nt][2]), "+f"(c[mt][nt][3])
                        : "r"(af[mt][0]), "r"(af[mt][1]),
                          "r"(af[mt][2]), "r"(af[mt][3]),
                          "r"(b0), "r"(b1));
                }
        }
        __syncthreads();
    }

    // ---- epilogue (fragment layout: e0:(qr,2qc) e1:(qr,2qc+1) e2:+8row e3) ----
    double local = 0.0;
#pragma unroll
    for (int mt = 0; mt < 4; mt++) {
#pragma unroll
        for (int nt = 0; nt < 4; nt++) {
#pragma unroll
            for (int e = 0; e < 4; e++) {
                int r  = rowBase + mBase + mt * 16 + qr + ((e >> 1) << 3);
                int nn = colBase + nBase + nt * 8 + (qc << 1) + (e & 1);
                size_t off = (size_t)r * N + nn;
                float z = c[mt][nt][e];
                if (bias_vec) z += bias_vec[nn];
                if (bias_arr) z += bias_arr[off];

                if (red_mode == 1) {  // softplus
                    local += (double)(fmaxf(z, 0.f) + log1pf(expf(-fabsf(z))));
                }

                if (mode == 0) {
                    if (outC) outC[off] = z;
                } else if (mode == 1) {
                    outC[off] = tanhf(z);
                } else {  // bernoulli sample
                    float p = 1.f / (1.f + expf(-z));
                    float u = jx_uniform(rk0, rk1, (uint32_t)off, half);
                    outC[off] = (u < p) ? 1.f : 0.f;
                    if (out2) out2[off] = p;
                    if (red_mode == 2) {
                        float v = vmon[off];
                        local += (double)(v * logf(p + 1e-10f)
                                          + (1.f - v) * logf(1.f - p + 1e-10f));
                    }
                }
            }
        }
    }

    if (red_mode) {
        __shared__ double rs[256];
        rs[tid] = local;
        __syncthreads();
        for (int s = 128; s > 0; s >>= 1) {
            if (tid < s) rs[tid] += rs[tid + s];
            __syncthreads();
        }
        if (tid == 0) atomicAdd(&red[slot], rs[0]);
    }
}

// ---------------------------------------------------------------------------
// dot-product reductions for the free-energy bias terms
// ---------------------------------------------------------------------------
__global__ void __launch_bounds__(256)
k_dots(const float* __restrict__ v,   const float* __restrict__ bvt,
       const float* __restrict__ vs,  const float* __restrict__ h1,
       const float* __restrict__ h1s, const float* __restrict__ bh1t,
       double* __restrict__ red)
{
    size_t i0  = (size_t)blockIdx.x * blockDim.x + threadIdx.x;
    size_t str = (size_t)gridDim.x * blockDim.x;
    size_t nv  = (size_t)SEQ_ * NV_;
    size_t nh  = (size_t)SEQ_ * NH_;
    double d5 = 0, d6 = 0, d7 = 0;
    for (size_t i = i0; i < nv; i += str) {
        float b = bvt[i];
        d5 += (double)(v[i]  * b);
        d6 += (double)(vs[i] * b);
    }
    for (size_t i = i0; i < nh; i += str)
        d7 += (double)((h1[i] - h1s[i]) * bh1t[i]);

    __shared__ double s5[256], s6[256], s7[256];
    int t = threadIdx.x;
    s5[t] = d5; s6[t] = d6; s7[t] = d7;
    __syncthreads();
    for (int s = 128; s > 0; s >>= 1) {
        if (t < s) { s5[t] += s5[t+s]; s6[t] += s6[t+s]; s7[t] += s7[t+s]; }
        __syncthreads();
    }
    if (t == 0) {
        atomicAdd(&red[5], s5[0]);
        atomicAdd(&red[6], s6[0]);
        atomicAdd(&red[7], s7[0]);
    }
}

__global__ void k_final(const double* __restrict__ red, float* __restrict__ out)
{
    double cost1 = (-red[5] - red[0] + red[6] + red[1]) / (double)SEQ_;
    double cost2 = (-red[7] - red[2] + red[3]) / (double)SEQ_;
    out[0] = (float)(cost1 + cost2);
    out[1] = (float)(red[4] / (double)SEQ_);
}

// ---------------------------------------------------------------------------
// host
// ---------------------------------------------------------------------------
static inline void launch_gemm(const float* A, int shiftA, const float* B, int transb,
                               int K, int N,
                               const float* bvec, const float* barr,
                               float* outC, float* out2, int mode,
                               int red_mode, int slot, const float* vmon,
                               uint32_t kk0, uint32_t kk1, double* acc)
{
    dim3 grid(N / BN, SEQ_ / BM), blk(256);
    uint32_t half = (uint32_t)(((size_t)SEQ_ * (size_t)N) / 2);
    if (transb) {
        cudaFuncSetAttribute(gemm_ep<true>,
                             cudaFuncAttributeMaxDynamicSharedMemorySize, GEMM_SMEM);
        gemm_ep<true ><<<grid, blk, GEMM_SMEM>>>(A, shiftA, B, K, N, bvec, barr, outC, out2,
                                      mode, red_mode, slot, vmon, kk0, kk1, half, acc);
    } else {
        cudaFuncSetAttribute(gemm_ep<false>,
                             cudaFuncAttributeMaxDynamicSharedMemorySize, GEMM_SMEM);
        gemm_ep<false><<<grid, blk, GEMM_SMEM>>>(A, shiftA, B, K, N, bvec, barr, outC, out2,
                                      mode, red_mode, slot, vmon, kk0, kk1, half, acc);
    }
}

extern "C" void kernel_launch(void* const* d_in, const int* in_sizes, int n_in,
                              void* d_out, int out_size)
{
    const float* v_seq = (const float*)d_in[0];
    const float* W1    = (const float*)d_in[1];
    const float* bv    = (const float*)d_in[2];
    const float* bh1   = (const float*)d_in[3];
    const float* W2    = (const float*)d_in[4];
    const float* bh2   = (const float*)d_in[5];
    const float* Wyv   = (const float*)d_in[6];
    const float* Wyh1  = (const float*)d_in[7];
    const float* Wyh2  = (const float*)d_in[8];
    const float* Wvu   = (const float*)d_in[9];
    const float* Wuu   = (const float*)d_in[10];
    const float* bu    = (const float*)d_in[11];
    float* out = (float*)d_out;

    float *X, *Ua, *Ub, *bvt, *bh1t, *bh2t, *h, *h1, *h2, *h1s, *vs;
    double* acc;
    cudaGetSymbolAddress((void**)&X,    g_X);
    cudaGetSymbolAddress((void**)&Ua,   g_Ua);
    cudaGetSymbolAddress((void**)&Ub,   g_Ub);
    cudaGetSymbolAddress((void**)&bvt,  g_bvt);
    cudaGetSymbolAddress((void**)&bh1t, g_bh1t);
    cudaGetSymbolAddress((void**)&bh2t, g_bh2t);
    cudaGetSymbolAddress((void**)&h,    g_h);
    cudaGetSymbolAddress((void**)&h1,   g_h1);
    cudaGetSymbolAddress((void**)&h2,   g_h2);
    cudaGetSymbolAddress((void**)&h1s,  g_h1s);
    cudaGetSymbolAddress((void**)&vs,   g_vs);
    cudaGetSymbolAddress((void**)&acc,  g_acc);

    // ---- JAX key schedule: key(42) -> 10x split(key,3) ----
    uint32_t kk0 = 0u, kk1 = 42u;
    uint32_t K1[10][2], K2[10][2];
    for (int i = 0; i < 10; i++) {
#if JAX_PARTITIONABLE
        uint32_t n0, n1, a0, a1, b0, b1;
        tf2x32(kk0, kk1, 0u, 0u, &n0, &n1);
        tf2x32(kk0, kk1, 0u, 1u, &a0, &a1);
        tf2x32(kk0, kk1, 0u, 2u, &b0, &b1);
        K1[i][0] = a0; K1[i][1] = a1;
        K2[i][0] = b0; K2[i][1] = b1;
        kk0 = n0; kk1 = n1;
#else
        uint32_t o00, o01, o10, o11, o20, o21;
        tf2x32(kk0, kk1, 0u, 3u, &o00, &o01);
        tf2x32(kk0, kk1, 1u, 4u, &o10, &o11);
        tf2x32(kk0, kk1, 2u, 5u, &o20, &o21);
        K1[i][0] = o20; K1[i][1] = o01;
        K2[i][0] = o11; K2[i][1] = o21;
        kk0 = o00; kk1 = o10;
#endif
    }

    k_init<<<1024, 256>>>();

    // X = v_seq @ Wvu + bu
    launch_gemm(v_seq, 0, Wvu, 0, NV_, NR_, bu, nullptr, X, nullptr, 0, 0, 0, nullptr, 0, 0, acc);

    // Jacobi sweeps: U <- tanh(X + shift(U) @ Wuu)
    for (int s = 0; s < NSWEEP; s++) {
        float* in    = (s % 2 == 0) ? Ua : Ub;
        float* out_u = (s % 2 == 0) ? Ub : Ua;
        launch_gemm(in, 1, Wuu, 0, NR_, NR_, nullptr, X, out_u, nullptr, 1, 0, 0, nullptr, 0, 0, acc);
    }
    // final U in Ua (NSWEEP even)

    // time-varying biases from shifted RNN output
    launch_gemm(Ua, 1, Wyv,  1, NR_, NV_, bv,  nullptr, bvt,  nullptr, 0, 0, 0, nullptr, 0, 0, acc);
    launch_gemm(Ua, 1, Wyh1, 1, NR_, NH_, bh1, nullptr, bh1t, nullptr, 0, 0, 0, nullptr, 0, 0, acc);
    launch_gemm(Ua, 1, Wyh2, 1, NR_, NH_, bh2, nullptr, bh2t, nullptr, 0, 0, 0, nullptr, 0, 0, acc);

    // ---- RBM1 CD-5 (splits 0..4). Iter 0 also yields h1 and FE1(v_seq) sp-sum.
    launch_gemm(v_seq, 0, W1, 0, NV_, NH_, nullptr, bh1t, h, h1, 2, 1, 0, nullptr,
                K1[0][0], K1[0][1], acc);
    launch_gemm(h, 0, W1, 1, NH_, NV_, nullptr, bvt, vs, nullptr, 2, 0, 0, nullptr,
                K2[0][0], K2[0][1], acc);
    for (int i = 1; i < CDK_ - 1; i++) {
        launch_gemm(vs, 0, W1, 0, NV_, NH_, nullptr, bh1t, h, nullptr, 2, 0, 0, nullptr,
                    K1[i][0], K1[i][1], acc);
        launch_gemm(h, 0, W1, 1, NH_, NV_, nullptr, bvt, vs, nullptr, 2, 0, 0, nullptr,
                    K2[i][0], K2[i][1], acc);
    }
    // last iter: the v-GEMM also accumulates the monitor with mean_v
    launch_gemm(vs, 0, W1, 0, NV_, NH_, nullptr, bh1t, h, nullptr, 2, 0, 0, nullptr,
                K1[CDK_-1][0], K1[CDK_-1][1], acc);
    launch_gemm(h, 0, W1, 1, NH_, NV_, nullptr, bvt, vs, nullptr, 2, 2, 4, v_seq,
                K2[CDK_-1][0], K2[CDK_-1][1], acc);

    // FE1(v_sample): softplus(vs@W1 + bh1t)
    launch_gemm(vs, 0, W1, 0, NV_, NH_, nullptr, bh1t, nullptr, nullptr, 0, 1, 1, nullptr,
                0, 0, acc);

    // ---- RBM2 CD-5 (splits 5..9). Iter 0 GEMM shares z with FE2(h1) sp-sum.
    launch_gemm(h1, 0, W2, 0, NH_, NH_, nullptr, bh2t, h2, nullptr, 2, 1, 2, nullptr,
                K1[5][0], K1[5][1], acc);
    launch_gemm(h2, 0, W2, 1, NH_, NH_, nullptr, bh1t, h1s, nullptr, 2, 0, 0, nullptr,
                K2[5][0], K2[5][1], acc);
    for (int i = 6; i < 10; i++) {
        launch_gemm(h1s, 0, W2, 0, NH_, NH_, nullptr, bh2t, h2, nullptr, 2, 0, 0, nullptr,
                    K1[i][0], K1[i][1], acc);
        launch_gemm(h2, 0, W2, 1, NH_, NH_, nullptr, bh1t, h1s, nullptr, 2, 0, 0, nullptr,
                    K2[i][0], K2[i][1], acc);
    }

    // FE2(h1_sample): softplus(h1s@W2 + bh2t)
    launch_gemm(h1s, 0, W2, 0, NH_, NH_, nullptr, bh2t, nullptr, nullptr, 0, 1, 3, nullptr,
                0, 0, acc);

    // bias dot terms + finalize
    k_dots<<<2048, 256>>>(v_seq, bvt, vs, h1, h1s, bh1t, acc);
    k_final<<<1, 1>>>(acc, out);
}

// round 12
// speedup vs baseline: 2.3542x; 1.1859x over previous
#include <cuda_runtime.h>
#include <stdint.h>
#include <math.h>

#define SEQ_   32768
#define NV_    256
#define NH_    512
#define NR_    256
#define CDK_   5
#define NSWEEP 10

// JAX >= 0.5 default: jax_threefry_partitionable = True
#define JAX_PARTITIONABLE 1

// ---------------------------------------------------------------------------
// Scratch (device globals; allocation-free per harness rules)
// ---------------------------------------------------------------------------
__device__ float g_X   [(size_t)SEQ_ * NR_];
__device__ float g_Ua  [(size_t)SEQ_ * NR_];
__device__ float g_Ub  [(size_t)SEQ_ * NR_];
__device__ float g_bvt [(size_t)SEQ_ * NV_];
__device__ float g_bh1t[(size_t)SEQ_ * NH_];
__device__ float g_bh2t[(size_t)SEQ_ * NH_];
__device__ float g_h   [(size_t)SEQ_ * NH_];
__device__ float g_h1  [(size_t)SEQ_ * NH_];
__device__ float g_h2  [(size_t)SEQ_ * NH_];
__device__ float g_h1s [(size_t)SEQ_ * NH_];
__device__ float g_vs  [(size_t)SEQ_ * NV_];
// tf32-rounded weight copies (all in [N,K] layout for the GEMM's B operand)
__device__ float g_W1t [(size_t)NH_ * NV_];   // W1^T  [NH,NV]
__device__ float g_W1r [(size_t)NV_ * NH_];   // W1    [NV,NH]
__device__ float g_W2t [(size_t)NH_ * NH_];   // W2^T
__device__ float g_W2r [(size_t)NH_ * NH_];   // W2
__device__ float g_Wuut[(size_t)NR_ * NR_];   // Wuu^T
__device__ float g_Wvut[(size_t)NR_ * NV_];   // Wvu^T
__device__ float g_Wyvr [(size_t)NV_ * NR_];
__device__ float g_Wyh1r[(size_t)NH_ * NR_];
__device__ float g_Wyh2r[(size_t)NH_ * NR_];
// 0: sum sp(v_seq)   1: sum sp(v_sample)  2: sum sp(h1)  3: sum sp(h1_sample)
// 4: monitor sum     5: sum v_seq.bvt     6: sum vs.bvt  7: sum (h1-h1s).bh1t
__device__ double g_acc[8];

// ---------------------------------------------------------------------------
// Threefry-2x32 (20 rounds) — exactly JAX's cipher
// ---------------------------------------------------------------------------
__host__ __device__ __forceinline__
void tf2x32(uint32_t k0, uint32_t k1, uint32_t x0, uint32_t x1,
            uint32_t* o0, uint32_t* o1)
{
    uint32_t ks2 = k0 ^ k1 ^ 0x1BD11BDAu;
    x0 += k0; x1 += k1;
#define TF_RND(R) { x0 += x1; x1 = (x1 << (R)) | (x1 >> (32 - (R))); x1 ^= x0; }
    TF_RND(13) TF_RND(15) TF_RND(26) TF_RND(6)
    x0 += k1;  x1 += ks2 + 1u;
    TF_RND(17) TF_RND(29) TF_RND(16) TF_RND(24)
    x0 += ks2; x1 += k0 + 2u;
    TF_RND(13) TF_RND(15) TF_RND(26) TF_RND(6)
    x0 += k0;  x1 += k1 + 3u;
    TF_RND(17) TF_RND(29) TF_RND(16) TF_RND(24)
    x0 += k1;  x1 += ks2 + 4u;
    TF_RND(13) TF_RND(15) TF_RND(26) TF_RND(6)
    x0 += ks2; x1 += k0 + 5u;
#undef TF_RND
    *o0 = x0; *o1 = x1;
}

__device__ __forceinline__
float jx_uniform(uint32_t k0, uint32_t k1, uint32_t idx, uint32_t half)
{
    uint32_t bits;
#if JAX_PARTITIONABLE
    uint32_t o0, o1;
    tf2x32(k0, k1, 0u, idx, &o0, &o1);
    bits = o0 ^ o1;
#else
    uint32_t o0, o1;
    if (idx < half) { tf2x32(k0, k1, idx, idx + half, &o0, &o1); bits = o0; }
    else            { tf2x32(k0, k1, idx - half, idx, &o0, &o1); bits = o1; }
#endif
    return __uint_as_float((bits >> 9) | 0x3f800000u) - 1.0f;
}

__device__ __forceinline__ float rna_tf32(float x)
{
    uint32_t u;
    asm("cvt.rna.tf32.f32 %0, %1;" : "=r"(u) : "f"(x));
    return __uint_as_float(u);
}

__device__ __forceinline__ uint32_t smem_u32(const void* p)
{
    uint32_t a;
    asm("{ .reg .u64 t; cvta.to.shared.u64 t, %1; cvt.u32.u64 %0, t; }"
        : "=r"(a) : "l"(p));
    return a;
}

__device__ __forceinline__ void cp16(uint32_t dst, const void* src, bool pred)
{
    int sz = pred ? 16 : 0;
    asm volatile("cp.async.cg.shared.global [%0], [%1], 16, %2;"
                 :: "r"(dst), "l"(src), "r"(sz));
}
template<int NWAIT>
__device__ __forceinline__ void cp_wait()
{
    asm volatile("cp.async.wait_group %0;" :: "n"(NWAIT) : "memory");
}
__device__ __forceinline__ void cp_commit()
{
    asm volatile("cp.async.commit_group;" ::: "memory");
}
__device__ __forceinline__ void ldsm_x4(uint32_t& r0, uint32_t& r1,
                                        uint32_t& r2, uint32_t& r3, uint32_t addr)
{
    asm volatile("ldmatrix.sync.aligned.m8n8.x4.shared.b16 {%0,%1,%2,%3}, [%4];"
                 : "=r"(r0), "=r"(r1), "=r"(r2), "=r"(r3) : "r"(addr));
}

// ---------------------------------------------------------------------------
// prep kernels
// ---------------------------------------------------------------------------
__global__ void k_init()
{
    int i = blockIdx.x * blockDim.x + threadIdx.x;
    if (i < 8) g_acc[i] = 0.0;
}

// out[i] = rna(in[i])
__global__ void k_round(const float* __restrict__ in, float* __restrict__ out, int n)
{
    int i = blockIdx.x * blockDim.x + threadIdx.x;
    if (i < n) out[i] = rna_tf32(in[i]);
}

// out[C,R] = rna(in[R,C]^T)
__global__ void k_tr(const float* __restrict__ in, float* __restrict__ out, int R, int C)
{
    __shared__ float t[32][33];
    int bx = blockIdx.x * 32, by = blockIdx.y * 32;
#pragma unroll
    for (int dy = 0; dy < 32; dy += 8)
        t[threadIdx.y + dy][threadIdx.x] = in[(size_t)(by + threadIdx.y + dy) * C + bx + threadIdx.x];
    __syncthreads();
#pragma unroll
    for (int dy = 0; dy < 32; dy += 8)
        out[(size_t)(bx + threadIdx.y + dy) * R + by + threadIdx.x] =
            rna_tf32(t[threadIdx.x][threadIdx.y + dy]);
}

// Ub = rna(tanh(X))   (first Jacobi application with U=0)
__global__ void k_tanhx()
{
    size_t i   = (size_t)blockIdx.x * blockDim.x + threadIdx.x;
    size_t tot = (size_t)SEQ_ * NR_;
    size_t str = (size_t)gridDim.x * blockDim.x;
    for (size_t j = i; j < tot; j += str) g_Ub[j] = rna_tf32(tanhf(g_X[j]));
}

// ---------------------------------------------------------------------------
// Fused tf32 tensor-core GEMM, ldmatrix + 3-stage cp.async pipeline.
//   C[S,N] = A[S,K] @ B^T, B given as [N,K] row-major (pre-transposed weights).
//   Block 128x128x32, 8 warps, warp tile 64x32 (mma.m16n8k8.tf32).
//   Smem: row-major [r][k], 16B-chunk swizzle ch^(r&7). 3 stages, 96KB.
//   shiftA: row t of A reads source row t-1 (row 0 -> zeros, cp.async zfill)
//   mode  : 0=linear  1=tanh(rounded)  2=bernoulli sample (out2 gets rounded p)
//   red   : 0=none  1=sum softplus(z)  2=sum monitor(vmon, p)  -> red[slot]
// ---------------------------------------------------------------------------
#define BM 128
#define BN 128
#define BK 32
#define STAGE_BYTES (BM * BK * 4)            // 16384
#define GEMM_SMEM   (6 * STAGE_BYTES)        // 98304: 3x A + 3x B

__global__ void __launch_bounds__(256, 2)
gemm_ep(const float* __restrict__ A, int shiftA,
        const float* __restrict__ Bm, int K, int N,
        const float* __restrict__ bias_vec,
        const float* __restrict__ bias_arr,
        float* __restrict__ outC, float* __restrict__ out2,
        int mode, int red_mode, int slot,
        const float* __restrict__ vmon,
        uint32_t rk0, uint32_t rk1, uint32_t half,
        double* __restrict__ red)
{
    extern __shared__ float dsm[];
    const uint32_t sA0 = smem_u32(dsm);
    const uint32_t sB0 = sA0 + 3u * STAGE_BYTES;

    const int tid  = threadIdx.x;
    const int lane = tid & 31;
    const int wid  = tid >> 5;
    const int warpM = wid >> 2;           // 0..1
    const int warpN = wid & 3;            // 0..3
    const int qr = lane >> 2;
    const int qc = lane & 3;
    const int rowBase = blockIdx.y * BM;
    const int colBase = blockIdx.x * BN;
    const int mBase = warpM * 64;
    const int nBase = warpN * 32;

    // ---- hoisted loader state: ch = tid&7 (16B chunk), rr = tid>>3 (row/8grp)
    const int ch = tid & 7;
    const int rr = tid >> 3;              // 0..31
    const float* aSrc[4];
    const float* bSrc[4];
    uint32_t aDst[4], bDst[4];
    bool aPred[4];
#pragma unroll
    for (int p = 0; p < 4; p++) {
        int r = p * 32 + rr;
        int srow = rowBase + r - shiftA;
        aPred[p] = (srow >= 0);
        aSrc[p] = A + (size_t)(srow < 0 ? 0 : srow) * K + ch * 4;
        aDst[p] = sA0 + (uint32_t)r * (BK * 4) + ((uint32_t)(ch ^ (rr & 7)) << 4);
        bSrc[p] = Bm + (size_t)(colBase + r) * K + ch * 4;
        bDst[p] = sB0 + (uint32_t)r * (BK * 4) + ((uint32_t)(ch ^ (rr & 7)) << 4);
    }

    // ---- hoisted ldmatrix fragment addresses (stage-0, kk=0) ----
    uint32_t pA[4], pB[2];
    {
        const int hi = lane >> 4;
#pragma unroll
        for (int mt = 0; mt < 4; mt++) {
            int row = mBase + mt * 16 + (lane & 15);
            pA[mt] = (sA0 + (uint32_t)row * (BK * 4))
                     ^ ((uint32_t)(row & 7) << 4) ^ ((uint32_t)hi << 4);
        }
        const int bsel = (lane >> 3) & 1;
#pragma unroll
        for (int pr = 0; pr < 2; pr++) {
            int n = nBase + pr * 16 + (lane & 7) + (hi << 3);
            pB[pr] = (sB0 + (uint32_t)n * (BK * 4))
                     ^ ((uint32_t)(n & 7) << 4) ^ ((uint32_t)bsel << 4);
        }
    }

    float c[4][4][4];
#pragma unroll
    for (int mt = 0; mt < 4; mt++)
#pragma unroll
        for (int nt = 0; nt < 4; nt++)
#pragma unroll
            for (int e = 0; e < 4; e++) c[mt][nt][e] = 0.0f;

    auto load_tile = [&](int st, int kc) {
        uint32_t so = (uint32_t)st * STAGE_BYTES;
#pragma unroll
        for (int p = 0; p < 4; p++) cp16(aDst[p] + so, aSrc[p] + kc, aPred[p]);
#pragma unroll
        for (int p = 0; p < 4; p++) cp16(bDst[p] + so, bSrc[p] + kc, true);
    };

    const int T = K / BK;
    load_tile(0, 0);          cp_commit();
    if (T > 1) { load_tile(1, BK); cp_commit(); }

    for (int t = 0; t < T; t++) {
        if (t + 2 < T) {
            load_tile((t + 2) % 3, (t + 2) * BK);
            cp_commit();
            cp_wait<2>();
        } else if (t + 1 < T) {
            cp_wait<1>();
        } else {
            cp_wait<0>();
        }
        __syncthreads();

        const uint32_t so = (uint32_t)(t % 3) * STAGE_BYTES;
#pragma unroll
        for (int kk = 0; kk < 4; kk++) {
            uint32_t af[4][4];
#pragma unroll
            for (int mt = 0; mt < 4; mt++)
                ldsm_x4(af[mt][0], af[mt][1], af[mt][2], af[mt][3],
                        (pA[mt] + so) ^ ((uint32_t)kk << 5));
            uint32_t bf[2][4];
#pragma unroll
            for (int pr = 0; pr < 2; pr++)
                ldsm_x4(bf[pr][0], bf[pr][1], bf[pr][2], bf[pr][3],
                        (pB[pr] + so) ^ ((uint32_t)kk << 5));
#pragma unroll
            for (int mt = 0; mt < 4; mt++)
#pragma unroll
                for (int nt = 0; nt < 4; nt++) {
                    uint32_t b0 = bf[nt >> 1][(nt & 1) * 2];
                    uint32_t b1 = bf[nt >> 1][(nt & 1) * 2 + 1];
                    asm volatile(
                        "mma.sync.aligned.m16n8k8.row.col.f32.tf32.tf32.f32 "
                        "{%0,%1,%2,%3}, {%4,%5,%6,%7}, {%8,%9}, {%0,%1,%2,%3};"
                        : "+f"(c[mt][nt][0]), "+f"(c[mt][nt][1]),
                          "+f"(c[mt][nt][2]), "+f"(c[mt][nt][3])
                        : "r"(af[mt][0]), "r"(af[mt][1]),
                          "r"(af[mt][2]), "r"(af[mt][3]),
                          "r"(b0), "r"(b1));
                }
        }
        __syncthreads();
    }

    // ---- epilogue (fragment layout: e0:(qr,2qc) e1:(qr,2qc+1) e2:+8row e3) ----
    double local = 0.0;
#pragma unroll
    for (int mt = 0; mt < 4; mt++) {
#pragma unroll
        for (int nt = 0; nt < 4; nt++) {
#pragma unroll
            for (int e = 0; e < 4; e++) {
                int r  = rowBase + mBase + mt * 16 + qr + ((e >> 1) << 3);
                int nn = colBase + nBase + nt * 8 + (qc << 1) + (e & 1);
                size_t off = (size_t)r * N + nn;
                float z = c[mt][nt][e];
                if (bias_vec) z += bias_vec[nn];
                if (bias_arr) z += bias_arr[off];

                if (red_mode == 1) {  // softplus
                    local += (double)(fmaxf(z, 0.f) + log1pf(expf(-fabsf(z))));
                }

                if (mode == 0) {
                    if (outC) outC[off] = z;
                } else if (mode == 1) {
                    outC[off] = rna_tf32(tanhf(z));   // MMA operand downstream
                } else {  // bernoulli sample
                    float p = 1.f / (1.f + expf(-z));
                    float u = jx_uniform(rk0, rk1, (uint32_t)off, half);
                    outC[off] = (u < p) ? 1.f : 0.f;
                    if (out2) out2[off] = rna_tf32(p);  // MMA operand downstream
                    if (red_mode == 2) {
                        float v = vmon[off];
                        local += (double)(v * logf(p + 1e-10f)
                                          + (1.f - v) * logf(1.f - p + 1e-10f));
                    }
                }
            }
        }
    }

    if (red_mode) {
        __shared__ double rs[256];
        rs[tid] = local;
        __syncthreads();
        for (int s = 128; s > 0; s >>= 1) {
            if (tid < s) rs[tid] += rs[tid + s];
            __syncthreads();
        }
        if (tid == 0) atomicAdd(&red[slot], rs[0]);
    }
}

// ---------------------------------------------------------------------------
// dot-product reductions for the free-energy bias terms
// ---------------------------------------------------------------------------
__global__ void __launch_bounds__(256)
k_dots(const float* __restrict__ v,   const float* __restrict__ bvt,
       const float* __restrict__ vs,  const float* __restrict__ h1,
       const float* __restrict__ h1s, const float* __restrict__ bh1t,
       double* __restrict__ red)
{
    size_t i0  = (size_t)blockIdx.x * blockDim.x + threadIdx.x;
    size_t str = (size_t)gridDim.x * blockDim.x;
    size_t nv  = (size_t)SEQ_ * NV_;
    size_t nh  = (size_t)SEQ_ * NH_;
    double d5 = 0, d6 = 0, d7 = 0;
    for (size_t i = i0; i < nv; i += str) {
        float b = bvt[i];
        d5 += (double)(v[i]  * b);
        d6 += (double)(vs[i] * b);
    }
    for (size_t i = i0; i < nh; i += str)
        d7 += (double)((h1[i] - h1s[i]) * bh1t[i]);

    __shared__ double s5[256], s6[256], s7[256];
    int t = threadIdx.x;
    s5[t] = d5; s6[t] = d6; s7[t] = d7;
    __syncthreads();
    for (int s = 128; s > 0; s >>= 1) {
        if (t < s) { s5[t] += s5[t+s]; s6[t] += s6[t+s]; s7[t] += s7[t+s]; }
        __syncthreads();
    }
    if (t == 0) {
        atomicAdd(&red[5], s5[0]);
        atomicAdd(&red[6], s6[0]);
        atomicAdd(&red[7], s7[0]);
    }
}

__global__ void k_final(const double* __restrict__ red, float* __restrict__ out)
{
    double cost1 = (-red[5] - red[0] + red[6] + red[1]) / (double)SEQ_;
    double cost2 = (-red[7] - red[2] + red[3]) / (double)SEQ_;
    out[0] = (float)(cost1 + cost2);
    out[1] = (float)(red[4] / (double)SEQ_);
}

// ---------------------------------------------------------------------------
// host
// ---------------------------------------------------------------------------
static inline void launch_gemm(const float* A, int shiftA, const float* B,
                               int K, int N,
                               const float* bvec, const float* barr,
                               float* outC, float* out2, int mode,
                               int red_mode, int slot, const float* vmon,
                               uint32_t kk0, uint32_t kk1, double* acc)
{
    dim3 grid(N / BN, SEQ_ / BM), blk(256);
    uint32_t half = (uint32_t)(((size_t)SEQ_ * (size_t)N) / 2);
    cudaFuncSetAttribute(gemm_ep, cudaFuncAttributeMaxDynamicSharedMemorySize, GEMM_SMEM);
    gemm_ep<<<grid, blk, GEMM_SMEM>>>(A, shiftA, B, K, N, bvec, barr, outC, out2,
                                      mode, red_mode, slot, vmon, kk0, kk1, half, acc);
}

extern "C" void kernel_launch(void* const* d_in, const int* in_sizes, int n_in,
                              void* d_out, int out_size)
{
    const float* v_seq = (const float*)d_in[0];
    const float* W1    = (const float*)d_in[1];
    const float* bv    = (const float*)d_in[2];
    const float* bh1   = (const float*)d_in[3];
    const float* W2    = (const float*)d_in[4];
    const float* bh2   = (const float*)d_in[5];
    const float* Wyv   = (const float*)d_in[6];
    const float* Wyh1  = (const float*)d_in[7];
    const float* Wyh2  = (const float*)d_in[8];
    const float* Wvu   = (const float*)d_in[9];
    const float* Wuu   = (const float*)d_in[10];
    const float* bu    = (const float*)d_in[11];
    float* out = (float*)d_out;

    float *X, *Ua, *Ub, *bvt, *bh1t, *bh2t, *h, *h1, *h2, *h1s, *vs;
    float *W1t, *W1r, *W2t, *W2r, *Wuut, *Wvut, *Wyvr, *Wyh1r, *Wyh2r;
    double* acc;
    cudaGetSymbolAddress((void**)&X,    g_X);
    cudaGetSymbolAddress((void**)&Ua,   g_Ua);
    cudaGetSymbolAddress((void**)&Ub,   g_Ub);
    cudaGetSymbolAddress((void**)&bvt,  g_bvt);
    cudaGetSymbolAddress((void**)&bh1t, g_bh1t);
    cudaGetSymbolAddress((void**)&bh2t, g_bh2t);
    cudaGetSymbolAddress((void**)&h,    g_h);
    cudaGetSymbolAddress((void**)&h1,   g_h1);
    cudaGetSymbolAddress((void**)&h2,   g_h2);
    cudaGetSymbolAddress((void**)&h1s,  g_h1s);
    cudaGetSymbolAddress((void**)&vs,   g_vs);
    cudaGetSymbolAddress((void**)&W1t,  g_W1t);
    cudaGetSymbolAddress((void**)&W1r,  g_W1r);
    cudaGetSymbolAddress((void**)&W2t,  g_W2t);
    cudaGetSymbolAddress((void**)&W2r,  g_W2r);
    cudaGetSymbolAddress((void**)&Wuut, g_Wuut);
    cudaGetSymbolAddress((void**)&Wvut, g_Wvut);
    cudaGetSymbolAddress((void**)&Wyvr, g_Wyvr);
    cudaGetSymbolAddress((void**)&Wyh1r,g_Wyh1r);
    cudaGetSymbolAddress((void**)&Wyh2r,g_Wyh2r);
    cudaGetSymbolAddress((void**)&acc,  g_acc);

    // ---- JAX key schedule: key(42) -> 10x split(key,3) ----
    uint32_t kk0 = 0u, kk1 = 42u;
    uint32_t K1[10][2], K2[10][2];
    for (int i = 0; i < 10; i++) {
#if JAX_PARTITIONABLE
        uint32_t n0, n1, a0, a1, b0, b1;
        tf2x32(kk0, kk1, 0u, 0u, &n0, &n1);
        tf2x32(kk0, kk1, 0u, 1u, &a0, &a1);
        tf2x32(kk0, kk1, 0u, 2u, &b0, &b1);
        K1[i][0] = a0; K1[i][1] = a1;
        K2[i][0] = b0; K2[i][1] = b1;
        kk0 = n0; kk1 = n1;
#else
        uint32_t o00, o01, o10, o11, o20, o21;
        tf2x32(kk0, kk1, 0u, 3u, &o00, &o01);
        tf2x32(kk0, kk1, 1u, 4u, &o10, &o11);
        tf2x32(kk0, kk1, 2u, 5u, &o20, &o21);
        K1[i][0] = o20; K1[i][1] = o01;
        K2[i][0] = o11; K2[i][1] = o21;
        kk0 = o00; kk1 = o10;
#endif
    }

    // ---- prep: accumulators + tf32-rounded / transposed weights ----
    k_init<<<1, 32>>>();
    dim3 trb(32, 8);
    k_tr<<<dim3(NH_/32, NV_/32), trb>>>(W1,  W1t,  NV_, NH_);
    k_tr<<<dim3(NH_/32, NH_/32), trb>>>(W2,  W2t,  NH_, NH_);
    k_tr<<<dim3(NR_/32, NV_/32), trb>>>(Wvu, Wvut, NV_, NR_);
    k_tr<<<dim3(NR_/32, NR_/32), trb>>>(Wuu, Wuut, NR_, NR_);
    k_round<<<(NV_*NH_+255)/256, 256>>>(W1,   W1r,   NV_*NH_);
    k_round<<<(NH_*NH_+255)/256, 256>>>(W2,   W2r,   NH_*NH_);
    k_round<<<(NV_*NR_+255)/256, 256>>>(Wyv,  Wyvr,  NV_*NR_);
    k_round<<<(NH_*NR_+255)/256, 256>>>(Wyh1, Wyh1r, NH_*NR_);
    k_round<<<(NH_*NR_+255)/256, 256>>>(Wyh2, Wyh2r, NH_*NR_);

    // X = v_seq @ Wvu + bu
    launch_gemm(v_seq, 0, Wvut, NV_, NR_, bu, nullptr, X, nullptr, 0, 0, 0, nullptr, 0, 0, acc);

    // Jacobi: sweep 0 is tanh(X) (U=0); then NSWEEP-1 GEMM sweeps
    k_tanhx<<<1024, 256>>>();
    for (int s = 1; s < NSWEEP; s++) {
        float* in    = (s % 2 == 1) ? Ub : Ua;
        float* out_u = (s % 2 == 1) ? Ua : Ub;
        launch_gemm(in, 1, Wuut, NR_, NR_, nullptr, X, out_u, nullptr, 1, 0, 0, nullptr, 0, 0, acc);
    }
    // NSWEEP=10 -> final U in Ua

    // time-varying biases from shifted RNN output
    launch_gemm(Ua, 1, Wyvr,  NR_, NV_, bv,  nullptr, bvt,  nullptr, 0, 0, 0, nullptr, 0, 0, acc);
    launch_gemm(Ua, 1, Wyh1r, NR_, NH_, bh1, nullptr, bh1t, nullptr, 0, 0, 0, nullptr, 0, 0, acc);
    launch_gemm(Ua, 1, Wyh2r, NR_, NH_, bh2, nullptr, bh2t, nullptr, 0, 0, 0, nullptr, 0, 0, acc);

    // ---- RBM1 CD-5 (splits 0..4). Iter 0 also yields h1 and FE1(v_seq) sp-sum.
    launch_gemm(v_seq, 0, W1t, NV_, NH_, nullptr, bh1t, h, h1, 2, 1, 0, nullptr,
                K1[0][0], K1[0][1], acc);
    launch_gemm(h, 0, W1r, NH_, NV_, nullptr, bvt, vs, nullptr, 2, 0, 0, nullptr,
                K2[0][0], K2[0][1], acc);
    for (int i = 1; i < CDK_ - 1; i++) {
        launch_gemm(vs, 0, W1t, NV_, NH_, nullptr, bh1t, h, nullptr, 2, 0, 0, nullptr,
                    K1[i][0], K1[i][1], acc);
        launch_gemm(h, 0, W1r, NH_, NV_, nullptr, bvt, vs, nullptr, 2, 0, 0, nullptr,
                    K2[i][0], K2[i][1], acc);
    }
    // last iter: the v-GEMM also accumulates the monitor with mean_v
    launch_gemm(vs, 0, W1t, NV_, NH_, nullptr, bh1t, h, nullptr, 2, 0, 0, nullptr,
                K1[CDK_-1][0], K1[CDK_-1][1], acc);
    launch_gemm(h, 0, W1r, NH_, NV_, nullptr, bvt, vs, nullptr, 2, 2, 4, v_seq,
                K2[CDK_-1][0], K2[CDK_-1][1], acc);

    // FE1(v_sample): softplus(vs@W1 + bh1t)
    launch_gemm(vs, 0, W1t, NV_, NH_, nullptr, bh1t, nullptr, nullptr, 0, 1, 1, nullptr,
                0, 0, acc);

    // ---- RBM2 CD-5 (splits 5..9). Iter 0 GEMM shares z with FE2(h1) sp-sum.
    launch_gemm(h1, 0, W2t, NH_, NH_, nullptr, bh2t, h2, nullptr, 2, 1, 2, nullptr,
                K1[5][0], K1[5][1], acc);
    launch_gemm(h2, 0, W2r, NH_, NH_, nullptr, bh1t, h1s, nullptr, 2, 0, 0, nullptr,
                K2[5][0], K2[5][1], acc);
    for (int i = 6; i < 10; i++) {
        launch_gemm(h1s, 0, W2t, NH_, NH_, nullptr, bh2t, h2, nullptr, 2, 0, 0, nullptr,
                    K1[i][0], K1[i][1], acc);
        launch_gemm(h2, 0, W2r, NH_, NH_, nullptr, bh1t, h1s, nullptr, 2, 0, 0, nullptr,
                    K2[i][0], K2[i][1], acc);
    }

    // FE2(h1_sample): softplus(h1s@W2 + bh2t)
    launch_gemm(h1s, 0, W2t, NH_, NH_, nullptr, bh2t, nullptr, nullptr, 0, 1, 3, nullptr,
                0, 0, acc);

    // bias dot terms + finalize
    k_dots<<<2048, 256>>>(v_seq, bvt, vs, h1, h1s, bh1t, acc);
    k_final<<<1, 1>>>(acc, out);
}

// round 13
// speedup vs baseline: 2.4170x; 1.0267x over previous
#include <cuda_runtime.h>
#include <stdint.h>
#include <math.h>

#define SEQ_   32768
#define NV_    256
#define NH_    512
#define NR_    256
#define CDK_   5
#define NSWEEP 8

// JAX >= 0.5 default: jax_threefry_partitionable = True
#define JAX_PARTITIONABLE 1

// ---------------------------------------------------------------------------
// Scratch (device globals; allocation-free per harness rules)
// ---------------------------------------------------------------------------
__device__ float g_X   [(size_t)SEQ_ * NR_];
__device__ float g_Ua  [(size_t)SEQ_ * NR_];
__device__ float g_Ub  [(size_t)SEQ_ * NR_];
__device__ float g_bvt [(size_t)SEQ_ * NV_];
__device__ float g_bh1t[(size_t)SEQ_ * NH_];
__device__ float g_bh2t[(size_t)SEQ_ * NH_];
__device__ float g_h   [(size_t)SEQ_ * NH_];
__device__ float g_h1  [(size_t)SEQ_ * NH_];
__device__ float g_h2  [(size_t)SEQ_ * NH_];
__device__ float g_h1s [(size_t)SEQ_ * NH_];
__device__ float g_vs  [(size_t)SEQ_ * NV_];
// tf32-rounded weight copies (all in [N,K] layout for the GEMM's B operand)
__device__ float g_W1t [(size_t)NH_ * NV_];   // W1^T  [NH,NV]
__device__ float g_W1r [(size_t)NV_ * NH_];   // W1    [NV,NH]
__device__ float g_W2t [(size_t)NH_ * NH_];   // W2^T
__device__ float g_W2r [(size_t)NH_ * NH_];   // W2
__device__ float g_Wuut[(size_t)NR_ * NR_];   // Wuu^T
__device__ float g_Wvut[(size_t)NR_ * NV_];   // Wvu^T
__device__ float g_Wyvr [(size_t)NV_ * NR_];
__device__ float g_Wyh1r[(size_t)NH_ * NR_];
__device__ float g_Wyh2r[(size_t)NH_ * NR_];
// 0: sum sp(v_seq)   1: sum sp(v_sample)  2: sum sp(h1)  3: sum sp(h1_sample)
// 4: monitor sum     5: sum v_seq.bvt     6: sum vs.bvt  7: sum (h1-h1s).bh1t
__device__ double g_acc[8];

// ---------------------------------------------------------------------------
// Threefry-2x32 (20 rounds) — exactly JAX's cipher
// ---------------------------------------------------------------------------
__host__ __device__ __forceinline__
void tf2x32(uint32_t k0, uint32_t k1, uint32_t x0, uint32_t x1,
            uint32_t* o0, uint32_t* o1)
{
    uint32_t ks2 = k0 ^ k1 ^ 0x1BD11BDAu;
    x0 += k0; x1 += k1;
#define TF_RND(R) { x0 += x1; x1 = (x1 << (R)) | (x1 >> (32 - (R))); x1 ^= x0; }
    TF_RND(13) TF_RND(15) TF_RND(26) TF_RND(6)
    x0 += k1;  x1 += ks2 + 1u;
    TF_RND(17) TF_RND(29) TF_RND(16) TF_RND(24)
    x0 += ks2; x1 += k0 + 2u;
    TF_RND(13) TF_RND(15) TF_RND(26) TF_RND(6)
    x0 += k0;  x1 += k1 + 3u;
    TF_RND(17) TF_RND(29) TF_RND(16) TF_RND(24)
    x0 += k1;  x1 += ks2 + 4u;
    TF_RND(13) TF_RND(15) TF_RND(26) TF_RND(6)
    x0 += ks2; x1 += k0 + 5u;
#undef TF_RND
    *o0 = x0; *o1 = x1;
}

__device__ __forceinline__
float jx_uniform(uint32_t k0, uint32_t k1, uint32_t idx, uint32_t half)
{
    uint32_t bits;
#if JAX_PARTITIONABLE
    uint32_t o0, o1;
    tf2x32(k0, k1, 0u, idx, &o0, &o1);
    bits = o0 ^ o1;
#else
    uint32_t o0, o1;
    if (idx < half) { tf2x32(k0, k1, idx, idx + half, &o0, &o1); bits = o0; }
    else            { tf2x32(k0, k1, idx - half, idx, &o0, &o1); bits = o1; }
#endif
    return __uint_as_float((bits >> 9) | 0x3f800000u) - 1.0f;
}

__device__ __forceinline__ float rna_tf32(float x)
{
    uint32_t u;
    asm("cvt.rna.tf32.f32 %0, %1;" : "=r"(u) : "f"(x));
    return __uint_as_float(u);
}

__device__ __forceinline__ uint32_t smem_u32(const void* p)
{
    uint32_t a;
    asm("{ .reg .u64 t; cvta.to.shared.u64 t, %1; cvt.u32.u64 %0, t; }"
        : "=r"(a) : "l"(p));
    return a;
}

__device__ __forceinline__ void cp16(uint32_t dst, const void* src, bool pred)
{
    int sz = pred ? 16 : 0;
    asm volatile("cp.async.cg.shared.global [%0], [%1], 16, %2;"
                 :: "r"(dst), "l"(src), "r"(sz));
}
template<int NWAIT>
__device__ __forceinline__ void cp_wait()
{
    asm volatile("cp.async.wait_group %0;" :: "n"(NWAIT) : "memory");
}
__device__ __forceinline__ void cp_commit()
{
    asm volatile("cp.async.commit_group;" ::: "memory");
}
__device__ __forceinline__ void ldsm_x4(uint32_t& r0, uint32_t& r1,
                                        uint32_t& r2, uint32_t& r3, uint32_t addr)
{
    asm volatile("ldmatrix.sync.aligned.m8n8.x4.shared.b16 {%0,%1,%2,%3}, [%4];"
                 : "=r"(r0), "=r"(r1), "=r"(r2), "=r"(r3) : "r"(addr));
}

// ---------------------------------------------------------------------------
// prep kernels
// ---------------------------------------------------------------------------
__global__ void k_init()
{
    int i = blockIdx.x * blockDim.x + threadIdx.x;
    if (i < 8) g_acc[i] = 0.0;
}

__global__ void k_round(const float* __restrict__ in, float* __restrict__ out, int n)
{
    int i = blockIdx.x * blockDim.x + threadIdx.x;
    if (i < n) out[i] = rna_tf32(in[i]);
}

__global__ void k_tr(const float* __restrict__ in, float* __restrict__ out, int R, int C)
{
    __shared__ float t[32][33];
    int bx = blockIdx.x * 32, by = blockIdx.y * 32;
#pragma unroll
    for (int dy = 0; dy < 32; dy += 8)
        t[threadIdx.y + dy][threadIdx.x] = in[(size_t)(by + threadIdx.y + dy) * C + bx + threadIdx.x];
    __syncthreads();
#pragma unroll
    for (int dy = 0; dy < 32; dy += 8)
        out[(size_t)(bx + threadIdx.y + dy) * R + by + threadIdx.x] =
            rna_tf32(t[threadIdx.x][threadIdx.y + dy]);
}

// Ub = rna(tanh(X))   (first Jacobi application with U=0)
__global__ void k_tanhx()
{
    size_t i   = (size_t)blockIdx.x * blockDim.x + threadIdx.x;
    size_t tot = (size_t)SEQ_ * NR_;
    size_t str = (size_t)gridDim.x * blockDim.x;
    for (size_t j = i; j < tot; j += str) g_Ub[j] = rna_tf32(tanhf(g_X[j]));
}

// ---------------------------------------------------------------------------
// Fused tf32 tensor-core GEMM, ldmatrix + 3-stage cp.async pipeline,
// A-fragment double buffering, one barrier per k-tile.
//   C[S,N] = A[S,K] @ B^T, B given as [N,K] row-major (pre-transposed weights).
//   Block 128x128x32, 8 warps, warp tile 64x32 (mma.m16n8k8.tf32).
//   Smem: row-major [r][k], 16B-chunk swizzle ch^(r&7). 3 stages, 96KB.
//   shiftA: row t of A reads source row t-1 (row 0 -> zeros, cp.async zfill)
//   mode  : 0=linear  1=tanh(rounded)  2=bernoulli sample (out2 gets rounded p)
//   red   : 0=none  1=sum softplus(z)  2=sum monitor(vmon, p)  -> red[slot]
// ---------------------------------------------------------------------------
#define BM 128
#define BN 128
#define BK 32
#define STAGE_BYTES (BM * BK * 4)            // 16384
#define GEMM_SMEM   (6 * STAGE_BYTES)        // 98304: 3x A + 3x B

__global__ void __launch_bounds__(256, 2)
gemm_ep(const float* __restrict__ A, int shiftA,
        const float* __restrict__ Bm, int K, int N,
        const float* __restrict__ bias_vec,
        const float* __restrict__ bias_arr,
        float* __restrict__ outC, float* __restrict__ out2,
        int mode, int red_mode, int slot,
        const float* __restrict__ vmon,
        uint32_t rk0, uint32_t rk1, uint32_t half,
        double* __restrict__ red)
{
    extern __shared__ float dsm[];
    const uint32_t sA0 = smem_u32(dsm);
    const uint32_t sB0 = sA0 + 3u * STAGE_BYTES;

    const int tid  = threadIdx.x;
    const int lane = tid & 31;
    const int wid  = tid >> 5;
    const int warpM = wid >> 2;           // 0..1
    const int warpN = wid & 3;            // 0..3
    const int qr = lane >> 2;
    const int qc = lane & 3;
    const int rowBase = blockIdx.y * BM;
    const int colBase = blockIdx.x * BN;
    const int mBase = warpM * 64;
    const int nBase = warpN * 32;

    // ---- compact loader state: ch = tid&7 (16B chunk), rr = tid>>3 (row grp)
    const int ch = tid & 7;
    const int rr = tid >> 3;              // 0..31
    const size_t kStride = (size_t)32 * K;          // rows 32 apart in source
    const float* aBase = A + (size_t)(rowBase + rr - shiftA) * K + ch * 4;
    const float* bBase = Bm + (size_t)(colBase + rr) * K + ch * 4;
    const uint32_t dOff = (uint32_t)rr * (BK * 4) + ((uint32_t)(ch ^ (rr & 7)) << 4);
    const int aRow0 = rowBase + rr - shiftA;        // predicate: aRow0 + 32p >= 0

    // ---- hoisted ldmatrix fragment addresses (stage-0, kk=0) ----
    uint32_t pA[4], pB[2];
    {
        const int hi = lane >> 4;
#pragma unroll
        for (int mt = 0; mt < 4; mt++) {
            int row = mBase + mt * 16 + (lane & 15);
            pA[mt] = (sA0 + (uint32_t)row * (BK * 4))
                     ^ ((uint32_t)(row & 7) << 4) ^ ((uint32_t)hi << 4);
        }
        const int bsel = (lane >> 3) & 1;
#pragma unroll
        for (int pr = 0; pr < 2; pr++) {
            int n = nBase + pr * 16 + (lane & 7) + (hi << 3);
            pB[pr] = (sB0 + (uint32_t)n * (BK * 4))
                     ^ ((uint32_t)(n & 7) << 4) ^ ((uint32_t)bsel << 4);
        }
    }

    float c[4][4][4];
#pragma unroll
    for (int mt = 0; mt < 4; mt++)
#pragma unroll
        for (int nt = 0; nt < 4; nt++)
#pragma unroll
            for (int e = 0; e < 4; e++) c[mt][nt][e] = 0.0f;

    auto load_tile = [&](int st, int kc) {
        const uint32_t so = (uint32_t)st * STAGE_BYTES;
        const uint32_t aD = sA0 + so + dOff;
        const uint32_t bD = sB0 + so + dOff;
#pragma unroll
        for (int p = 0; p < 4; p++)
            cp16(aD + (uint32_t)p * 32 * (BK * 4), aBase + p * kStride + kc,
                 (aRow0 + 32 * p) >= 0);
#pragma unroll
        for (int p = 0; p < 4; p++)
            cp16(bD + (uint32_t)p * 32 * (BK * 4), bBase + p * kStride + kc, true);
    };

    const int T = K / BK;
    load_tile(0, 0);               cp_commit();
    if (T > 1) { load_tile(1, BK); cp_commit(); }

    for (int t = 0; t < T; t++) {
        if (t + 1 < T) cp_wait<1>(); else cp_wait<0>();
        __syncthreads();
        if (t + 2 < T) { load_tile((t + 2) % 3, (t + 2) * BK); cp_commit(); }

        const uint32_t so = (uint32_t)(t % 3) * STAGE_BYTES;

        // A-fragment double buffer: prefetch kk=0
        uint32_t af[2][4][4];
#pragma unroll
        for (int mt = 0; mt < 4; mt++)
            ldsm_x4(af[0][mt][0], af[0][mt][1], af[0][mt][2], af[0][mt][3],
                    pA[mt] + so);

#pragma unroll
        for (int kk = 0; kk < 4; kk++) {
            const int cur = kk & 1;
            if (kk < 3) {
#pragma unroll
                for (int mt = 0; mt < 4; mt++)
                    ldsm_x4(af[cur ^ 1][mt][0], af[cur ^ 1][mt][1],
                            af[cur ^ 1][mt][2], af[cur ^ 1][mt][3],
                            (pA[mt] + so) ^ ((uint32_t)(kk + 1) << 5));
            }
            uint32_t bf[2][4];
#pragma unroll
            for (int pr = 0; pr < 2; pr++)
                ldsm_x4(bf[pr][0], bf[pr][1], bf[pr][2], bf[pr][3],
                        (pB[pr] + so) ^ ((uint32_t)kk << 5));
#pragma unroll
            for (int mt = 0; mt < 4; mt++)
#pragma unroll
                for (int nt = 0; nt < 4; nt++) {
                    uint32_t b0 = bf[nt >> 1][(nt & 1) * 2];
                    uint32_t b1 = bf[nt >> 1][(nt & 1) * 2 + 1];
                    asm volatile(
                        "mma.sync.aligned.m16n8k8.row.col.f32.tf32.tf32.f32 "
                        "{%0,%1,%2,%3}, {%4,%5,%6,%7}, {%8,%9}, {%0,%1,%2,%3};"
                        : "+f"(c[mt][nt][0]), "+f"(c[mt][nt][1]),
                          "+f"(c[mt][nt][2]), "+f"(c[mt][nt][3])
                        : "r"(af[cur][mt][0]), "r"(af[cur][mt][1]),
                          "r"(af[cur][mt][2]), "r"(af[cur][mt][3]),
                          "r"(b0), "r"(b1));
                }
        }
    }

    // ---- epilogue (fragment layout: e0:(qr,2qc) e1:(qr,2qc+1) e2:+8row e3) ----
    double local = 0.0;
#pragma unroll
    for (int mt = 0; mt < 4; mt++) {
#pragma unroll
        for (int nt = 0; nt < 4; nt++) {
#pragma unroll
            for (int e = 0; e < 4; e++) {
                int r  = rowBase + mBase + mt * 16 + qr + ((e >> 1) << 3);
                int nn = colBase + nBase + nt * 8 + (qc << 1) + (e & 1);
                size_t off = (size_t)r * N + nn;
                float z = c[mt][nt][e];
                if (bias_vec) z += bias_vec[nn];
                if (bias_arr) z += bias_arr[off];

                if (red_mode == 1) {  // softplus
                    local += (double)(fmaxf(z, 0.f) + log1pf(expf(-fabsf(z))));
                }

                if (mode == 0) {
                    if (outC) outC[off] = z;
                } else if (mode == 1) {
                    outC[off] = rna_tf32(tanhf(z));   // MMA operand downstream
                } else {  // bernoulli sample
                    float p = 1.f / (1.f + expf(-z));
                    float u = jx_uniform(rk0, rk1, (uint32_t)off, half);
                    outC[off] = (u < p) ? 1.f : 0.f;
                    if (out2) out2[off] = rna_tf32(p);  // MMA operand downstream
                    if (red_mode == 2) {
                        float v = vmon[off];
                        local += (double)(v * logf(p + 1e-10f)
                                          + (1.f - v) * logf(1.f - p + 1e-10f));
                    }
                }
            }
        }
    }

    if (red_mode) {
        __shared__ double rs[256];
        rs[tid] = local;
        __syncthreads();
        for (int s = 128; s > 0; s >>= 1) {
            if (tid < s) rs[tid] += rs[tid + s];
            __syncthreads();
        }
        if (tid == 0) atomicAdd(&red[slot], rs[0]);
    }
}

// ---------------------------------------------------------------------------
// dot-product reductions for the free-energy bias terms
// ---------------------------------------------------------------------------
__global__ void __launch_bounds__(256)
k_dots(const float* __restrict__ v,   const float* __restrict__ bvt,
       const float* __restrict__ vs,  const float* __restrict__ h1,
       const float* __restrict__ h1s, const float* __restrict__ bh1t,
       double* __restrict__ red)
{
    size_t i0  = (size_t)blockIdx.x * blockDim.x + threadIdx.x;
    size_t str = (size_t)gridDim.x * blockDim.x;
    size_t nv  = (size_t)SEQ_ * NV_;
    size_t nh  = (size_t)SEQ_ * NH_;
    double d5 = 0, d6 = 0, d7 = 0;
    for (size_t i = i0; i < nv; i += str) {
        float b = bvt[i];
        d5 += (double)(v[i]  * b);
        d6 += (double)(vs[i] * b);
    }
    for (size_t i = i0; i < nh; i += str)
        d7 += (double)((h1[i] - h1s[i]) * bh1t[i]);

    __shared__ double s5[256], s6[256], s7[256];
    int t = threadIdx.x;
    s5[t] = d5; s6[t] = d6; s7[t] = d7;
    __syncthreads();
    for (int s = 128; s > 0; s >>= 1) {
        if (t < s) { s5[t] += s5[t+s]; s6[t] += s6[t+s]; s7[t] += s7[t+s]; }
        __syncthreads();
    }
    if (t == 0) {
        atomicAdd(&red[5], s5[0]);
        atomicAdd(&red[6], s6[0]);
        atomicAdd(&red[7], s7[0]);
    }
}

__global__ void k_final(const double* __restrict__ red, float* __restrict__ out)
{
    double cost1 = (-red[5] - red[0] + red[6] + red[1]) / (double)SEQ_;
    double cost2 = (-red[7] - red[2] + red[3]) / (double)SEQ_;
    out[0] = (float)(cost1 + cost2);
    out[1] = (float)(red[4] / (double)SEQ_);
}

// ---------------------------------------------------------------------------
// host
// ---------------------------------------------------------------------------
static inline void launch_gemm(const float* A, int shiftA, const float* B,
                               int K, int N,
                               const float* bvec, const float* barr,
                               float* outC, float* out2, int mode,
                               int red_mode, int slot, const float* vmon,
                               uint32_t kk0, uint32_t kk1, double* acc)
{
    dim3 grid(N / BN, SEQ_ / BM), blk(256);
    uint32_t half = (uint32_t)(((size_t)SEQ_ * (size_t)N) / 2);
    gemm_ep<<<grid, blk, GEMM_SMEM>>>(A, shiftA, B, K, N, bvec, barr, outC, out2,
                                      mode, red_mode, slot, vmon, kk0, kk1, half, acc);
}

extern "C" void kernel_launch(void* const* d_in, const int* in_sizes, int n_in,
                              void* d_out, int out_size)
{
    const float* v_seq = (const float*)d_in[0];
    const float* W1    = (const float*)d_in[1];
    const float* bv    = (const float*)d_in[2];
    const float* bh1   = (const float*)d_in[3];
    const float* W2    = (const float*)d_in[4];
    const float* bh2   = (const float*)d_in[5];
    const float* Wyv   = (const float*)d_in[6];
    const float* Wyh1  = (const float*)d_in[7];
    const float* Wyh2  = (const float*)d_in[8];
    const float* Wvu   = (const float*)d_in[9];
    const float* Wuu   = (const float*)d_in[10];
    const float* bu    = (const float*)d_in[11];
    float* out = (float*)d_out;

    cudaFuncSetAttribute(gemm_ep, cudaFuncAttributeMaxDynamicSharedMemorySize, GEMM_SMEM);

    float *X, *Ua, *Ub, *bvt, *bh1t, *bh2t, *h, *h1, *h2, *h1s, *vs;
    float *W1t, *W1r, *W2t, *W2r, *Wuut, *Wvut, *Wyvr, *Wyh1r, *Wyh2r;
    double* acc;
    cudaGetSymbolAddress((void**)&X,    g_X);
    cudaGetSymbolAddress((void**)&Ua,   g_Ua);
    cudaGetSymbolAddress((void**)&Ub,   g_Ub);
    cudaGetSymbolAddress((void**)&bvt,  g_bvt);
    cudaGetSymbolAddress((void**)&bh1t, g_bh1t);
    cudaGetSymbolAddress((void**)&bh2t, g_bh2t);
    cudaGetSymbolAddress((void**)&h,    g_h);
    cudaGetSymbolAddress((void**)&h1,   g_h1);
    cudaGetSymbolAddress((void**)&h2,   g_h2);
    cudaGetSymbolAddress((void**)&h1s,  g_h1s);
    cudaGetSymbolAddress((void**)&vs,   g_vs);
    cudaGetSymbolAddress((void**)&W1t,  g_W1t);
    cudaGetSymbolAddress((void**)&W1r,  g_W1r);
    cudaGetSymbolAddress((void**)&W2t,  g_W2t);
    cudaGetSymbolAddress((void**)&W2r,  g_W2r);
    cudaGetSymbolAddress((void**)&Wuut, g_Wuut);
    cudaGetSymbolAddress((void**)&Wvut, g_Wvut);
    cudaGetSymbolAddress((void**)&Wyvr, g_Wyvr);
    cudaGetSymbolAddress((void**)&Wyh1r,g_Wyh1r);
    cudaGetSymbolAddress((void**)&Wyh2r,g_Wyh2r);
    cudaGetSymbolAddress((void**)&acc,  g_acc);

    // ---- JAX key schedule: key(42) -> 10x split(key,3) ----
    uint32_t kk0 = 0u, kk1 = 42u;
    uint32_t K1[10][2], K2[10][2];
    for (int i = 0; i < 10; i++) {
#if JAX_PARTITIONABLE
        uint32_t n0, n1, a0, a1, b0, b1;
        tf2x32(kk0, kk1, 0u, 0u, &n0, &n1);
        tf2x32(kk0, kk1, 0u, 1u, &a0, &a1);
        tf2x32(kk0, kk1, 0u, 2u, &b0, &b1);
        K1[i][0] = a0; K1[i][1] = a1;
        K2[i][0] = b0; K2[i][1] = b1;
        kk0 = n0; kk1 = n1;
#else
        uint32_t o00, o01, o10, o11, o20, o21;
        tf2x32(kk0, kk1, 0u, 3u, &o00, &o01);
        tf2x32(kk0, kk1, 1u, 4u, &o10, &o11);
        tf2x32(kk0, kk1, 2u, 5u, &o20, &o21);
        K1[i][0] = o20; K1[i][1] = o01;
        K2[i][0] = o11; K2[i][1] = o21;
        kk0 = o00; kk1 = o10;
#endif
    }

    // ---- prep: accumulators + tf32-rounded / transposed weights ----
    k_init<<<1, 32>>>();
    dim3 trb(32, 8);
    k_tr<<<dim3(NH_/32, NV_/32), trb>>>(W1,  W1t,  NV_, NH_);
    k_tr<<<dim3(NH_/32, NH_/32), trb>>>(W2,  W2t,  NH_, NH_);
    k_tr<<<dim3(NR_/32, NV_/32), trb>>>(Wvu, Wvut, NV_, NR_);
    k_tr<<<dim3(NR_/32, NR_/32), trb>>>(Wuu, Wuut, NR_, NR_);
    k_round<<<(NV_*NH_+255)/256, 256>>>(W1,   W1r,   NV_*NH_);
    k_round<<<(NH_*NH_+255)/256, 256>>>(W2,   W2r,   NH_*NH_);
    k_round<<<(NV_*NR_+255)/256, 256>>>(Wyv,  Wyvr,  NV_*NR_);
    k_round<<<(NH_*NR_+255)/256, 256>>>(Wyh1, Wyh1r, NH_*NR_);
    k_round<<<(NH_*NR_+255)/256, 256>>>(Wyh2, Wyh2r, NH_*NR_);

    // X = v_seq @ Wvu + bu
    launch_gemm(v_seq, 0, Wvut, NV_, NR_, bu, nullptr, X, nullptr, 0, 0, 0, nullptr, 0, 0, acc);

    // Jacobi: sweep 0 is tanh(X) (U=0); then NSWEEP-1 GEMM sweeps
    k_tanhx<<<1024, 256>>>();
    for (int s = 1; s < NSWEEP; s++) {
        float* in    = (s % 2 == 1) ? Ub : Ua;
        float* out_u = (s % 2 == 1) ? Ua : Ub;
        launch_gemm(in, 1, Wuut, NR_, NR_, nullptr, X, out_u, nullptr, 1, 0, 0, nullptr, 0, 0, acc);
    }
    // NSWEEP=8 -> final U in Ua

    // time-varying biases from shifted RNN output
    launch_gemm(Ua, 1, Wyvr,  NR_, NV_, bv,  nullptr, bvt,  nullptr, 0, 0, 0, nullptr, 0, 0, acc);
    launch_gemm(Ua, 1, Wyh1r, NR_, NH_, bh1, nullptr, bh1t, nullptr, 0, 0, 0, nullptr, 0, 0, acc);
    launch_gemm(Ua, 1, Wyh2r, NR_, NH_, bh2, nullptr, bh2t, nullptr, 0, 0, 0, nullptr, 0, 0, acc);

    // ---- RBM1 CD-5 (splits 0..4). Iter 0 also yields h1 and FE1(v_seq) sp-sum.
    launch_gemm(v_seq, 0, W1t, NV_, NH_, nullptr, bh1t, h, h1, 2, 1, 0, nullptr,
                K1[0][0], K1[0][1], acc);
    launch_gemm(h, 0, W1r, NH_, NV_, nullptr, bvt, vs, nullptr, 2, 0, 0, nullptr,
                K2[0][0], K2[0][1], acc);
    for (int i = 1; i < CDK_ - 1; i++) {
        launch_gemm(vs, 0, W1t, NV_, NH_, nullptr, bh1t, h, nullptr, 2, 0, 0, nullptr,
                    K1[i][0], K1[i][1], acc);
        launch_gemm(h, 0, W1r, NH_, NV_, nullptr, bvt, vs, nullptr, 2, 0, 0, nullptr,
                    K2[i][0], K2[i][1], acc);
    }
    // last iter: the v-GEMM also accumulates the monitor with mean_v
    launch_gemm(vs, 0, W1t, NV_, NH_, nullptr, bh1t, h, nullptr, 2, 0, 0, nullptr,
                K1[CDK_-1][0], K1[CDK_-1][1], acc);
    launch_gemm(h, 0, W1r, NH_, NV_, nullptr, bvt, vs, nullptr, 2, 2, 4, v_seq,
                K2[CDK_-1][0], K2[CDK_-1][1], acc);

    // FE1(v_sample): softplus(vs@W1 + bh1t)
    launch_gemm(vs, 0, W1t, NV_, NH_, nullptr, bh1t, nullptr, nullptr, 0, 1, 1, nullptr,
                0, 0, acc);

    // ---- RBM2 CD-5 (splits 5..9). Iter 0 GEMM shares z with FE2(h1) sp-sum.
    launch_gemm(h1, 0, W2t, NH_, NH_, nullptr, bh2t, h2, nullptr, 2, 1, 2, nullptr,
                K1[5][0], K1[5][1], acc);
    launch_gemm(h2, 0, W2r, NH_, NH_, nullptr, bh1t, h1s, nullptr, 2, 0, 0, nullptr,
                K2[5][0], K2[5][1], acc);
    for (int i = 6; i < 10; i++) {
        launch_gemm(h1s, 0, W2t, NH_, NH_, nullptr, bh2t, h2, nullptr, 2, 0, 0, nullptr,
                    K1[i][0], K1[i][1], acc);
        launch_gemm(h2, 0, W2r, NH_, NH_, nullptr, bh1t, h1s, nullptr, 2, 0, 0, nullptr,
                    K2[i][0], K2[i][1], acc);
    }

    // FE2(h1_sample): softplus(h1s@W2 + bh2t)
    launch_gemm(h1s, 0, W2t, NH_, NH_, nullptr, bh2t, nullptr, nullptr, 0, 1, 3, nullptr,
                0, 0, acc);

    // bias dot terms + finalize
    k_dots<<<2048, 256>>>(v_seq, bvt, vs, h1, h1s, bh1t, acc);
    k_final<<<1, 1>>>(acc, out);
}

// round 14
// speedup vs baseline: 2.7983x; 1.1578x over previous
#include <cuda_runtime.h>
#include <stdint.h>
#include <math.h>

#define SEQ_   32768
#define NV_    256
#define NH_    512
#define NR_    256
#define CDK_   5
#define NSWEEP 8

// JAX >= 0.5 default: jax_threefry_partitionable = True
#define JAX_PARTITIONABLE 1

// ---------------------------------------------------------------------------
// Scratch (device globals; allocation-free per harness rules)
// ---------------------------------------------------------------------------
__device__ float g_X   [(size_t)SEQ_ * NR_];
__device__ float g_Ua  [(size_t)SEQ_ * NR_];
__device__ float g_Ub  [(size_t)SEQ_ * NR_];
__device__ float g_bvt [(size_t)SEQ_ * NV_];
__device__ float g_bh1t[(size_t)SEQ_ * NH_];
__device__ float g_bh2t[(size_t)SEQ_ * NH_];
__device__ float g_h   [(size_t)SEQ_ * NH_];
__device__ float g_h1  [(size_t)SEQ_ * NH_];
__device__ float g_h2  [(size_t)SEQ_ * NH_];
__device__ float g_h1s [(size_t)SEQ_ * NH_];
__device__ float g_vs  [(size_t)SEQ_ * NV_];
// tf32-rounded weight copies (all in [N,K] layout for the GEMM's B operand)
__device__ float g_W1t [(size_t)NH_ * NV_];   // W1^T  [NH,NV]
__device__ float g_W1r [(size_t)NV_ * NH_];   // W1    [NV,NH]
__device__ float g_W2t [(size_t)NH_ * NH_];   // W2^T
__device__ float g_W2r [(size_t)NH_ * NH_];   // W2
__device__ float g_Wuut[(size_t)NR_ * NR_];   // Wuu^T
__device__ float g_Wvut[(size_t)NR_ * NV_];   // Wvu^T
__device__ float g_Wyvr [(size_t)NV_ * NR_];
__device__ float g_Wyh1r[(size_t)NH_ * NR_];
__device__ float g_Wyh2r[(size_t)NH_ * NR_];
// 0: sum sp(v_seq)   1: sum sp(v_sample)  2: sum sp(h1)  3: sum sp(h1_sample)
// 4: monitor sum     5: sum v_seq.bvt     6: sum vs.bvt  7: sum (h1-h1s).bh1t
__device__ double g_acc[8];

// ---------------------------------------------------------------------------
// Threefry-2x32 (20 rounds) — exactly JAX's cipher
// ---------------------------------------------------------------------------
__host__ __device__ __forceinline__
void tf2x32(uint32_t k0, uint32_t k1, uint32_t x0, uint32_t x1,
            uint32_t* o0, uint32_t* o1)
{
    uint32_t ks2 = k0 ^ k1 ^ 0x1BD11BDAu;
    x0 += k0; x1 += k1;
#define TF_RND(R) { x0 += x1; x1 = (x1 << (R)) | (x1 >> (32 - (R))); x1 ^= x0; }
    TF_RND(13) TF_RND(15) TF_RND(26) TF_RND(6)
    x0 += k1;  x1 += ks2 + 1u;
    TF_RND(17) TF_RND(29) TF_RND(16) TF_RND(24)
    x0 += ks2; x1 += k0 + 2u;
    TF_RND(13) TF_RND(15) TF_RND(26) TF_RND(6)
    x0 += k0;  x1 += k1 + 3u;
    TF_RND(17) TF_RND(29) TF_RND(16) TF_RND(24)
    x0 += k1;  x1 += ks2 + 4u;
    TF_RND(13) TF_RND(15) TF_RND(26) TF_RND(6)
    x0 += ks2; x1 += k0 + 5u;
#undef TF_RND
    *o0 = x0; *o1 = x1;
}

__device__ __forceinline__
float jx_uniform(uint32_t k0, uint32_t k1, uint32_t idx, uint32_t half)
{
    uint32_t bits;
#if JAX_PARTITIONABLE
    uint32_t o0, o1;
    tf2x32(k0, k1, 0u, idx, &o0, &o1);
    bits = o0 ^ o1;
#else
    uint32_t o0, o1;
    if (idx < half) { tf2x32(k0, k1, idx, idx + half, &o0, &o1); bits = o0; }
    else            { tf2x32(k0, k1, idx - half, idx, &o0, &o1); bits = o1; }
#endif
    return __uint_as_float((bits >> 9) | 0x3f800000u) - 1.0f;
}

__device__ __forceinline__ float rna_tf32(float x)
{
    uint32_t u;
    asm("cvt.rna.tf32.f32 %0, %1;" : "=r"(u) : "f"(x));
    return __uint_as_float(u);
}

__device__ __forceinline__ uint32_t smem_u32(const void* p)
{
    uint32_t a;
    asm("{ .reg .u64 t; cvta.to.shared.u64 t, %1; cvt.u32.u64 %0, t; }"
        : "=r"(a) : "l"(p));
    return a;
}

__device__ __forceinline__ void cp16(uint32_t dst, const void* src, bool pred)
{
    int sz = pred ? 16 : 0;
    asm volatile("cp.async.cg.shared.global [%0], [%1], 16, %2;"
                 :: "r"(dst), "l"(src), "r"(sz));
}
template<int NWAIT>
__device__ __forceinline__ void cp_wait()
{
    asm volatile("cp.async.wait_group %0;" :: "n"(NWAIT) : "memory");
}
__device__ __forceinline__ void cp_commit()
{
    asm volatile("cp.async.commit_group;" ::: "memory");
}
__device__ __forceinline__ void ldsm_x4(uint32_t& r0, uint32_t& r1,
                                        uint32_t& r2, uint32_t& r3, uint32_t addr)
{
    asm volatile("ldmatrix.sync.aligned.m8n8.x4.shared.b16 {%0,%1,%2,%3}, [%4];"
                 : "=r"(r0), "=r"(r1), "=r"(r2), "=r"(r3) : "r"(addr));
}

// ---------------------------------------------------------------------------
// prep kernels
// ---------------------------------------------------------------------------
__global__ void k_init()
{
    int i = blockIdx.x * blockDim.x + threadIdx.x;
    if (i < 8) g_acc[i] = 0.0;
}

__global__ void k_round(const float* __restrict__ in, float* __restrict__ out, int n)
{
    int i = blockIdx.x * blockDim.x + threadIdx.x;
    if (i < n) out[i] = rna_tf32(in[i]);
}

__global__ void k_tr(const float* __restrict__ in, float* __restrict__ out, int R, int C)
{
    __shared__ float t[32][33];
    int bx = blockIdx.x * 32, by = blockIdx.y * 32;
#pragma unroll
    for (int dy = 0; dy < 32; dy += 8)
        t[threadIdx.y + dy][threadIdx.x] = in[(size_t)(by + threadIdx.y + dy) * C + bx + threadIdx.x];
    __syncthreads();
#pragma unroll
    for (int dy = 0; dy < 32; dy += 8)
        out[(size_t)(bx + threadIdx.y + dy) * R + by + threadIdx.x] =
            rna_tf32(t[threadIdx.x][threadIdx.y + dy]);
}

// Ub = rna(tanh(X))   (first Jacobi application with U=0)
__global__ void k_tanhx()
{
    size_t i   = (size_t)blockIdx.x * blockDim.x + threadIdx.x;
    size_t tot = (size_t)SEQ_ * NR_;
    size_t str = (size_t)gridDim.x * blockDim.x;
    for (size_t j = i; j < tot; j += str) g_Ub[j] = rna_tf32(tanhf(g_X[j]));
}

// ---------------------------------------------------------------------------
// Fused tf32 tensor-core GEMM (unchanged from round 13 — proven).
// ---------------------------------------------------------------------------
#define BM 128
#define BN 128
#define BK 32
#define STAGE_BYTES (BM * BK * 4)            // 16384
#define GEMM_SMEM   (6 * STAGE_BYTES)        // 98304: 3x A + 3x B

__global__ void __launch_bounds__(256, 2)
gemm_ep(const float* __restrict__ A, int shiftA,
        const float* __restrict__ Bm, int K, int N,
        const float* __restrict__ bias_vec,
        const float* __restrict__ bias_arr,
        float* __restrict__ outC, float* __restrict__ out2,
        int mode, int red_mode, int slot,
        const float* __restrict__ vmon,
        uint32_t rk0, uint32_t rk1, uint32_t half,
        double* __restrict__ red)
{
    extern __shared__ float dsm[];
    const uint32_t sA0 = smem_u32(dsm);
    const uint32_t sB0 = sA0 + 3u * STAGE_BYTES;

    const int tid  = threadIdx.x;
    const int lane = tid & 31;
    const int wid  = tid >> 5;
    const int warpM = wid >> 2;
    const int warpN = wid & 3;
    const int qr = lane >> 2;
    const int qc = lane & 3;
    const int rowBase = blockIdx.y * BM;
    const int colBase = blockIdx.x * BN;
    const int mBase = warpM * 64;
    const int nBase = warpN * 32;

    const int ch = tid & 7;
    const int rr = tid >> 3;
    const size_t kStride = (size_t)32 * K;
    const float* aBase = A + (size_t)(rowBase + rr - shiftA) * K + ch * 4;
    const float* bBase = Bm + (size_t)(colBase + rr) * K + ch * 4;
    const uint32_t dOff = (uint32_t)rr * (BK * 4) + ((uint32_t)(ch ^ (rr & 7)) << 4);
    const int aRow0 = rowBase + rr - shiftA;

    uint32_t pA[4], pB[2];
    {
        const int hi = lane >> 4;
#pragma unroll
        for (int mt = 0; mt < 4; mt++) {
            int row = mBase + mt * 16 + (lane & 15);
            pA[mt] = (sA0 + (uint32_t)row * (BK * 4))
                     ^ ((uint32_t)(row & 7) << 4) ^ ((uint32_t)hi << 4);
        }
        const int bsel = (lane >> 3) & 1;
#pragma unroll
        for (int pr = 0; pr < 2; pr++) {
            int n = nBase + pr * 16 + (lane & 7) + (hi << 3);
            pB[pr] = (sB0 + (uint32_t)n * (BK * 4))
                     ^ ((uint32_t)(n & 7) << 4) ^ ((uint32_t)bsel << 4);
        }
    }

    float c[4][4][4];
#pragma unroll
    for (int mt = 0; mt < 4; mt++)
#pragma unroll
        for (int nt = 0; nt < 4; nt++)
#pragma unroll
            for (int e = 0; e < 4; e++) c[mt][nt][e] = 0.0f;

    auto load_tile = [&](int st, int kc) {
        const uint32_t so = (uint32_t)st * STAGE_BYTES;
        const uint32_t aD = sA0 + so + dOff;
        const uint32_t bD = sB0 + so + dOff;
#pragma unroll
        for (int p = 0; p < 4; p++)
            cp16(aD + (uint32_t)p * 32 * (BK * 4), aBase + p * kStride + kc,
                 (aRow0 + 32 * p) >= 0);
#pragma unroll
        for (int p = 0; p < 4; p++)
            cp16(bD + (uint32_t)p * 32 * (BK * 4), bBase + p * kStride + kc, true);
    };

    const int T = K / BK;
    load_tile(0, 0);               cp_commit();
    if (T > 1) { load_tile(1, BK); cp_commit(); }

    for (int t = 0; t < T; t++) {
        if (t + 1 < T) cp_wait<1>(); else cp_wait<0>();
        __syncthreads();
        if (t + 2 < T) { load_tile((t + 2) % 3, (t + 2) * BK); cp_commit(); }

        const uint32_t so = (uint32_t)(t % 3) * STAGE_BYTES;

        uint32_t af[2][4][4];
#pragma unroll
        for (int mt = 0; mt < 4; mt++)
            ldsm_x4(af[0][mt][0], af[0][mt][1], af[0][mt][2], af[0][mt][3],
                    pA[mt] + so);

#pragma unroll
        for (int kk = 0; kk < 4; kk++) {
            const int cur = kk & 1;
            if (kk < 3) {
#pragma unroll
                for (int mt = 0; mt < 4; mt++)
                    ldsm_x4(af[cur ^ 1][mt][0], af[cur ^ 1][mt][1],
                            af[cur ^ 1][mt][2], af[cur ^ 1][mt][3],
                            (pA[mt] + so) ^ ((uint32_t)(kk + 1) << 5));
            }
            uint32_t bf[2][4];
#pragma unroll
            for (int pr = 0; pr < 2; pr++)
                ldsm_x4(bf[pr][0], bf[pr][1], bf[pr][2], bf[pr][3],
                        (pB[pr] + so) ^ ((uint32_t)kk << 5));
#pragma unroll
            for (int mt = 0; mt < 4; mt++)
#pragma unroll
                for (int nt = 0; nt < 4; nt++) {
                    uint32_t b0 = bf[nt >> 1][(nt & 1) * 2];
                    uint32_t b1 = bf[nt >> 1][(nt & 1) * 2 + 1];
                    asm volatile(
                        "mma.sync.aligned.m16n8k8.row.col.f32.tf32.tf32.f32 "
                        "{%0,%1,%2,%3}, {%4,%5,%6,%7}, {%8,%9}, {%0,%1,%2,%3};"
                        : "+f"(c[mt][nt][0]), "+f"(c[mt][nt][1]),
                          "+f"(c[mt][nt][2]), "+f"(c[mt][nt][3])
                        : "r"(af[cur][mt][0]), "r"(af[cur][mt][1]),
                          "r"(af[cur][mt][2]), "r"(af[cur][mt][3]),
                          "r"(b0), "r"(b1));
                }
        }
    }

    double local = 0.0;
#pragma unroll
    for (int mt = 0; mt < 4; mt++) {
#pragma unroll
        for (int nt = 0; nt < 4; nt++) {
#pragma unroll
            for (int e = 0; e < 4; e++) {
                int r  = rowBase + mBase + mt * 16 + qr + ((e >> 1) << 3);
                int nn = colBase + nBase + nt * 8 + (qc << 1) + (e & 1);
                size_t off = (size_t)r * N + nn;
                float z = c[mt][nt][e];
                if (bias_vec) z += bias_vec[nn];
                if (bias_arr) z += bias_arr[off];

                if (red_mode == 1) {
                    local += (double)(fmaxf(z, 0.f) + log1pf(expf(-fabsf(z))));
                }

                if (mode == 0) {
                    if (outC) outC[off] = z;
                } else if (mode == 1) {
                    outC[off] = rna_tf32(tanhf(z));
                } else {
                    float p = 1.f / (1.f + expf(-z));
                    float u = jx_uniform(rk0, rk1, (uint32_t)off, half);
                    outC[off] = (u < p) ? 1.f : 0.f;
                    if (out2) out2[off] = rna_tf32(p);
                    if (red_mode == 2) {
                        float v = vmon[off];
                        local += (double)(v * logf(p + 1e-10f)
                                          + (1.f - v) * logf(1.f - p + 1e-10f));
                    }
                }
            }
        }
    }

    if (red_mode) {
        __shared__ double rs[256];
        rs[tid] = local;
        __syncthreads();
        for (int s = 128; s > 0; s >>= 1) {
            if (tid < s) rs[tid] += rs[tid + s];
            __syncthreads();
        }
        if (tid == 0) atomicAdd(&red[slot], rs[0]);
    }
}

// ---------------------------------------------------------------------------
// dot-product reductions for the free-energy bias terms
// ---------------------------------------------------------------------------
__global__ void __launch_bounds__(256)
k_dots(const float* __restrict__ v,   const float* __restrict__ bvt,
       const float* __restrict__ vs,  const float* __restrict__ h1,
       const float* __restrict__ h1s, const float* __restrict__ bh1t,
       double* __restrict__ red)
{
    size_t i0  = (size_t)blockIdx.x * blockDim.x + threadIdx.x;
    size_t str = (size_t)gridDim.x * blockDim.x;
    size_t nv  = (size_t)SEQ_ * NV_;
    size_t nh  = (size_t)SEQ_ * NH_;
    double d5 = 0, d6 = 0, d7 = 0;
    for (size_t i = i0; i < nv; i += str) {
        float b = bvt[i];
        d5 += (double)(v[i]  * b);
        d6 += (double)(vs[i] * b);
    }
    for (size_t i = i0; i < nh; i += str)
        d7 += (double)((h1[i] - h1s[i]) * bh1t[i]);

    __shared__ double s5[256], s6[256], s7[256];
    int t = threadIdx.x;
    s5[t] = d5; s6[t] = d6; s7[t] = d7;
    __syncthreads();
    for (int s = 128; s > 0; s >>= 1) {
        if (t < s) { s5[t] += s5[t+s]; s6[t] += s6[t+s]; s7[t] += s7[t+s]; }
        __syncthreads();
    }
    if (t == 0) {
        atomicAdd(&red[5], s5[0]);
        atomicAdd(&red[6], s6[0]);
        atomicAdd(&red[7], s7[0]);
    }
}

__global__ void k_final(const double* __restrict__ red, float* __restrict__ out)
{
    double cost1 = (-red[5] - red[0] + red[6] + red[1]) / (double)SEQ_;
    double cost2 = (-red[7] - red[2] + red[3]) / (double)SEQ_;
    out[0] = (float)(cost1 + cost2);
    out[1] = (float)(red[4] / (double)SEQ_);
}

// ---------------------------------------------------------------------------
// host
// ---------------------------------------------------------------------------
static inline void launch_gemm(cudaStream_t st,
                               const float* A, int shiftA, const float* B,
                               int K, int N,
                               const float* bvec, const float* barr,
                               float* outC, float* out2, int mode,
                               int red_mode, int slot, const float* vmon,
                               uint32_t kk0, uint32_t kk1, double* acc)
{
    dim3 grid(N / BN, SEQ_ / BM), blk(256);
    uint32_t half = (uint32_t)(((size_t)SEQ_ * (size_t)N) / 2);
    gemm_ep<<<grid, blk, GEMM_SMEM, st>>>(A, shiftA, B, K, N, bvec, barr, outC, out2,
                                          mode, red_mode, slot, vmon, kk0, kk1, half, acc);
}

extern "C" void kernel_launch(void* const* d_in, const int* in_sizes, int n_in,
                              void* d_out, int out_size)
{
    const float* v_seq = (const float*)d_in[0];
    const float* W1    = (const float*)d_in[1];
    const float* bv    = (const float*)d_in[2];
    const float* bh1   = (const float*)d_in[3];
    const float* W2    = (const float*)d_in[4];
    const float* bh2   = (const float*)d_in[5];
    const float* Wyv   = (const float*)d_in[6];
    const float* Wyh1  = (const float*)d_in[7];
    const float* Wyh2  = (const float*)d_in[8];
    const float* Wvu   = (const float*)d_in[9];
    const float* Wuu   = (const float*)d_in[10];
    const float* bu    = (const float*)d_in[11];
    float* out = (float*)d_out;

    // one-time setup of second stream + fork/join events (host objects only)
    static cudaStream_t s2 = nullptr;
    static cudaEvent_t evFork, evBvt, evH1, evD;
    if (!s2) {
        cudaStreamCreateWithFlags(&s2, cudaStreamNonBlocking);
        cudaEventCreateWithFlags(&evFork, cudaEventDisableTiming);
        cudaEventCreateWithFlags(&evBvt,  cudaEventDisableTiming);
        cudaEventCreateWithFlags(&evH1,   cudaEventDisableTiming);
        cudaEventCreateWithFlags(&evD,    cudaEventDisableTiming);
        cudaFuncSetAttribute(gemm_ep, cudaFuncAttributeMaxDynamicSharedMemorySize, GEMM_SMEM);
    }
    cudaStream_t s0 = 0;

    float *X, *Ua, *Ub, *bvt, *bh1t, *bh2t, *h, *h1, *h2, *h1s, *vs;
    float *W1t, *W1r, *W2t, *W2r, *Wuut, *Wvut, *Wyvr, *Wyh1r, *Wyh2r;
    double* acc;
    cudaGetSymbolAddress((void**)&X,    g_X);
    cudaGetSymbolAddress((void**)&Ua,   g_Ua);
    cudaGetSymbolAddress((void**)&Ub,   g_Ub);
    cudaGetSymbolAddress((void**)&bvt,  g_bvt);
    cudaGetSymbolAddress((void**)&bh1t, g_bh1t);
    cudaGetSymbolAddress((void**)&bh2t, g_bh2t);
    cudaGetSymbolAddress((void**)&h,    g_h);
    cudaGetSymbolAddress((void**)&h1,   g_h1);
    cudaGetSymbolAddress((void**)&h2,   g_h2);
    cudaGetSymbolAddress((void**)&h1s,  g_h1s);
    cudaGetSymbolAddress((void**)&vs,   g_vs);
    cudaGetSymbolAddress((void**)&W1t,  g_W1t);
    cudaGetSymbolAddress((void**)&W1r,  g_W1r);
    cudaGetSymbolAddress((void**)&W2t,  g_W2t);
    cudaGetSymbolAddress((void**)&W2r,  g_W2r);
    cudaGetSymbolAddress((void**)&Wuut, g_Wuut);
    cudaGetSymbolAddress((void**)&Wvut, g_Wvut);
    cudaGetSymbolAddress((void**)&Wyvr, g_Wyvr);
    cudaGetSymbolAddress((void**)&Wyh1r,g_Wyh1r);
    cudaGetSymbolAddress((void**)&Wyh2r,g_Wyh2r);
    cudaGetSymbolAddress((void**)&acc,  g_acc);

    // ---- JAX key schedule: key(42) -> 10x split(key,3) ----
    uint32_t kk0 = 0u, kk1 = 42u;
    uint32_t K1[10][2], K2[10][2];
    for (int i = 0; i < 10; i++) {
#if JAX_PARTITIONABLE
        uint32_t n0, n1, a0, a1, b0, b1;
        tf2x32(kk0, kk1, 0u, 0u, &n0, &n1);
        tf2x32(kk0, kk1, 0u, 1u, &a0, &a1);
        tf2x32(kk0, kk1, 0u, 2u, &b0, &b1);
        K1[i][0] = a0; K1[i][1] = a1;
        K2[i][0] = b0; K2[i][1] = b1;
        kk0 = n0; kk1 = n1;
#else
        uint32_t o00, o01, o10, o11, o20, o21;
        tf2x32(kk0, kk1, 0u, 3u, &o00, &o01);
        tf2x32(kk0, kk1, 1u, 4u, &o10, &o11);
        tf2x32(kk0, kk1, 2u, 5u, &o20, &o21);
        K1[i][0] = o20; K1[i][1] = o01;
        K2[i][0] = o11; K2[i][1] = o21;
        kk0 = o00; kk1 = o10;
#endif
    }

    // ===== fork: s2 joins the capture graph =====
    cudaEventRecord(evFork, s0);
    cudaStreamWaitEvent(s2, evFork, 0);

    // ---- prep (split across streams) ----
    dim3 trb(32, 8);
    // s0: everything the s0 chain needs
    k_init<<<1, 32, 0, s0>>>();
    k_tr<<<dim3(NR_/32, NV_/32), trb, 0, s0>>>(Wvu, Wvut, NV_, NR_);
    k_tr<<<dim3(NR_/32, NR_/32), trb, 0, s0>>>(Wuu, Wuut, NR_, NR_);
    k_tr<<<dim3(NH_/32, NV_/32), trb, 0, s0>>>(W1,  W1t,  NV_, NH_);
    k_round<<<(NV_*NH_+255)/256, 256, 0, s0>>>(W1,   W1r,   NV_*NH_);
    k_round<<<(NV_*NR_+255)/256, 256, 0, s0>>>(Wyv,  Wyvr,  NV_*NR_);
    k_round<<<(NH_*NR_+255)/256, 256, 0, s0>>>(Wyh1, Wyh1r, NH_*NR_);
    // s2: RBM2's weights
    k_tr<<<dim3(NH_/32, NH_/32), trb, 0, s2>>>(W2,  W2t,  NH_, NH_);
    k_round<<<(NH_*NH_+255)/256, 256, 0, s2>>>(W2,   W2r,   NH_*NH_);
    k_round<<<(NH_*NR_+255)/256, 256, 0, s2>>>(Wyh2, Wyh2r, NH_*NR_);

    // ---- s0: X = v_seq @ Wvu + bu; Jacobi; bh1t ----
    launch_gemm(s0, v_seq, 0, Wvut, NV_, NR_, bu, nullptr, X, nullptr, 0, 0, 0, nullptr, 0, 0, acc);
    k_tanhx<<<1024, 256, 0, s0>>>();
    for (int s = 1; s < NSWEEP; s++) {
        float* in    = (s % 2 == 1) ? Ub : Ua;
        float* out_u = (s % 2 == 1) ? Ua : Ub;
        launch_gemm(s0, in, 1, Wuut, NR_, NR_, nullptr, X, out_u, nullptr, 1, 0, 0, nullptr, 0, 0, acc);
    }
    // NSWEEP=8 -> final U in Ua
    launch_gemm(s0, Ua, 1, Wyh1r, NR_, NH_, bh1, nullptr, bh1t, nullptr, 0, 0, 0, nullptr, 0, 0, acc);
    cudaEventRecord(evFork, s0);               // reuse as "Ua+Wyvr ready"
    cudaStreamWaitEvent(s2, evFork, 0);

    // ---- s2: bvt, bh2t (concurrent with s0's RBM1 iter-0) ----
    launch_gemm(s2, Ua, 1, Wyvr,  NR_, NV_, bv,  nullptr, bvt,  nullptr, 0, 0, 0, nullptr, 0, 0, acc);
    cudaEventRecord(evBvt, s2);
    launch_gemm(s2, Ua, 1, Wyh2r, NR_, NH_, bh2, nullptr, bh2t, nullptr, 0, 0, 0, nullptr, 0, 0, acc);

    // ---- s0: RBM1 iter 0 (yields h, h1, FE1(v_seq) sp-sum) ----
    launch_gemm(s0, v_seq, 0, W1t, NV_, NH_, nullptr, bh1t, h, h1, 2, 1, 0, nullptr,
                K1[0][0], K1[0][1], acc);
    cudaEventRecord(evH1, s0);

    // ---- s2: RBM2 CD-5 chain (needs h1, bh2t, bh1t) ----
    cudaStreamWaitEvent(s2, evH1, 0);
    launch_gemm(s2, h1, 0, W2t, NH_, NH_, nullptr, bh2t, h2, nullptr, 2, 1, 2, nullptr,
                K1[5][0], K1[5][1], acc);
    launch_gemm(s2, h2, 0, W2r, NH_, NH_, nullptr, bh1t, h1s, nullptr, 2, 0, 0, nullptr,
                K2[5][0], K2[5][1], acc);
    for (int i = 6; i < 10; i++) {
        launch_gemm(s2, h1s, 0, W2t, NH_, NH_, nullptr, bh2t, h2, nullptr, 2, 0, 0, nullptr,
                    K1[i][0], K1[i][1], acc);
        launch_gemm(s2, h2, 0, W2r, NH_, NH_, nullptr, bh1t, h1s, nullptr, 2, 0, 0, nullptr,
                    K2[i][0], K2[i][1], acc);
    }
    launch_gemm(s2, h1s, 0, W2t, NH_, NH_, nullptr, bh2t, nullptr, nullptr, 0, 1, 3, nullptr,
                0, 0, acc);
    cudaEventRecord(evD, s2);

    // ---- s0: RBM1 chain (needs bvt from s2) ----
    cudaStreamWaitEvent(s0, evBvt, 0);
    launch_gemm(s0, h, 0, W1r, NH_, NV_, nullptr, bvt, vs, nullptr, 2, 0, 0, nullptr,
                K2[0][0], K2[0][1], acc);
    for (int i = 1; i < CDK_ - 1; i++) {
        launch_gemm(s0, vs, 0, W1t, NV_, NH_, nullptr, bh1t, h, nullptr, 2, 0, 0, nullptr,
                    K1[i][0], K1[i][1], acc);
        launch_gemm(s0, h, 0, W1r, NH_, NV_, nullptr, bvt, vs, nullptr, 2, 0, 0, nullptr,
                    K2[i][0], K2[i][1], acc);
    }
    launch_gemm(s0, vs, 0, W1t, NV_, NH_, nullptr, bh1t, h, nullptr, 2, 0, 0, nullptr,
                K1[CDK_-1][0], K1[CDK_-1][1], acc);
    launch_gemm(s0, h, 0, W1r, NH_, NV_, nullptr, bvt, vs, nullptr, 2, 2, 4, v_seq,
                K2[CDK_-1][0], K2[CDK_-1][1], acc);
    launch_gemm(s0, vs, 0, W1t, NV_, NH_, nullptr, bh1t, nullptr, nullptr, 0, 1, 1, nullptr,
                0, 0, acc);

    // ===== join: s0 waits for s2's chain, then reduce/finalize =====
    cudaStreamWaitEvent(s0, evD, 0);
    k_dots<<<2048, 256, 0, s0>>>(v_seq, bvt, vs, h1, h1s, bh1t, acc);
    k_final<<<1, 1, 0, s0>>>(acc, out);
}

// round 15
// speedup vs baseline: 3.8277x; 1.3679x over previous
#include <cuda_runtime.h>
#include <stdint.h>
#include <math.h>

#define SEQ_   32768
#define NV_    256
#define NH_    512
#define NR_    256
#define CDK_   5
#define NSWEEP 6

// JAX >= 0.5 default: jax_threefry_partitionable = True
#define JAX_PARTITIONABLE 1

// ---------------------------------------------------------------------------
// Scratch (device globals; allocation-free per harness rules)
// ---------------------------------------------------------------------------
__device__ float g_X   [(size_t)SEQ_ * NR_];
__device__ float g_Ua  [(size_t)SEQ_ * NR_];
__device__ float g_Ub  [(size_t)SEQ_ * NR_];
__device__ float g_bvt [(size_t)SEQ_ * NV_];
__device__ float g_bh1t[(size_t)SEQ_ * NH_];
__device__ float g_bh2t[(size_t)SEQ_ * NH_];
__device__ float g_h   [(size_t)SEQ_ * NH_];
__device__ float g_h1  [(size_t)SEQ_ * NH_];
__device__ float g_h2  [(size_t)SEQ_ * NH_];
__device__ float g_h1s [(size_t)SEQ_ * NH_];
__device__ float g_vs  [(size_t)SEQ_ * NV_];
// tf32-rounded weight copies (all in [N,K] layout for the GEMM's B operand)
__device__ float g_W1t [(size_t)NH_ * NV_];   // W1^T  [NH,NV]
__device__ float g_W1r [(size_t)NV_ * NH_];   // W1    [NV,NH]
__device__ float g_W2t [(size_t)NH_ * NH_];   // W2^T
__device__ float g_W2r [(size_t)NH_ * NH_];   // W2
__device__ float g_Wuut[(size_t)NR_ * NR_];   // Wuu^T
__device__ float g_Wvut[(size_t)NR_ * NV_];   // Wvu^T
__device__ float g_Wyvr [(size_t)NV_ * NR_];
__device__ float g_Wyh1r[(size_t)NH_ * NR_];
__device__ float g_Wyh2r[(size_t)NH_ * NR_];
// 0: sum sp(v_seq)   1: sum sp(v_sample)  2: sum sp(h1)  3: sum sp(h1_sample)
// 4: monitor sum     5: sum v_seq.bvt     6: sum vs.bvt  7: sum (h1-h1s).bh1t
__device__ double g_acc[8];

// ---------------------------------------------------------------------------
// Threefry-2x32 (20 rounds) — exactly JAX's cipher
// ---------------------------------------------------------------------------
__host__ __device__ __forceinline__
void tf2x32(uint32_t k0, uint32_t k1, uint32_t x0, uint32_t x1,
            uint32_t* o0, uint32_t* o1)
{
    uint32_t ks2 = k0 ^ k1 ^ 0x1BD11BDAu;
    x0 += k0; x1 += k1;
#define TF_RND(R) { x0 += x1; x1 = (x1 << (R)) | (x1 >> (32 - (R))); x1 ^= x0; }
    TF_RND(13) TF_RND(15) TF_RND(26) TF_RND(6)
    x0 += k1;  x1 += ks2 + 1u;
    TF_RND(17) TF_RND(29) TF_RND(16) TF_RND(24)
    x0 += ks2; x1 += k0 + 2u;
    TF_RND(13) TF_RND(15) TF_RND(26) TF_RND(6)
    x0 += k0;  x1 += k1 + 3u;
    TF_RND(17) TF_RND(29) TF_RND(16) TF_RND(24)
    x0 += k1;  x1 += ks2 + 4u;
    TF_RND(13) TF_RND(15) TF_RND(26) TF_RND(6)
    x0 += ks2; x1 += k0 + 5u;
#undef TF_RND
    *o0 = x0; *o1 = x1;
}

__device__ __forceinline__
float jx_uniform(uint32_t k0, uint32_t k1, uint32_t idx, uint32_t half)
{
    uint32_t bits;
#if JAX_PARTITIONABLE
    uint32_t o0, o1;
    tf2x32(k0, k1, 0u, idx, &o0, &o1);
    bits = o0 ^ o1;
#else
    uint32_t o0, o1;
    if (idx < half) { tf2x32(k0, k1, idx, idx + half, &o0, &o1); bits = o0; }
    else            { tf2x32(k0, k1, idx - half, idx, &o0, &o1); bits = o1; }
#endif
    return __uint_as_float((bits >> 9) | 0x3f800000u) - 1.0f;
}

__device__ __forceinline__ float rna_tf32(float x)
{
    uint32_t u;
    asm("cvt.rna.tf32.f32 %0, %1;" : "=r"(u) : "f"(x));
    return __uint_as_float(u);
}

__device__ __forceinline__ uint32_t smem_u32(const void* p)
{
    uint32_t a;
    asm("{ .reg .u64 t; cvta.to.shared.u64 t, %1; cvt.u32.u64 %0, t; }"
        : "=r"(a) : "l"(p));
    return a;
}

__device__ __forceinline__ void cp16(uint32_t dst, const void* src, bool pred)
{
    int sz = pred ? 16 : 0;
    asm volatile("cp.async.cg.shared.global [%0], [%1], 16, %2;"
                 :: "r"(dst), "l"(src), "r"(sz));
}
template<int NWAIT>
__device__ __forceinline__ void cp_wait()
{
    asm volatile("cp.async.wait_group %0;" :: "n"(NWAIT) : "memory");
}
__device__ __forceinline__ void cp_commit()
{
    asm volatile("cp.async.commit_group;" ::: "memory");
}
__device__ __forceinline__ void ldsm_x4(uint32_t& r0, uint32_t& r1,
                                        uint32_t& r2, uint32_t& r3, uint32_t addr)
{
    asm volatile("ldmatrix.sync.aligned.m8n8.x4.shared.b16 {%0,%1,%2,%3}, [%4];"
                 : "=r"(r0), "=r"(r1), "=r"(r2), "=r"(r3) : "r"(addr));
}

// ---------------------------------------------------------------------------
// prep kernels
// ---------------------------------------------------------------------------
__global__ void k_init()
{
    int i = blockIdx.x * blockDim.x + threadIdx.x;
    if (i < 8) g_acc[i] = 0.0;
}

__global__ void k_round(const float* __restrict__ in, float* __restrict__ out, int n)
{
    int i = blockIdx.x * blockDim.x + threadIdx.x;
    if (i < n) out[i] = rna_tf32(in[i]);
}

__global__ void k_tr(const float* __restrict__ in, float* __restrict__ out, int R, int C)
{
    __shared__ float t[32][33];
    int bx = blockIdx.x * 32, by = blockIdx.y * 32;
#pragma unroll
    for (int dy = 0; dy < 32; dy += 8)
        t[threadIdx.y + dy][threadIdx.x] = in[(size_t)(by + threadIdx.y + dy) * C + bx + threadIdx.x];
    __syncthreads();
#pragma unroll
    for (int dy = 0; dy < 32; dy += 8)
        out[(size_t)(bx + threadIdx.y + dy) * R + by + threadIdx.x] =
            rna_tf32(t[threadIdx.x][threadIdx.y + dy]);
}

// Ub = rna(tanh(X))   (first Jacobi application with U=0)
__global__ void k_tanhx()
{
    size_t i   = (size_t)blockIdx.x * blockDim.x + threadIdx.x;
    size_t tot = (size_t)SEQ_ * NR_;
    size_t str = (size_t)gridDim.x * blockDim.x;
    for (size_t j = i; j < tot; j += str) g_Ub[j] = rna_tf32(tanhf(g_X[j]));
}

// ---------------------------------------------------------------------------
// Fused tf32 tensor-core GEMM — 128x64x32 block tile, 3 CTAs/SM.
//   C[S,N] = A[S,K] @ B^T, B given as [N,K] row-major (pre-transposed weights).
//   8 warps (4 M x 2 N), warp tile 32x32 (mma.m16n8k8.tf32).
//   Smem: row-major [r][k], 16B-chunk swizzle ch^(r&7). 3 stages, 72KB.
//   shiftA: row t of A reads source row t-1 (row 0 -> zeros, cp.async zfill)
//   mode  : 0=linear  1=tanh(rounded)  2=bernoulli sample (out2 gets rounded p)
//   red   : 0=none  1=sum softplus(z)  2=sum monitor(vmon, p)  -> red[slot]
// ---------------------------------------------------------------------------
#define BM 128
#define BN 64
#define BK 32
#define STAGE_A (BM * BK * 4)                  // 16384
#define STAGE_B (BN * BK * 4)                  // 8192
#define GEMM_SMEM (3 * (STAGE_A + STAGE_B))    // 73728

__global__ void __launch_bounds__(256, 3)
gemm_ep(const float* __restrict__ A, int shiftA,
        const float* __restrict__ Bm, int K, int N,
        const float* __restrict__ bias_vec,
        const float* __restrict__ bias_arr,
        float* __restrict__ outC, float* __restrict__ out2,
        int mode, int red_mode, int slot,
        const float* __restrict__ vmon,
        uint32_t rk0, uint32_t rk1, uint32_t half,
        double* __restrict__ red)
{
    extern __shared__ float dsm[];
    const uint32_t sA0 = smem_u32(dsm);
    const uint32_t sB0 = sA0 + 3u * STAGE_A;

    const int tid  = threadIdx.x;
    const int lane = tid & 31;
    const int wid  = tid >> 5;
    const int warpM = wid & 3;            // 0..3  (x32 rows)
    const int warpN = wid >> 2;           // 0..1  (x32 cols)
    const int qr = lane >> 2;
    const int qc = lane & 3;
    const int rowBase = blockIdx.y * BM;
    const int colBase = blockIdx.x * BN;
    const int mBase = warpM * 32;
    const int nBase = warpN * 32;

    // ---- compact loader state ----
    const int ch = tid & 7;
    const int rr = tid >> 3;              // 0..31
    const size_t kStride = (size_t)32 * K;
    const float* aBase = A + (size_t)(rowBase + rr - shiftA) * K + ch * 4;
    const float* bBase = Bm + (size_t)(colBase + rr) * K + ch * 4;
    const uint32_t dOff = (uint32_t)rr * (BK * 4) + ((uint32_t)(ch ^ (rr & 7)) << 4);
    const int aRow0 = rowBase + rr - shiftA;

    // ---- hoisted ldmatrix fragment addresses (stage-0, kk=0) ----
    uint32_t pA[2], pB[2];
    {
        const int hi = lane >> 4;
#pragma unroll
        for (int mt = 0; mt < 2; mt++) {
            int row = mBase + mt * 16 + (lane & 15);
            pA[mt] = (sA0 + (uint32_t)row * (BK * 4))
                     ^ ((uint32_t)(row & 7) << 4) ^ ((uint32_t)hi << 4);
        }
        const int bsel = (lane >> 3) & 1;
#pragma unroll
        for (int pr = 0; pr < 2; pr++) {
            int n = nBase + pr * 16 + (lane & 7) + (hi << 3);
            pB[pr] = (sB0 + (uint32_t)n * (BK * 4))
                     ^ ((uint32_t)(n & 7) << 4) ^ ((uint32_t)bsel << 4);
        }
    }

    float c[2][4][4];
#pragma unroll
    for (int mt = 0; mt < 2; mt++)
#pragma unroll
        for (int nt = 0; nt < 4; nt++)
#pragma unroll
            for (int e = 0; e < 4; e++) c[mt][nt][e] = 0.0f;

    auto load_tile = [&](int st, int kc) {
        const uint32_t aD = sA0 + (uint32_t)st * STAGE_A + dOff;
        const uint32_t bD = sB0 + (uint32_t)st * STAGE_B + dOff;
#pragma unroll
        for (int p = 0; p < 4; p++)
            cp16(aD + (uint32_t)p * 32 * (BK * 4), aBase + p * kStride + kc,
                 (aRow0 + 32 * p) >= 0);
#pragma unroll
        for (int p = 0; p < 2; p++)
            cp16(bD + (uint32_t)p * 32 * (BK * 4), bBase + p * kStride + kc, true);
    };

    const int T = K / BK;
    load_tile(0, 0);               cp_commit();
    if (T > 1) { load_tile(1, BK); cp_commit(); }

    for (int t = 0; t < T; t++) {
        if (t + 1 < T) cp_wait<1>(); else cp_wait<0>();
        __syncthreads();
        if (t + 2 < T) { load_tile((t + 2) % 3, (t + 2) * BK); cp_commit(); }

        const uint32_t soA = (uint32_t)(t % 3) * STAGE_A;
        const uint32_t soB = (uint32_t)(t % 3) * STAGE_B;

        // A-fragment double buffer: prefetch kk=0
        uint32_t af[2][2][4];
#pragma unroll
        for (int mt = 0; mt < 2; mt++)
            ldsm_x4(af[0][mt][0], af[0][mt][1], af[0][mt][2], af[0][mt][3],
                    pA[mt] + soA);

#pragma unroll
        for (int kk = 0; kk < 4; kk++) {
            const int cur = kk & 1;
            if (kk < 3) {
#pragma unroll
                for (int mt = 0; mt < 2; mt++)
                    ldsm_x4(af[cur ^ 1][mt][0], af[cur ^ 1][mt][1],
                            af[cur ^ 1][mt][2], af[cur ^ 1][mt][3],
                            (pA[mt] + soA) ^ ((uint32_t)(kk + 1) << 5));
            }
            uint32_t bf[2][4];
#pragma unroll
            for (int pr = 0; pr < 2; pr++)
                ldsm_x4(bf[pr][0], bf[pr][1], bf[pr][2], bf[pr][3],
                        (pB[pr] + soB) ^ ((uint32_t)kk << 5));
#pragma unroll
            for (int mt = 0; mt < 2; mt++)
#pragma unroll
                for (int nt = 0; nt < 4; nt++) {
                    uint32_t b0 = bf[nt >> 1][(nt & 1) * 2];
                    uint32_t b1 = bf[nt >> 1][(nt & 1) * 2 + 1];
                    asm volatile(
                        "mma.sync.aligned.m16n8k8.row.col.f32.tf32.tf32.f32 "
                        "{%0,%1,%2,%3}, {%4,%5,%6,%7}, {%8,%9}, {%0,%1,%2,%3};"
                        : "+f"(c[mt][nt][0]), "+f"(c[mt][nt][1]),
                          "+f"(c[mt][nt][2]), "+f"(c[mt][nt][3])
                        : "r"(af[cur][mt][0]), "r"(af[cur][mt][1]),
                          "r"(af[cur][mt][2]), "r"(af[cur][mt][3]),
                          "r"(b0), "r"(b1));
                }
        }
    }

    // ---- epilogue (fragment layout: e0:(qr,2qc) e1:(qr,2qc+1) e2:+8row e3) ----
    double local = 0.0;
#pragma unroll
    for (int mt = 0; mt < 2; mt++) {
#pragma unroll
        for (int nt = 0; nt < 4; nt++) {
#pragma unroll
            for (int e = 0; e < 4; e++) {
                int r  = rowBase + mBase + mt * 16 + qr + ((e >> 1) << 3);
                int nn = colBase + nBase + nt * 8 + (qc << 1) + (e & 1);
                size_t off = (size_t)r * N + nn;
                float z = c[mt][nt][e];
                if (bias_vec) z += bias_vec[nn];
                if (bias_arr) z += bias_arr[off];

                if (red_mode == 1) {
                    local += (double)(fmaxf(z, 0.f) + log1pf(expf(-fabsf(z))));
                }

                if (mode == 0) {
                    if (outC) outC[off] = z;
                } else if (mode == 1) {
                    outC[off] = rna_tf32(tanhf(z));
                } else {
                    float p = 1.f / (1.f + expf(-z));
                    float u = jx_uniform(rk0, rk1, (uint32_t)off, half);
                    outC[off] = (u < p) ? 1.f : 0.f;
                    if (out2) out2[off] = rna_tf32(p);
                    if (red_mode == 2) {
                        float v = vmon[off];
                        local += (double)(v * logf(p + 1e-10f)
                                          + (1.f - v) * logf(1.f - p + 1e-10f));
                    }
                }
            }
        }
    }

    if (red_mode) {
        __shared__ double rs[256];
        rs[tid] = local;
        __syncthreads();
        for (int s = 128; s > 0; s >>= 1) {
            if (tid < s) rs[tid] += rs[tid + s];
            __syncthreads();
        }
        if (tid == 0) atomicAdd(&red[slot], rs[0]);
    }
}

// ---------------------------------------------------------------------------
// dot-product reductions for the free-energy bias terms
// ---------------------------------------------------------------------------
__global__ void __launch_bounds__(256)
k_dots(const float* __restrict__ v,   const float* __restrict__ bvt,
       const float* __restrict__ vs,  const float* __restrict__ h1,
       const float* __restrict__ h1s, const float* __restrict__ bh1t,
       double* __restrict__ red)
{
    size_t i0  = (size_t)blockIdx.x * blockDim.x + threadIdx.x;
    size_t str = (size_t)gridDim.x * blockDim.x;
    size_t nv  = (size_t)SEQ_ * NV_;
    size_t nh  = (size_t)SEQ_ * NH_;
    double d5 = 0, d6 = 0, d7 = 0;
    for (size_t i = i0; i < nv; i += str) {
        float b = bvt[i];
        d5 += (double)(v[i]  * b);
        d6 += (double)(vs[i] * b);
    }
    for (size_t i = i0; i < nh; i += str)
        d7 += (double)((h1[i] - h1s[i]) * bh1t[i]);

    __shared__ double s5[256], s6[256], s7[256];
    int t = threadIdx.x;
    s5[t] = d5; s6[t] = d6; s7[t] = d7;
    __syncthreads();
    for (int s = 128; s > 0; s >>= 1) {
        if (t < s) { s5[t] += s5[t+s]; s6[t] += s6[t+s]; s7[t] += s7[t+s]; }
        __syncthreads();
    }
    if (t == 0) {
        atomicAdd(&red[5], s5[0]);
        atomicAdd(&red[6], s6[0]);
        atomicAdd(&red[7], s7[0]);
    }
}

__global__ void k_final(const double* __restrict__ red, float* __restrict__ out)
{
    double cost1 = (-red[5] - red[0] + red[6] + red[1]) / (double)SEQ_;
    double cost2 = (-red[7] - red[2] + red[3]) / (double)SEQ_;
    out[0] = (float)(cost1 + cost2);
    out[1] = (float)(red[4] / (double)SEQ_);
}

// ---------------------------------------------------------------------------
// host
// ---------------------------------------------------------------------------
static inline void launch_gemm(cudaStream_t st,
                               const float* A, int shiftA, const float* B,
                               int K, int N,
                               const float* bvec, const float* barr,
                               float* outC, float* out2, int mode,
                               int red_mode, int slot, const float* vmon,
                               uint32_t kk0, uint32_t kk1, double* acc)
{
    dim3 grid(N / BN, SEQ_ / BM), blk(256);
    uint32_t half = (uint32_t)(((size_t)SEQ_ * (size_t)N) / 2);
    gemm_ep<<<grid, blk, GEMM_SMEM, st>>>(A, shiftA, B, K, N, bvec, barr, outC, out2,
                                          mode, red_mode, slot, vmon, kk0, kk1, half, acc);
}

extern "C" void kernel_launch(void* const* d_in, const int* in_sizes, int n_in,
                              void* d_out, int out_size)
{
    const float* v_seq = (const float*)d_in[0];
    const float* W1    = (const float*)d_in[1];
    const float* bv    = (const float*)d_in[2];
    const float* bh1   = (const float*)d_in[3];
    const float* W2    = (const float*)d_in[4];
    const float* bh2   = (const float*)d_in[5];
    const float* Wyv   = (const float*)d_in[6];
    const float* Wyh1  = (const float*)d_in[7];
    const float* Wyh2  = (const float*)d_in[8];
    const float* Wvu   = (const float*)d_in[9];
    const float* Wuu   = (const float*)d_in[10];
    const float* bu    = (const float*)d_in[11];
    float* out = (float*)d_out;

    // one-time setup of second stream + fork/join events (host objects only)
    static cudaStream_t s2 = nullptr;
    static cudaEvent_t evFork, evBvt, evH1, evD;
    if (!s2) {
        cudaStreamCreateWithFlags(&s2, cudaStreamNonBlocking);
        cudaEventCreateWithFlags(&evFork, cudaEventDisableTiming);
        cudaEventCreateWithFlags(&evBvt,  cudaEventDisableTiming);
        cudaEventCreateWithFlags(&evH1,   cudaEventDisableTiming);
        cudaEventCreateWithFlags(&evD,    cudaEventDisableTiming);
        cudaFuncSetAttribute(gemm_ep, cudaFuncAttributeMaxDynamicSharedMemorySize, GEMM_SMEM);
    }
    cudaStream_t s0 = 0;

    float *X, *Ua, *Ub, *bvt, *bh1t, *bh2t, *h, *h1, *h2, *h1s, *vs;
    float *W1t, *W1r, *W2t, *W2r, *Wuut, *Wvut, *Wyvr, *Wyh1r, *Wyh2r;
    double* acc;
    cudaGetSymbolAddress((void**)&X,    g_X);
    cudaGetSymbolAddress((void**)&Ua,   g_Ua);
    cudaGetSymbolAddress((void**)&Ub,   g_Ub);
    cudaGetSymbolAddress((void**)&bvt,  g_bvt);
    cudaGetSymbolAddress((void**)&bh1t, g_bh1t);
    cudaGetSymbolAddress((void**)&bh2t, g_bh2t);
    cudaGetSymbolAddress((void**)&h,    g_h);
    cudaGetSymbolAddress((void**)&h1,   g_h1);
    cudaGetSymbolAddress((void**)&h2,   g_h2);
    cudaGetSymbolAddress((void**)&h1s,  g_h1s);
    cudaGetSymbolAddress((void**)&vs,   g_vs);
    cudaGetSymbolAddress((void**)&W1t,  g_W1t);
    cudaGetSymbolAddress((void**)&W1r,  g_W1r);
    cudaGetSymbolAddress((void**)&W2t,  g_W2t);
    cudaGetSymbolAddress((void**)&W2r,  g_W2r);
    cudaGetSymbolAddress((void**)&Wuut, g_Wuut);
    cudaGetSymbolAddress((void**)&Wvut, g_Wvut);
    cudaGetSymbolAddress((void**)&Wyvr, g_Wyvr);
    cudaGetSymbolAddress((void**)&Wyh1r,g_Wyh1r);
    cudaGetSymbolAddress((void**)&Wyh2r,g_Wyh2r);
    cudaGetSymbolAddress((void**)&acc,  g_acc);

    // ---- JAX key schedule: key(42) -> 10x split(key,3) ----
    uint32_t kk0 = 0u, kk1 = 42u;
    uint32_t K1[10][2], K2[10][2];
    for (int i = 0; i < 10; i++) {
#if JAX_PARTITIONABLE
        uint32_t n0, n1, a0, a1, b0, b1;
        tf2x32(kk0, kk1, 0u, 0u, &n0, &n1);
        tf2x32(kk0, kk1, 0u, 1u, &a0, &a1);
        tf2x32(kk0, kk1, 0u, 2u, &b0, &b1);
        K1[i][0] = a0; K1[i][1] = a1;
        K2[i][0] = b0; K2[i][1] = b1;
        kk0 = n0; kk1 = n1;
#else
        uint32_t o00, o01, o10, o11, o20, o21;
        tf2x32(kk0, kk1, 0u, 3u, &o00, &o01);
        tf2x32(kk0, kk1, 1u, 4u, &o10, &o11);
        tf2x32(kk0, kk1, 2u, 5u, &o20, &o21);
        K1[i][0] = o20; K1[i][1] = o01;
        K2[i][0] = o11; K2[i][1] = o21;
        kk0 = o00; kk1 = o10;
#endif
    }

    // ===== fork: s2 joins the capture graph =====
    cudaEventRecord(evFork, s0);
    cudaStreamWaitEvent(s2, evFork, 0);

    // ---- prep (split across streams) ----
    dim3 trb(32, 8);
    k_init<<<1, 32, 0, s0>>>();
    k_tr<<<dim3(NR_/32, NV_/32), trb, 0, s0>>>(Wvu, Wvut, NV_, NR_);
    k_tr<<<dim3(NR_/32, NR_/32), trb, 0, s0>>>(Wuu, Wuut, NR_, NR_);
    k_tr<<<dim3(NH_/32, NV_/32), trb, 0, s0>>>(W1,  W1t,  NV_, NH_);
    k_round<<<(NV_*NH_+255)/256, 256, 0, s0>>>(W1,   W1r,   NV_*NH_);
    k_round<<<(NV_*NR_+255)/256, 256, 0, s0>>>(Wyv,  Wyvr,  NV_*NR_);
    k_round<<<(NH_*NR_+255)/256, 256, 0, s0>>>(Wyh1, Wyh1r, NH_*NR_);
    k_tr<<<dim3(NH_/32, NH_/32), trb, 0, s2>>>(W2,  W2t,  NH_, NH_);
    k_round<<<(NH_*NH_+255)/256, 256, 0, s2>>>(W2,   W2r,   NH_*NH_);
    k_round<<<(NH_*NR_+255)/256, 256, 0, s2>>>(Wyh2, Wyh2r, NH_*NR_);

    // ---- s0: X = v_seq @ Wvu + bu; Jacobi; bh1t ----
    launch_gemm(s0, v_seq, 0, Wvut, NV_, NR_, bu, nullptr, X, nullptr, 0, 0, 0, nullptr, 0, 0, acc);
    k_tanhx<<<1024, 256, 0, s0>>>();
    for (int s = 1; s < NSWEEP; s++) {
        float* in    = (s % 2 == 1) ? Ub : Ua;
        float* out_u = (s % 2 == 1) ? Ua : Ub;
        launch_gemm(s0, in, 1, Wuut, NR_, NR_, nullptr, X, out_u, nullptr, 1, 0, 0, nullptr, 0, 0, acc);
    }
    // NSWEEP=6 -> final U in Ua
    launch_gemm(s0, Ua, 1, Wyh1r, NR_, NH_, bh1, nullptr, bh1t, nullptr, 0, 0, 0, nullptr, 0, 0, acc);
    cudaEventRecord(evFork, s0);               // "Ua ready"
    cudaStreamWaitEvent(s2, evFork, 0);

    // ---- s2: bvt, bh2t (concurrent with s0's RBM1 iter-0) ----
    launch_gemm(s2, Ua, 1, Wyvr,  NR_, NV_, bv,  nullptr, bvt,  nullptr, 0, 0, 0, nullptr, 0, 0, acc);
    cudaEventRecord(evBvt, s2);
    launch_gemm(s2, Ua, 1, Wyh2r, NR_, NH_, bh2, nullptr, bh2t, nullptr, 0, 0, 0, nullptr, 0, 0, acc);

    // ---- s0: RBM1 iter 0 (yields h, h1, FE1(v_seq) sp-sum) ----
    launch_gemm(s0, v_seq, 0, W1t, NV_, NH_, nullptr, bh1t, h, h1, 2, 1, 0, nullptr,
                K1[0][0], K1[0][1], acc);
    cudaEventRecord(evH1, s0);

    // ---- s2: RBM2 CD-5 chain (needs h1, bh2t, bh1t) ----
    cudaStreamWaitEvent(s2, evH1, 0);
    launch_gemm(s2, h1, 0, W2t, NH_, NH_, nullptr, bh2t, h2, nullptr, 2, 1, 2, nullptr,
                K1[5][0], K1[5][1], acc);
    launch_gemm(s2, h2, 0, W2r, NH_, NH_, nullptr, bh1t, h1s, nullptr, 2, 0, 0, nullptr,
                K2[5][0], K2[5][1], acc);
    for (int i = 6; i < 10; i++) {
        launch_gemm(s2, h1s, 0, W2t, NH_, NH_, nullptr, bh2t, h2, nullptr, 2, 0, 0, nullptr,
                    K1[i][0], K1[i][1], acc);
        launch_gemm(s2, h2, 0, W2r, NH_, NH_, nullptr, bh1t, h1s, nullptr, 2, 0, 0, nullptr,
                    K2[i][0], K2[i][1], acc);
    }
    launch_gemm(s2, h1s, 0, W2t, NH_, NH_, nullptr, bh2t, nullptr, nullptr, 0, 1, 3, nullptr,
                0, 0, acc);
    cudaEventRecord(evD, s2);

    // ---- s0: RBM1 chain (needs bvt from s2) ----
    cudaStreamWaitEvent(s0, evBvt, 0);
    launch_gemm(s0, h, 0, W1r, NH_, NV_, nullptr, bvt, vs, nullptr, 2, 0, 0, nullptr,
                K2[0][0], K2[0][1], acc);
    for (int i = 1; i < CDK_ - 1; i++) {
        launch_gemm(s0, vs, 0, W1t, NV_, NH_, nullptr, bh1t, h, nullptr, 2, 0, 0, nullptr,
                    K1[i][0], K1[i][1], acc);
        launch_gemm(s0, h, 0, W1r, NH_, NV_, nullptr, bvt, vs, nullptr, 2, 0, 0, nullptr,
                    K2[i][0], K2[i][1], acc);
    }
    launch_gemm(s0, vs, 0, W1t, NV_, NH_, nullptr, bh1t, h, nullptr, 2, 0, 0, nullptr,
                K1[CDK_-1][0], K1[CDK_-1][1], acc);
    launch_gemm(s0, h, 0, W1r, NH_, NV_, nullptr, bvt, vs, nullptr, 2, 2, 4, v_seq,
                K2[CDK_-1][0], K2[CDK_-1][1], acc);
    launch_gemm(s0, vs, 0, W1t, NV_, NH_, nullptr, bh1t, nullptr, nullptr, 0, 1, 1, nullptr,
                0, 0, acc);

    // ===== join: s0 waits for s2's chain, then reduce/finalize =====
    cudaStreamWaitEvent(s0, evD, 0);
    k_dots<<<2048, 256, 0, s0>>>(v_seq, bvt, vs, h1, h1s, bh1t, acc);
    k_final<<<1, 1, 0, s0>>>(acc, out);
}

// round 16
// speedup vs baseline: 4.4689x; 1.1675x over previous
#include <cuda_runtime.h>
#include <cuda_fp16.h>
#include <stdint.h>
#include <math.h>

#define SEQ_   32768
#define NV_    256
#define NH_    512
#define NR_    256
#define CDK_   5
#define NSWEEP 6

// JAX >= 0.5 default: jax_threefry_partitionable = True
#define JAX_PARTITIONABLE 1

// ---------------------------------------------------------------------------
// Scratch (device globals; allocation-free per harness rules)
// ---------------------------------------------------------------------------
__device__ float  g_X   [(size_t)SEQ_ * NR_];
__device__ __half g_Ua  [(size_t)SEQ_ * NR_];
__device__ __half g_Ub  [(size_t)SEQ_ * NR_];
__device__ float  g_bvt [(size_t)SEQ_ * NV_];
__device__ float  g_bh1t[(size_t)SEQ_ * NH_];
__device__ float  g_bh2t[(size_t)SEQ_ * NH_];
__device__ __half g_h   [(size_t)SEQ_ * NH_];
__device__ __half g_h1  [(size_t)SEQ_ * NH_];
__device__ __half g_h2  [(size_t)SEQ_ * NH_];
__device__ __half g_h1s [(size_t)SEQ_ * NH_];
__device__ __half g_vs  [(size_t)SEQ_ * NV_];
__device__ __half g_v16 [(size_t)SEQ_ * NV_];   // fp16 copy of v_seq (binary, exact)
// fp16 weight copies (all in [N,K] layout for the GEMM's B operand)
__device__ __half g_W1t [(size_t)NH_ * NV_];   // W1^T  [NH,NV]
__device__ __half g_W1r [(size_t)NV_ * NH_];   // W1    [NV,NH]
__device__ __half g_W2t [(size_t)NH_ * NH_];   // W2^T
__device__ __half g_W2r [(size_t)NH_ * NH_];   // W2
__device__ __half g_Wuut[(size_t)NR_ * NR_];   // Wuu^T
__device__ __half g_Wvut[(size_t)NR_ * NV_];   // Wvu^T
__device__ __half g_Wyvr [(size_t)NV_ * NR_];
__device__ __half g_Wyh1r[(size_t)NH_ * NR_];
__device__ __half g_Wyh2r[(size_t)NH_ * NR_];
// 0: sum sp(v_seq)   1: sum sp(v_sample)  2: sum sp(h1)  3: sum sp(h1_sample)
// 4: monitor sum     5: sum v_seq.bvt     6: sum vs.bvt  7: sum (h1-h1s).bh1t
__device__ double g_acc[8];

// ---------------------------------------------------------------------------
// Threefry-2x32 (20 rounds) — exactly JAX's cipher
// ---------------------------------------------------------------------------
__host__ __device__ __forceinline__
void tf2x32(uint32_t k0, uint32_t k1, uint32_t x0, uint32_t x1,
            uint32_t* o0, uint32_t* o1)
{
    uint32_t ks2 = k0 ^ k1 ^ 0x1BD11BDAu;
    x0 += k0; x1 += k1;
#define TF_RND(R) { x0 += x1; x1 = (x1 << (R)) | (x1 >> (32 - (R))); x1 ^= x0; }
    TF_RND(13) TF_RND(15) TF_RND(26) TF_RND(6)
    x0 += k1;  x1 += ks2 + 1u;
    TF_RND(17) TF_RND(29) TF_RND(16) TF_RND(24)
    x0 += ks2; x1 += k0 + 2u;
    TF_RND(13) TF_RND(15) TF_RND(26) TF_RND(6)
    x0 += k0;  x1 += k1 + 3u;
    TF_RND(17) TF_RND(29) TF_RND(16) TF_RND(24)
    x0 += k1;  x1 += ks2 + 4u;
    TF_RND(13) TF_RND(15) TF_RND(26) TF_RND(6)
    x0 += ks2; x1 += k0 + 5u;
#undef TF_RND
    *o0 = x0; *o1 = x1;
}

__device__ __forceinline__
float jx_uniform(uint32_t k0, uint32_t k1, uint32_t idx, uint32_t half)
{
    uint32_t bits;
#if JAX_PARTITIONABLE
    uint32_t o0, o1;
    tf2x32(k0, k1, 0u, idx, &o0, &o1);
    bits = o0 ^ o1;
#else
    uint32_t o0, o1;
    if (idx < half) { tf2x32(k0, k1, idx, idx + half, &o0, &o1); bits = o0; }
    else            { tf2x32(k0, k1, idx - half, idx, &o0, &o1); bits = o1; }
#endif
    return __uint_as_float((bits >> 9) | 0x3f800000u) - 1.0f;
}

__device__ __forceinline__ uint32_t smem_u32(const void* p)
{
    uint32_t a;
    asm("{ .reg .u64 t; cvta.to.shared.u64 t, %1; cvt.u32.u64 %0, t; }"
        : "=r"(a) : "l"(p));
    return a;
}

__device__ __forceinline__ void cp16(uint32_t dst, const void* src, bool pred)
{
    int sz = pred ? 16 : 0;
    asm volatile("cp.async.cg.shared.global [%0], [%1], 16, %2;"
                 :: "r"(dst), "l"(src), "r"(sz));
}
template<int NWAIT>
__device__ __forceinline__ void cp_wait()
{
    asm volatile("cp.async.wait_group %0;" :: "n"(NWAIT) : "memory");
}
__device__ __forceinline__ void cp_commit()
{
    asm volatile("cp.async.commit_group;" ::: "memory");
}
__device__ __forceinline__ void ldsm_x4(uint32_t& r0, uint32_t& r1,
                                        uint32_t& r2, uint32_t& r3, uint32_t addr)
{
    asm volatile("ldmatrix.sync.aligned.m8n8.x4.shared.b16 {%0,%1,%2,%3}, [%4];"
                 : "=r"(r0), "=r"(r1), "=r"(r2), "=r"(r3) : "r"(addr));
}

// ---------------------------------------------------------------------------
// prep kernels
// ---------------------------------------------------------------------------
__global__ void k_init()
{
    int i = blockIdx.x * blockDim.x + threadIdx.x;
    if (i < 8) g_acc[i] = 0.0;
}

// out[i] = half(in[i])
__global__ void k_f2h(const float* __restrict__ in, __half* __restrict__ out, int n)
{
    int i = blockIdx.x * blockDim.x + threadIdx.x;
    if (i < n) out[i] = __float2half_rn(in[i]);
}

// out[C,R] = half(in[R,C]^T)
__global__ void k_tr(const float* __restrict__ in, __half* __restrict__ out, int R, int C)
{
    __shared__ float t[32][33];
    int bx = blockIdx.x * 32, by = blockIdx.y * 32;
#pragma unroll
    for (int dy = 0; dy < 32; dy += 8)
        t[threadIdx.y + dy][threadIdx.x] = in[(size_t)(by + threadIdx.y + dy) * C + bx + threadIdx.x];
    __syncthreads();
#pragma unroll
    for (int dy = 0; dy < 32; dy += 8)
        out[(size_t)(bx + threadIdx.y + dy) * R + by + threadIdx.x] =
            __float2half_rn(t[threadIdx.x][threadIdx.y + dy]);
}

// Ub = half(tanh(X))   (first Jacobi application with U=0)
__global__ void k_tanhx()
{
    size_t i   = (size_t)blockIdx.x * blockDim.x + threadIdx.x;
    size_t tot = (size_t)SEQ_ * NR_;
    size_t str = (size_t)gridDim.x * blockDim.x;
    for (size_t j = i; j < tot; j += str) g_Ub[j] = __float2half_rn(tanhf(g_X[j]));
}

// ---------------------------------------------------------------------------
// Fused fp16 tensor-core GEMM — 128x64x64 block tile, 3 CTAs/SM.
//   C[S,N] = A[S,K] @ B^T, A/B fp16, B given as [N,K] row-major.
//   8 warps (4 M x 2 N), warp tile 32x32 (mma.m16n8k16.f16, fp32 accum).
//   Smem: row-major [r][k], rows = 128B = 8x16B chunks, swizzle ch^(r&7).
//   3 stages, 72KB total. Byte layout identical to the proven tf32 kernel.
//   shiftA: row t of A reads source row t-1 (row 0 -> zeros, cp.async zfill)
//   mode  : 0=linear(fp32 out)  1=tanh(fp16 out)  2=bernoulli sample(fp16)
//   red   : 0=none  1=sum softplus(z)  2=sum monitor(vmon, p)  -> red[slot]
// ---------------------------------------------------------------------------
#define BM 128
#define BN 64
#define BK 64                                   // fp16 elements; 128 bytes/row
#define ROWB 128
#define STAGE_A (BM * ROWB)                     // 16384
#define STAGE_B (BN * ROWB)                     // 8192
#define GEMM_SMEM (3 * (STAGE_A + STAGE_B))     // 73728

__global__ void __launch_bounds__(256, 3)
gemm_ep(const __half* __restrict__ A, int shiftA,
        const __half* __restrict__ Bm, int K, int N,
        const float* __restrict__ bias_vec,
        const float* __restrict__ bias_arr,
        float* __restrict__ outF, __half* __restrict__ outH,
        __half* __restrict__ out2,
        int mode, int red_mode, int slot,
        const float* __restrict__ vmon,
        uint32_t rk0, uint32_t rk1, uint32_t half,
        double* __restrict__ red)
{
    extern __shared__ char dsm[];
    const uint32_t sA0 = smem_u32(dsm);
    const uint32_t sB0 = sA0 + 3u * STAGE_A;

    const int tid  = threadIdx.x;
    const int lane = tid & 31;
    const int wid  = tid >> 5;
    const int warpM = wid & 3;            // 0..3  (x32 rows)
    const int warpN = wid >> 2;           // 0..1  (x32 cols)
    const int qr = lane >> 2;
    const int qc = lane & 3;
    const int rowBase = blockIdx.y * BM;
    const int colBase = blockIdx.x * BN;
    const int mBase = warpM * 32;
    const int nBase = warpN * 32;

    // ---- compact loader state: ch = 16B chunk (8 halves), rr = row group ----
    const int ch = tid & 7;
    const int rr = tid >> 3;              // 0..31
    const size_t kStride = (size_t)32 * K;          // rows 32 apart (halves)
    const __half* aBase = A + (size_t)(rowBase + rr - shiftA) * K + ch * 8;
    const __half* bBase = Bm + (size_t)(colBase + rr) * K + ch * 8;
    const uint32_t dOff = (uint32_t)rr * ROWB + ((uint32_t)(ch ^ (rr & 7)) << 4);
    const int aRow0 = rowBase + rr - shiftA;

    // ---- hoisted ldmatrix fragment addresses (stage-0, kk=0) ----
    // A: lanes0-7 r0-7/c0, 8-15 r8-15/c0, 16-23 r0-7/c1, 24-31 r8-15/c1
    //    -> {a0,a1,a2,a3} of mma.m16n8k16
    // B: lanes0-7 n0-7/c0, 8-15 n0-7/c1, 16-23 n8-15/c0, 24-31 n8-15/c1
    //    -> {b0(nt0),b1(nt0),b0(nt1),b1(nt1)}
    uint32_t pA[2], pB[2];
    {
        const int hi = lane >> 4;
#pragma unroll
        for (int mt = 0; mt < 2; mt++) {
            int row = mBase + mt * 16 + (lane & 15);
            pA[mt] = (sA0 + (uint32_t)row * ROWB)
                     ^ ((uint32_t)(row & 7) << 4) ^ ((uint32_t)hi << 4);
        }
        const int bsel = (lane >> 3) & 1;
#pragma unroll
        for (int pr = 0; pr < 2; pr++) {
            int n = nBase + pr * 16 + (lane & 7) + (hi << 3);
            pB[pr] = (sB0 + (uint32_t)n * ROWB)
                     ^ ((uint32_t)(n & 7) << 4) ^ ((uint32_t)bsel << 4);
        }
    }

    float c[2][4][4];
#pragma unroll
    for (int mt = 0; mt < 2; mt++)
#pragma unroll
        for (int nt = 0; nt < 4; nt++)
#pragma unroll
            for (int e = 0; e < 4; e++) c[mt][nt][e] = 0.0f;

    auto load_tile = [&](int st, int kc) {   // kc in halves
        const uint32_t aD = sA0 + (uint32_t)st * STAGE_A + dOff;
        const uint32_t bD = sB0 + (uint32_t)st * STAGE_B + dOff;
#pragma unroll
        for (int p = 0; p < 4; p++)
            cp16(aD + (uint32_t)p * 32 * ROWB, aBase + p * kStride + kc,
                 (aRow0 + 32 * p) >= 0);
#pragma unroll
        for (int p = 0; p < 2; p++)
            cp16(bD + (uint32_t)p * 32 * ROWB, bBase + p * kStride + kc, true);
    };

    const int T = K / BK;
    load_tile(0, 0);               cp_commit();
    if (T > 1) { load_tile(1, BK); cp_commit(); }

    for (int t = 0; t < T; t++) {
        if (t + 1 < T) cp_wait<1>(); else cp_wait<0>();
        __syncthreads();
        if (t + 2 < T) { load_tile((t + 2) % 3, (t + 2) * BK); cp_commit(); }

        const uint32_t soA = (uint32_t)(t % 3) * STAGE_A;
        const uint32_t soB = (uint32_t)(t % 3) * STAGE_B;

        // A-fragment double buffer: prefetch kk=0 (k16 steps, 4 per tile)
        uint32_t af[2][2][4];
#pragma unroll
        for (int mt = 0; mt < 2; mt++)
            ldsm_x4(af[0][mt][0], af[0][mt][1], af[0][mt][2], af[0][mt][3],
                    pA[mt] + soA);

#pragma unroll
        for (int kk = 0; kk < 4; kk++) {
            const int cur = kk & 1;
            if (kk < 3) {
#pragma unroll
                for (int mt = 0; mt < 2; mt++)
                    ldsm_x4(af[cur ^ 1][mt][0], af[cur ^ 1][mt][1],
                            af[cur ^ 1][mt][2], af[cur ^ 1][mt][3],
                            (pA[mt] + soA) ^ ((uint32_t)(kk + 1) << 5));
            }
            uint32_t bf[2][4];
#pragma unroll
            for (int pr = 0; pr < 2; pr++)
                ldsm_x4(bf[pr][0], bf[pr][1], bf[pr][2], bf[pr][3],
                        (pB[pr] + soB) ^ ((uint32_t)kk << 5));
#pragma unroll
            for (int mt = 0; mt < 2; mt++)
#pragma unroll
                for (int nt = 0; nt < 4; nt++) {
                    uint32_t b0 = bf[nt >> 1][(nt & 1) * 2];
                    uint32_t b1 = bf[nt >> 1][(nt & 1) * 2 + 1];
                    asm volatile(
                        "mma.sync.aligned.m16n8k16.row.col.f32.f16.f16.f32 "
                        "{%0,%1,%2,%3}, {%4,%5,%6,%7}, {%8,%9}, {%0,%1,%2,%3};"
                        : "+f"(c[mt][nt][0]), "+f"(c[mt][nt][1]),
                          "+f"(c[mt][nt][2]), "+f"(c[mt][nt][3])
                        : "r"(af[cur][mt][0]), "r"(af[cur][mt][1]),
                          "r"(af[cur][mt][2]), "r"(af[cur][mt][3]),
                          "r"(b0), "r"(b1));
                }
        }
    }

    // ---- epilogue (fragment layout: e0:(qr,2qc) e1:(qr,2qc+1) e2:+8row e3) ----
    double local = 0.0;
#pragma unroll
    for (int mt = 0; mt < 2; mt++) {
#pragma unroll
        for (int nt = 0; nt < 4; nt++) {
#pragma unroll
            for (int e = 0; e < 4; e++) {
                int r  = rowBase + mBase + mt * 16 + qr + ((e >> 1) << 3);
                int nn = colBase + nBase + nt * 8 + (qc << 1) + (e & 1);
                size_t off = (size_t)r * N + nn;
                float z = c[mt][nt][e];
                if (bias_vec) z += bias_vec[nn];
                if (bias_arr) z += bias_arr[off];

                if (red_mode == 1) {
                    local += (double)(fmaxf(z, 0.f) + log1pf(expf(-fabsf(z))));
                }

                if (mode == 0) {
                    if (outF) outF[off] = z;
                } else if (mode == 1) {
                    outH[off] = __float2half_rn(tanhf(z));
                } else {
                    float p = 1.f / (1.f + expf(-z));
                    float u = jx_uniform(rk0, rk1, (uint32_t)off, half);
                    outH[off] = __float2half_rn((u < p) ? 1.f : 0.f);
                    if (out2) out2[off] = __float2half_rn(p);
                    if (red_mode == 2) {
                        float v = vmon[off];
                        local += (double)(v * logf(p + 1e-10f)
                                          + (1.f - v) * logf(1.f - p + 1e-10f));
                    }
                }
            }
        }
    }

    if (red_mode) {
        __shared__ double rs[256];
        rs[tid] = local;
        __syncthreads();
        for (int s = 128; s > 0; s >>= 1) {
            if (tid < s) rs[tid] += rs[tid + s];
            __syncthreads();
        }
        if (tid == 0) atomicAdd(&red[slot], rs[0]);
    }
}

// ---------------------------------------------------------------------------
// dot-product reductions for the free-energy bias terms
// ---------------------------------------------------------------------------
__global__ void __launch_bounds__(256)
k_dots(const float* __restrict__ v,    const float* __restrict__ bvt,
       const __half* __restrict__ vs,  const __half* __restrict__ h1,
       const __half* __restrict__ h1s, const float* __restrict__ bh1t,
       double* __restrict__ red)
{
    size_t i0  = (size_t)blockIdx.x * blockDim.x + threadIdx.x;
    size_t str = (size_t)gridDim.x * blockDim.x;
    size_t nv  = (size_t)SEQ_ * NV_;
    size_t nh  = (size_t)SEQ_ * NH_;
    double d5 = 0, d6 = 0, d7 = 0;
    for (size_t i = i0; i < nv; i += str) {
        float b = bvt[i];
        d5 += (double)(v[i] * b);
        d6 += (double)(__half2float(vs[i]) * b);
    }
    for (size_t i = i0; i < nh; i += str)
        d7 += (double)((__half2float(h1[i]) - __half2float(h1s[i])) * bh1t[i]);

    __shared__ double s5[256], s6[256], s7[256];
    int t = threadIdx.x;
    s5[t] = d5; s6[t] = d6; s7[t] = d7;
    __syncthreads();
    for (int s = 128; s > 0; s >>= 1) {
        if (t < s) { s5[t] += s5[t+s]; s6[t] += s6[t+s]; s7[t] += s7[t+s]; }
        __syncthreads();
    }
    if (t == 0) {
        atomicAdd(&red[5], s5[0]);
        atomicAdd(&red[6], s6[0]);
        atomicAdd(&red[7], s7[0]);
    }
}

__global__ void k_final(const double* __restrict__ red, float* __restrict__ out)
{
    double cost1 = (-red[5] - red[0] + red[6] + red[1]) / (double)SEQ_;
    double cost2 = (-red[7] - red[2] + red[3]) / (double)SEQ_;
    out[0] = (float)(cost1 + cost2);
    out[1] = (float)(red[4] / (double)SEQ_);
}

// ---------------------------------------------------------------------------
// host
// ---------------------------------------------------------------------------
static inline void launch_gemm(cudaStream_t st,
                               const __half* A, int shiftA, const __half* B,
                               int K, int N,
                               const float* bvec, const float* barr,
                               float* outF, __half* outH, __half* out2, int mode,
                               int red_mode, int slot, const float* vmon,
                               uint32_t kk0, uint32_t kk1, double* acc)
{
    dim3 grid(N / BN, SEQ_ / BM), blk(256);
    uint32_t half = (uint32_t)(((size_t)SEQ_ * (size_t)N) / 2);
    gemm_ep<<<grid, blk, GEMM_SMEM, st>>>(A, shiftA, B, K, N, bvec, barr,
                                          outF, outH, out2,
                                          mode, red_mode, slot, vmon,
                                          kk0, kk1, half, acc);
}

extern "C" void kernel_launch(void* const* d_in, const int* in_sizes, int n_in,
                              void* d_out, int out_size)
{
    const float* v_seq = (const float*)d_in[0];
    const float* W1    = (const float*)d_in[1];
    const float* bv    = (const float*)d_in[2];
    const float* bh1   = (const float*)d_in[3];
    const float* W2    = (const float*)d_in[4];
    const float* bh2   = (const float*)d_in[5];
    const float* Wyv   = (const float*)d_in[6];
    const float* Wyh1  = (const float*)d_in[7];
    const float* Wyh2  = (const float*)d_in[8];
    const float* Wvu   = (const float*)d_in[9];
    const float* Wuu   = (const float*)d_in[10];
    const float* bu    = (const float*)d_in[11];
    float* out = (float*)d_out;

    // one-time setup of second stream + fork/join events (host objects only)
    static cudaStream_t s2 = nullptr;
    static cudaEvent_t evFork, evBvt, evH1, evD;
    if (!s2) {
        cudaStreamCreateWithFlags(&s2, cudaStreamNonBlocking);
        cudaEventCreateWithFlags(&evFork, cudaEventDisableTiming);
        cudaEventCreateWithFlags(&evBvt,  cudaEventDisableTiming);
        cudaEventCreateWithFlags(&evH1,   cudaEventDisableTiming);
        cudaEventCreateWithFlags(&evD,    cudaEventDisableTiming);
        cudaFuncSetAttribute(gemm_ep, cudaFuncAttributeMaxDynamicSharedMemorySize, GEMM_SMEM);
    }
    cudaStream_t s0 = 0;

    float *X, *bvt, *bh1t, *bh2t;
    __half *Ua, *Ub, *h, *h1, *h2, *h1s, *vs, *v16;
    __half *W1t, *W1r, *W2t, *W2r, *Wuut, *Wvut, *Wyvr, *Wyh1r, *Wyh2r;
    double* acc;
    cudaGetSymbolAddress((void**)&X,    g_X);
    cudaGetSymbolAddress((void**)&Ua,   g_Ua);
    cudaGetSymbolAddress((void**)&Ub,   g_Ub);
    cudaGetSymbolAddress((void**)&bvt,  g_bvt);
    cudaGetSymbolAddress((void**)&bh1t, g_bh1t);
    cudaGetSymbolAddress((void**)&bh2t, g_bh2t);
    cudaGetSymbolAddress((void**)&h,    g_h);
    cudaGetSymbolAddress((void**)&h1,   g_h1);
    cudaGetSymbolAddress((void**)&h2,   g_h2);
    cudaGetSymbolAddress((void**)&h1s,  g_h1s);
    cudaGetSymbolAddress((void**)&vs,   g_vs);
    cudaGetSymbolAddress((void**)&v16,  g_v16);
    cudaGetSymbolAddress((void**)&W1t,  g_W1t);
    cudaGetSymbolAddress((void**)&W1r,  g_W1r);
    cudaGetSymbolAddress((void**)&W2t,  g_W2t);
    cudaGetSymbolAddress((void**)&W2r,  g_W2r);
    cudaGetSymbolAddress((void**)&Wuut, g_Wuut);
    cudaGetSymbolAddress((void**)&Wvut, g_Wvut);
    cudaGetSymbolAddress((void**)&Wyvr, g_Wyvr);
    cudaGetSymbolAddress((void**)&Wyh1r,g_Wyh1r);
    cudaGetSymbolAddress((void**)&Wyh2r,g_Wyh2r);
    cudaGetSymbolAddress((void**)&acc,  g_acc);

    // ---- JAX key schedule: key(42) -> 10x split(key,3) ----
    uint32_t kk0 = 0u, kk1 = 42u;
    uint32_t K1[10][2], K2[10][2];
    for (int i = 0; i < 10; i++) {
#if JAX_PARTITIONABLE
        uint32_t n0, n1, a0, a1, b0, b1;
        tf2x32(kk0, kk1, 0u, 0u, &n0, &n1);
        tf2x32(kk0, kk1, 0u, 1u, &a0, &a1);
        tf2x32(kk0, kk1, 0u, 2u, &b0, &b1);
        K1[i][0] = a0; K1[i][1] = a1;
        K2[i][0] = b0; K2[i][1] = b1;
        kk0 = n0; kk1 = n1;
#else
        uint32_t o00, o01, o10, o11, o20, o21;
        tf2x32(kk0, kk1, 0u, 3u, &o00, &o01);
        tf2x32(kk0, kk1, 1u, 4u, &o10, &o11);
        tf2x32(kk0, kk1, 2u, 5u, &o20, &o21);
        K1[i][0] = o20; K1[i][1] = o01;
        K2[i][0] = o11; K2[i][1] = o21;
        kk0 = o00; kk1 = o10;
#endif
    }

    // ===== fork: s2 joins the capture graph =====
    cudaEventRecord(evFork, s0);
    cudaStreamWaitEvent(s2, evFork, 0);

    // ---- prep (split across streams) ----
    dim3 trb(32, 8);
    k_init<<<1, 32, 0, s0>>>();
    k_tr<<<dim3(NR_/32, NV_/32), trb, 0, s0>>>(Wvu, Wvut, NV_, NR_);
    k_tr<<<dim3(NR_/32, NR_/32), trb, 0, s0>>>(Wuu, Wuut, NR_, NR_);
    k_tr<<<dim3(NH_/32, NV_/32), trb, 0, s0>>>(W1,  W1t,  NV_, NH_);
    k_f2h<<<(NV_*NH_+255)/256, 256, 0, s0>>>(W1,   W1r,   NV_*NH_);
    k_f2h<<<(NV_*NR_+255)/256, 256, 0, s0>>>(Wyv,  Wyvr,  NV_*NR_);
    k_f2h<<<(NH_*NR_+255)/256, 256, 0, s0>>>(Wyh1, Wyh1r, NH_*NR_);
    k_f2h<<<(SEQ_*NV_+255)/256, 256, 0, s0>>>(v_seq, v16, SEQ_*NV_);
    k_tr<<<dim3(NH_/32, NH_/32), trb, 0, s2>>>(W2,  W2t,  NH_, NH_);
    k_f2h<<<(NH_*NH_+255)/256, 256, 0, s2>>>(W2,   W2r,   NH_*NH_);
    k_f2h<<<(NH_*NR_+255)/256, 256, 0, s2>>>(Wyh2, Wyh2r, NH_*NR_);

    // ---- s0: X = v_seq @ Wvu + bu; Jacobi; bh1t ----
    launch_gemm(s0, v16, 0, Wvut, NV_, NR_, bu, nullptr, X, nullptr, nullptr, 0, 0, 0, nullptr, 0, 0, acc);
    k_tanhx<<<1024, 256, 0, s0>>>();
    for (int s = 1; s < NSWEEP; s++) {
        __half* in    = (s % 2 == 1) ? Ub : Ua;
        __half* out_u = (s % 2 == 1) ? Ua : Ub;
        launch_gemm(s0, in, 1, Wuut, NR_, NR_, nullptr, X, nullptr, out_u, nullptr, 1, 0, 0, nullptr, 0, 0, acc);
    }
    // NSWEEP=6 -> final U in Ua
    launch_gemm(s0, Ua, 1, Wyh1r, NR_, NH_, bh1, nullptr, bh1t, nullptr, nullptr, 0, 0, 0, nullptr, 0, 0, acc);
    cudaEventRecord(evFork, s0);               // "Ua ready"
    cudaStreamWaitEvent(s2, evFork, 0);

    // ---- s2: bvt, bh2t (concurrent with s0's RBM1 iter-0) ----
    launch_gemm(s2, Ua, 1, Wyvr,  NR_, NV_, bv,  nullptr, bvt,  nullptr, nullptr, 0, 0, 0, nullptr, 0, 0, acc);
    cudaEventRecord(evBvt, s2);
    launch_gemm(s2, Ua, 1, Wyh2r, NR_, NH_, bh2, nullptr, bh2t, nullptr, nullptr, 0, 0, 0, nullptr, 0, 0, acc);

    // ---- s0: RBM1 iter 0 (yields h, h1, FE1(v_seq) sp-sum) ----
    launch_gemm(s0, v16, 0, W1t, NV_, NH_, nullptr, bh1t, nullptr, h, h1, 2, 1, 0, nullptr,
                K1[0][0], K1[0][1], acc);
    cudaEventRecord(evH1, s0);

    // ---- s2: RBM2 CD-5 chain (needs h1, bh2t, bh1t) ----
    cudaStreamWaitEvent(s2, evH1, 0);
    launch_gemm(s2, h1, 0, W2t, NH_, NH_, nullptr, bh2t, nullptr, h2, nullptr, 2, 1, 2, nullptr,
                K1[5][0], K1[5][1], acc);
    launch_gemm(s2, h2, 0, W2r, NH_, NH_, nullptr, bh1t, nullptr, h1s, nullptr, 2, 0, 0, nullptr,
                K2[5][0], K2[5][1], acc);
    for (int i = 6; i < 10; i++) {
        launch_gemm(s2, h1s, 0, W2t, NH_, NH_, nullptr, bh2t, nullptr, h2, nullptr, 2, 0, 0, nullptr,
                    K1[i][0], K1[i][1], acc);
        launch_gemm(s2, h2, 0, W2r, NH_, NH_, nullptr, bh1t, nullptr, h1s, nullptr, 2, 0, 0, nullptr,
                    K2[i][0], K2[i][1], acc);
    }
    launch_gemm(s2, h1s, 0, W2t, NH_, NH_, nullptr, bh2t, nullptr, nullptr, nullptr, 0, 1, 3, nullptr,
                0, 0, acc);
    cudaEventRecord(evD, s2);

    // ---- s0: RBM1 chain (needs bvt from s2) ----
    cudaStreamWaitEvent(s0, evBvt, 0);
    launch_gemm(s0, h, 0, W1r, NH_, NV_, nullptr, bvt, nullptr, vs, nullptr, 2, 0, 0, nullptr,
                K2[0][0], K2[0][1], acc);
    for (int i = 1; i < CDK_ - 1; i++) {
        launch_gemm(s0, vs, 0, W1t, NV_, NH_, nullptr, bh1t, nullptr, h, nullptr, 2, 0, 0, nullptr,
                    K1[i][0], K1[i][1], acc);
        launch_gemm(s0, h, 0, W1r, NH_, NV_, nullptr, bvt, nullptr, vs, nullptr, 2, 0, 0, nullptr,
                    K2[i][0], K2[i][1], acc);
    }
    launch_gemm(s0, vs, 0, W1t, NV_, NH_, nullptr, bh1t, nullptr, h, nullptr, 2, 0, 0, nullptr,
                K1[CDK_-1][0], K1[CDK_-1][1], acc);
    launch_gemm(s0, h, 0, W1r, NH_, NV_, nullptr, bvt, nullptr, vs, nullptr, 2, 2, 4, v_seq,
                K2[CDK_-1][0], K2[CDK_-1][1], acc);
    launch_gemm(s0, vs, 0, W1t, NV_, NH_, nullptr, bh1t, nullptr, nullptr, nullptr, 0, 1, 1, nullptr,
                0, 0, acc);

    // ===== join: s0 waits for s2's chain, then reduce/finalize =====
    cudaStreamWaitEvent(s0, evD, 0);
    k_dots<<<2048, 256, 0, s0>>>(v_seq, bvt, vs, h1, h1s, bh1t, acc);
    k_final<<<1, 1, 0, s0>>>(acc, out);
}